// round 7
// baseline (speedup 1.0000x reference)
#include <cuda_runtime.h>
#include <cuda_fp16.h>
#include <cstdint>

#define B_ 2
#define S_ 2048
#define D_ 1024
#define H_ 16
#define HD_ 64
#define M_TOT 4096
#define KEFF 2048          // [hi|lo] split concat for A-side
#define NKITER 32          // KEFF / 64
#define LOG2E 1.44269504f

// ---------------------------------------------------------------------------
// Scratch (device globals; no allocation)
// ---------------------------------------------------------------------------
__device__ __half g_a1[(size_t)M_TOT * KEFF];          // x split [hi|lo]
__device__ __half g_a2[(size_t)M_TOT * KEFF];          // attn-out split [hi|lo]
__device__ __half g_wqkvT[(size_t)(3 * D_) * D_];      // w_qkv^T hi [3072,1024]
__device__ __half g_wprojT[(size_t)D_ * D_];           // w_proj^T hi [1024,1024]
__device__ __half g_Q[(size_t)B_ * H_ * S_ * 128];     // scaled q split [hi|lo]
__device__ __half g_K[(size_t)B_ * H_ * S_ * 64];      // k hi
__device__ __half g_Vhi[(size_t)B_ * H_ * S_ * 64];
__device__ __half g_Vlo[(size_t)B_ * H_ * S_ * 64];

// ---------------------------------------------------------------------------
// PTX helpers
// ---------------------------------------------------------------------------
__device__ __forceinline__ uint32_t smem_u32(const void* p) {
    uint32_t a;
    asm("{ .reg .u64 t; cvta.to.shared.u64 t, %1; cvt.u32.u64 %0, t; }"
        : "=r"(a) : "l"(p));
    return a;
}
#define CP_ASYNC16(dst, src) \
    asm volatile("cp.async.cg.shared.global [%0], [%1], 16;" \
                 :: "r"(dst), "l"(src))
#define CP_COMMIT() asm volatile("cp.async.commit_group;")
#define CP_WAIT(n)  asm volatile("cp.async.wait_group %0;" :: "n"(n))

__device__ __forceinline__ void ldsm_x4(uint32_t& r0, uint32_t& r1,
                                        uint32_t& r2, uint32_t& r3,
                                        uint32_t addr) {
    asm volatile("ldmatrix.sync.aligned.m8n8.x4.shared.b16 {%0,%1,%2,%3}, [%4];"
                 : "=r"(r0), "=r"(r1), "=r"(r2), "=r"(r3) : "r"(addr));
}
__device__ __forceinline__ void ldsm_x4_t(uint32_t& r0, uint32_t& r1,
                                          uint32_t& r2, uint32_t& r3,
                                          uint32_t addr) {
    asm volatile("ldmatrix.sync.aligned.m8n8.x4.trans.shared.b16 {%0,%1,%2,%3}, [%4];"
                 : "=r"(r0), "=r"(r1), "=r"(r2), "=r"(r3) : "r"(addr));
}
__device__ __forceinline__ void mma16816(float* c, const uint32_t* a,
                                         uint32_t b0, uint32_t b1) {
    asm volatile(
        "mma.sync.aligned.m16n8k16.row.col.f32.f16.f16.f32 "
        "{%0,%1,%2,%3}, {%4,%5,%6,%7}, {%8,%9}, {%0,%1,%2,%3};"
        : "+f"(c[0]), "+f"(c[1]), "+f"(c[2]), "+f"(c[3])
        : "r"(a[0]), "r"(a[1]), "r"(a[2]), "r"(a[3]), "r"(b0), "r"(b1));
}

__device__ __forceinline__ float fexp2(float t) {
    t = fmaxf(t, -126.0f);
    float z = t + 12582912.0f;
    int ii = __float_as_int(z) - 0x4B400000;
    float f = t - (z - 12582912.0f);
    float p = 1.33336e-3f;
    p = fmaf(p, f, 9.61813e-3f);
    p = fmaf(p, f, 5.550411e-2f);
    p = fmaf(p, f, 2.4022651e-1f);
    p = fmaf(p, f, 6.9314718e-1f);
    p = fmaf(p, f, 1.0f);
    return p * __int_as_float((ii + 127) << 23);
}

__device__ __forceinline__ uint32_t packh2(float a, float b) {
    __half2 h = __floats2half2_rn(a, b);
    return *reinterpret_cast<uint32_t*>(&h);
}

// ---------------------------------------------------------------------------
// fp16 split conversion kernels
// ---------------------------------------------------------------------------
__global__ __launch_bounds__(256) void split_a_kernel(
    const float* __restrict__ src, __half* __restrict__ dst)
{
    int i = blockIdx.x * 256 + threadIdx.x;
    float v = src[i];
    __half hi = __float2half_rn(v);
    __half lo = __float2half_rn(v - __half2float(hi));
    int row = i >> 10;
    int col = i & 1023;
    size_t base = (size_t)row * KEFF;
    dst[base + col] = hi;
    dst[base + 1024 + col] = lo;
}

__global__ __launch_bounds__(256) void transpose_hi_kernel(
    const float* __restrict__ w, __half* __restrict__ wt, int N)
{
    __shared__ float tile[32][33];
    int bx = blockIdx.x * 32;
    int by = blockIdx.y * 32;
    int tx = threadIdx.x;
    int ty = threadIdx.y;
#pragma unroll
    for (int i = ty; i < 32; i += 8)
        tile[i][tx] = w[(size_t)(by + i) * N + bx + tx];
    __syncthreads();
#pragma unroll
    for (int i = ty; i < 32; i += 8) {
        int n = bx + i;
        int k = by + tx;
        wt[(size_t)n * D_ + k] = __float2half_rn(tile[tx][i]);
    }
}

// ---------------------------------------------------------------------------
// HMMA GEMM: C[m,n] = sum_k (A_hi+A_lo)[m,k]*Bt_hi[n,k] (+bias)
// A:[M,2048] ([hi|lo]), Bt:[N,1024] (hi). B k-index wraps (kb & 15).
// CTA 128x128, BK=64, 3-stage cp.async, 256 thr = 8 warps (2m x 4n).
// EPI==0: fp32 C + bias.  EPI==1: QKV epilogue -> g_Q/g_K/g_Vhi/g_Vlo.
// ---------------------------------------------------------------------------
#define GEMM_SMEM (3 * 32768)

template <int EPI>
__global__ __launch_bounds__(256) void gemm_hmma_kernel(
    const __half* __restrict__ A, const __half* __restrict__ Bt,
    const float* __restrict__ bias, float* __restrict__ C, int N)
{
    extern __shared__ char smem[];
    const uint32_t sbase = smem_u32(smem);
    const int t = threadIdx.x;
    const int lane = t & 31;
    const int wid = t >> 5;
    const int wm = wid >> 2;
    const int wn = wid & 3;
    const int row0 = blockIdx.y * 128;
    const int col0 = blockIdx.x * 128;

    const __half* Ag = A + (size_t)row0 * KEFF;
    const __half* Bg = Bt + (size_t)col0 * D_;

    float c[4][4][4];
#pragma unroll
    for (int i = 0; i < 4; i++)
#pragma unroll
        for (int j = 0; j < 4; j++)
#pragma unroll
            for (int r = 0; r < 4; r++) c[i][j][r] = 0.0f;

    auto load_stage = [&](int kb, int st) {
        uint32_t sa = sbase + st * 32768;
        uint32_t sb = sa + 16384;
        const __half* Agk = Ag + kb * 64;
        const __half* Bgk = Bg + (kb & 15) * 64;
#pragma unroll
        for (int i = 0; i < 4; i++) {
            int id = t + 256 * i;
            int r = id >> 3;
            int u = id & 7;
            uint32_t sw = (uint32_t)(r * 128 + ((u ^ (r & 7)) << 4));
            CP_ASYNC16(sa + sw, Agk + (size_t)r * KEFF + u * 8);
            CP_ASYNC16(sb + sw, Bgk + (size_t)r * D_ + u * 8);
        }
    };

    load_stage(0, 0);
    CP_COMMIT();
    load_stage(1, 1);
    CP_COMMIT();

    const int mat = lane >> 3;
    const int wi = lane & 7;

    for (int kb = 0; kb < NKITER; kb++) {
        if (kb + 1 < NKITER) { CP_WAIT(1); } else { CP_WAIT(0); }
        __syncthreads();
        if (kb + 2 < NKITER) {
            load_stage(kb + 2, (kb + 2) % 3);
            CP_COMMIT();
        }

        uint32_t sa = sbase + (kb % 3) * 32768;
        uint32_t sb = sa + 16384;

#pragma unroll
        for (int s = 0; s < 4; s++) {
            uint32_t a[4][4];
#pragma unroll
            for (int mi = 0; mi < 4; mi++) {
                int row = wm * 64 + mi * 16 + (mat & 1) * 8 + wi;
                int u = 2 * s + (mat >> 1);
                ldsm_x4(a[mi][0], a[mi][1], a[mi][2], a[mi][3],
                        sa + row * 128 + (((u ^ wi) & 7) << 4));
            }
            uint32_t b[2][4];
#pragma unroll
            for (int j = 0; j < 2; j++) {
                int row = wn * 32 + j * 16 + (mat & 1) * 8 + wi;
                int u = 2 * s + (mat >> 1);
                ldsm_x4(b[j][0], b[j][1], b[j][2], b[j][3],
                        sb + row * 128 + (((u ^ wi) & 7) << 4));
            }
#pragma unroll
            for (int mi = 0; mi < 4; mi++)
#pragma unroll
                for (int nn = 0; nn < 4; nn++)
                    mma16816(c[mi][nn], a[mi],
                             b[nn >> 1][nn & 1], b[nn >> 1][(nn & 1) + 2]);
        }
        __syncthreads();
    }

    // Epilogue
#pragma unroll
    for (int mi = 0; mi < 4; mi++) {
#pragma unroll
        for (int nn = 0; nn < 4; nn++) {
#pragma unroll
            for (int rp = 0; rp < 2; rp++) {
                int m = row0 + wm * 64 + mi * 16 + (lane >> 2) + rp * 8;
                int n = col0 + wn * 32 + nn * 8 + (lane & 3) * 2;
                float v0 = c[mi][nn][rp * 2 + 0] + bias[n];
                float v1 = c[mi][nn][rp * 2 + 1] + bias[n + 1];
                if (EPI == 0) {
                    float2 v = make_float2(v0, v1);
                    *reinterpret_cast<float2*>(C + (size_t)m * N + n) = v;
                } else {
                    int type = n >> 10;
                    int rr = n & 1023;
                    int h = rr >> 6;
                    int d = rr & 63;
                    int b = m >> 11;
                    int s = m & 2047;
                    if (type == 0) { v0 *= 0.125f; v1 *= 0.125f; }
                    __half h0 = __float2half_rn(v0);
                    __half h1 = __float2half_rn(v1);
                    __half2 hh = __halves2half2(h0, h1);
                    size_t hb = (size_t)(b * H_ + h) * S_ + s;
                    if (type == 0) {            // Q: [hi|lo], pre-scaled
                        __half l0 = __float2half_rn(v0 - __half2float(h0));
                        __half l1 = __float2half_rn(v1 - __half2float(h1));
                        __half* p = g_Q + hb * 128 + d;
                        *reinterpret_cast<__half2*>(p)      = hh;
                        *reinterpret_cast<__half2*>(p + 64) = __halves2half2(l0, l1);
                    } else if (type == 1) {     // K: hi only
                        *reinterpret_cast<__half2*>(g_K + hb * 64 + d) = hh;
                    } else {                    // V: hi / lo arrays
                        __half l0 = __float2half_rn(v0 - __half2float(h0));
                        __half l1 = __float2half_rn(v1 - __half2float(h1));
                        *reinterpret_cast<__half2*>(g_Vhi + hb * 64 + d) = hh;
                        *reinterpret_cast<__half2*>(g_Vlo + hb * 64 + d) =
                            __halves2half2(l0, l1);
                    }
                }
            }
        }
    }
}

// ---------------------------------------------------------------------------
// Flash attention (HMMA): q-tile 128 (Q split [hi|lo] = 128 cols), key blocks
// of 64 (K hi only, reused for both Q halves). PV: 3 passes (Phi*Vhi,
// Phi*Vlo, Plo*Vhi). 256 thr = 8 warps; warp w owns q-rows 16w..16w+15.
// ---------------------------------------------------------------------------
#define FA_SMEM (32768 + 16384 + 32768)   // Q 32K + K 2x8K + V 2x16K = 80K

__global__ __launch_bounds__(256) void flash_kernel(__half* __restrict__ a2out)
{
    extern __shared__ char smem[];
    const uint32_t sQ = smem_u32(smem);
    const uint32_t sK0 = sQ + 32768;
    const uint32_t sV0 = sK0 + 16384;
    const int t = threadIdx.x;
    const int lane = t & 31;
    const int wid = t >> 5;
    const int qb = blockIdx.x;
    const int h = blockIdx.y;
    const int b = blockIdx.z;

    const size_t headbase = (size_t)(b * H_ + h) * S_;
    const __half* Qg = g_Q + (headbase + qb * 128) * 128;
    const __half* Kg = g_K + headbase * 64;
    const __half* Vh = g_Vhi + headbase * 64;
    const __half* Vl = g_Vlo + headbase * 64;

    // Load Q tile (128 x 128 fp16, 256B rows, swizzled within 128B halves)
#pragma unroll
    for (int i = 0; i < 8; i++) {
        int id = t + 256 * i;
        int r = id >> 4;
        int u = id & 15;
        int swu = (u & 8) | ((u ^ r) & 7);
        CP_ASYNC16(sQ + r * 256 + swu * 16, Qg + (size_t)r * 128 + u * 8);
    }

    auto loadKV = [&](int kb, int st) {
        uint32_t sk = sK0 + st * 8192;
        uint32_t sv = sV0 + st * 16384;
        const __half* kg = Kg + (size_t)kb * 64 * 64;
        const __half* vh = Vh + (size_t)kb * 64 * 64;
        const __half* vl = Vl + (size_t)kb * 64 * 64;
#pragma unroll
        for (int i = 0; i < 2; i++) {
            int id = t + 256 * i;
            int r = id >> 3;
            int u = id & 7;
            int swu = u ^ (r & 7);
            CP_ASYNC16(sk + r * 128 + swu * 16, kg + (size_t)r * 64 + u * 8);
            CP_ASYNC16(sv + r * 128 + swu * 16, vh + (size_t)r * 64 + u * 8);
            CP_ASYNC16(sv + 8192 + r * 128 + swu * 16, vl + (size_t)r * 64 + u * 8);
        }
    };

    loadKV(0, 0);
    CP_COMMIT();

    float o[8][4];
#pragma unroll
    for (int i = 0; i < 8; i++)
#pragma unroll
        for (int j = 0; j < 4; j++) o[i][j] = 0.0f;
    float m0 = -1e30f, m1 = -1e30f, l0 = 0.0f, l1 = 0.0f;

    const int mat = lane >> 3;
    const int wi = lane & 7;

    for (int kb = 0; kb < 32; kb++) {
        int st = kb & 1;
        if (kb + 1 < 32) {
            loadKV(kb + 1, st ^ 1);
            CP_COMMIT();
            CP_WAIT(1);
        } else {
            CP_WAIT(0);
        }
        __syncthreads();

        // ---- scores: S = (Qhi + Qlo) @ Khi^T  (two passes over same K) ----
        float s[8][4];
#pragma unroll
        for (int i = 0; i < 8; i++)
#pragma unroll
            for (int j = 0; j < 4; j++) s[i][j] = 0.0f;

        uint32_t skb = sK0 + st * 8192;
#pragma unroll
        for (int half = 0; half < 2; half++) {
#pragma unroll
            for (int ks = 0; ks < 4; ks++) {
                uint32_t a[4];
                {
                    int row = wid * 16 + (mat & 1) * 8 + wi;
                    int u = half * 8 + 2 * ks + (mat >> 1);
                    int swu = (u & 8) | ((u ^ row) & 7);
                    ldsm_x4(a[0], a[1], a[2], a[3], sQ + row * 256 + swu * 16);
                }
#pragma unroll
                for (int j = 0; j < 4; j++) {
                    uint32_t bb[4];
                    int row = j * 16 + (mat & 1) * 8 + wi;
                    int u = 2 * ks + (mat >> 1);
                    ldsm_x4(bb[0], bb[1], bb[2], bb[3],
                            skb + row * 128 + (((u ^ row) & 7) << 4));
                    mma16816(s[j * 2 + 0], a, bb[0], bb[2]);
                    mma16816(s[j * 2 + 1], a, bb[1], bb[3]);
                }
            }
        }

        // ---- online softmax ----
        float nm0 = -1e30f, nm1 = -1e30f;
#pragma unroll
        for (int nn = 0; nn < 8; nn++) {
            nm0 = fmaxf(nm0, fmaxf(s[nn][0], s[nn][1]));
            nm1 = fmaxf(nm1, fmaxf(s[nn][2], s[nn][3]));
        }
        nm0 = fmaxf(nm0, __shfl_xor_sync(0xffffffffu, nm0, 1));
        nm0 = fmaxf(nm0, __shfl_xor_sync(0xffffffffu, nm0, 2));
        nm1 = fmaxf(nm1, __shfl_xor_sync(0xffffffffu, nm1, 1));
        nm1 = fmaxf(nm1, __shfl_xor_sync(0xffffffffu, nm1, 2));
        nm0 = fmaxf(nm0, m0);
        nm1 = fmaxf(nm1, m1);
        float al0 = fexp2((m0 - nm0) * LOG2E);
        float al1 = fexp2((m1 - nm1) * LOG2E);
        m0 = nm0;
        m1 = nm1;

        float sum0 = 0.0f, sum1 = 0.0f;
        uint32_t ph0[8], ph1[8], pl0[8], pl1[8];
#pragma unroll
        for (int nn = 0; nn < 8; nn++) {
            float p00 = fexp2((s[nn][0] - m0) * LOG2E);
            float p01 = fexp2((s[nn][1] - m0) * LOG2E);
            float p10 = fexp2((s[nn][2] - m1) * LOG2E);
            float p11 = fexp2((s[nn][3] - m1) * LOG2E);
            sum0 += p00 + p01;
            sum1 += p10 + p11;
            ph0[nn] = packh2(p00, p01);
            ph1[nn] = packh2(p10, p11);
            __half2 h0 = *reinterpret_cast<__half2*>(&ph0[nn]);
            __half2 h1 = *reinterpret_cast<__half2*>(&ph1[nn]);
            pl0[nn] = packh2(p00 - __low2float(h0), p01 - __high2float(h0));
            pl1[nn] = packh2(p10 - __low2float(h1), p11 - __high2float(h1));
        }
        sum0 += __shfl_xor_sync(0xffffffffu, sum0, 1);
        sum0 += __shfl_xor_sync(0xffffffffu, sum0, 2);
        sum1 += __shfl_xor_sync(0xffffffffu, sum1, 1);
        sum1 += __shfl_xor_sync(0xffffffffu, sum1, 2);
        l0 = l0 * al0 + sum0;
        l1 = l1 * al1 + sum1;
#pragma unroll
        for (int nn = 0; nn < 8; nn++) {
            o[nn][0] *= al0;
            o[nn][1] *= al0;
            o[nn][2] *= al1;
            o[nn][3] *= al1;
        }

        // ---- O += P @ V  (Phi*Vhi, Phi*Vlo, Plo*Vhi) ----
        uint32_t sv = sV0 + st * 16384;
#pragma unroll
        for (int pass = 0; pass < 3; pass++) {
            const uint32_t* A0 = (pass == 2) ? pl0 : ph0;
            const uint32_t* A1 = (pass == 2) ? pl1 : ph1;
            uint32_t vb = (pass == 1) ? sv + 8192 : sv;
#pragma unroll
            for (int ks = 0; ks < 4; ks++) {
                uint32_t a[4] = { A0[2 * ks], A1[2 * ks],
                                  A0[2 * ks + 1], A1[2 * ks + 1] };
#pragma unroll
                for (int j = 0; j < 4; j++) {
                    uint32_t bb[4];
                    int krow = ks * 16 + (mat & 1) * 8 + wi;
                    int u = j * 2 + (mat >> 1);
                    int swu = u ^ (krow & 7);
                    ldsm_x4_t(bb[0], bb[1], bb[2], bb[3],
                              vb + krow * 128 + swu * 16);
                    mma16816(o[j * 2 + 0], a, bb[0], bb[1]);
                    mma16816(o[j * 2 + 1], a, bb[2], bb[3]);
                }
            }
        }
        __syncthreads();
    }

    // ---- epilogue: normalize, write split [hi|lo] proj input ----
    float inv0 = 1.0f / l0;
    float inv1 = 1.0f / l1;
    int s0 = qb * 128 + wid * 16 + (lane >> 2);
    int s1 = s0 + 8;
#pragma unroll
    for (int nn = 0; nn < 8; nn++) {
        int d = h * 64 + nn * 8 + (lane & 3) * 2;
#pragma unroll
        for (int rp = 0; rp < 2; rp++) {
            int srow = rp ? s1 : s0;
            float inv = rp ? inv1 : inv0;
            float v0 = o[nn][rp * 2 + 0] * inv;
            float v1 = o[nn][rp * 2 + 1] * inv;
            __half h0 = __float2half_rn(v0);
            __half h1 = __float2half_rn(v1);
            __half l0h = __float2half_rn(v0 - __half2float(h0));
            __half l1h = __float2half_rn(v1 - __half2float(h1));
            __half* p = a2out + (size_t)(b * S_ + srow) * KEFF + d;
            *reinterpret_cast<__half2*>(p)        = __halves2half2(h0, h1);
            *reinterpret_cast<__half2*>(p + 1024) = __halves2half2(l0h, l1h);
        }
    }
}

// ---------------------------------------------------------------------------
extern "C" void kernel_launch(void* const* d_in, const int* in_sizes, int n_in,
                              void* d_out, int out_size)
{
    const float* x      = (const float*)d_in[0];
    const float* w_qkv  = (const float*)d_in[1];
    const float* b_qkv  = (const float*)d_in[2];
    const float* w_proj = (const float*)d_in[3];
    const float* b_proj = (const float*)d_in[4];
    float* out = (float*)d_out;

    __half *a1_p, *a2_p, *wq_p, *wp_p;
    cudaGetSymbolAddress((void**)&a1_p, g_a1);
    cudaGetSymbolAddress((void**)&a2_p, g_a2);
    cudaGetSymbolAddress((void**)&wq_p, g_wqkvT);
    cudaGetSymbolAddress((void**)&wp_p, g_wprojT);

    cudaFuncSetAttribute(gemm_hmma_kernel<0>,
                         cudaFuncAttributeMaxDynamicSharedMemorySize, GEMM_SMEM);
    cudaFuncSetAttribute(gemm_hmma_kernel<1>,
                         cudaFuncAttributeMaxDynamicSharedMemorySize, GEMM_SMEM);
    cudaFuncSetAttribute(flash_kernel,
                         cudaFuncAttributeMaxDynamicSharedMemorySize, FA_SMEM);

    // 1) splits
    split_a_kernel<<<(M_TOT * D_) / 256, 256>>>(x, a1_p);
    transpose_hi_kernel<<<dim3((3 * D_) / 32, D_ / 32), dim3(32, 8)>>>(
        w_qkv, wq_p, 3 * D_);
    transpose_hi_kernel<<<dim3(D_ / 32, D_ / 32), dim3(32, 8)>>>(
        w_proj, wp_p, D_);

    // 2) QKV GEMM (epilogue writes split/scaled Q,K,V directly)
    gemm_hmma_kernel<1><<<dim3((3 * D_) / 128, M_TOT / 128), 256, GEMM_SMEM>>>(
        a1_p, wq_p, b_qkv, nullptr, 3 * D_);

    // 3) flash attention (epilogue writes split proj input)
    flash_kernel<<<dim3(S_ / 128, H_, B_), 256, FA_SMEM>>>(a2_p);

    // 4) projection GEMM
    gemm_hmma_kernel<0><<<dim3(D_ / 128, M_TOT / 128), 256, GEMM_SMEM>>>(
        a2_p, wp_p, b_proj, out, D_);
}

// round 8
// speedup vs baseline: 1.2148x; 1.2148x over previous
#include <cuda_runtime.h>
#include <cuda_fp16.h>
#include <cstdint>

#define B_ 2
#define S_ 2048
#define D_ 1024
#define H_ 16
#define HD_ 64
#define M_TOT 4096
#define KEFF 3072          // 3 * 1024  (fp16 hi/lo split concat)
#define NKITER 48          // KEFF / 64
#define LOG2E 1.44269504f

// ---------------------------------------------------------------------------
// Scratch (device globals; no allocation)
// ---------------------------------------------------------------------------
__device__ __half g_a1[(size_t)M_TOT * KEFF];          // x split [hi|lo|hi]
__device__ __half g_a2[(size_t)M_TOT * KEFF];          // attn-out split [hi|lo|hi]
__device__ __half g_wqkvT[(size_t)(3 * D_) * KEFF];    // w_qkv^T split [hi|hi|lo]
__device__ __half g_wprojT[(size_t)D_ * KEFF];         // w_proj^T split [hi|hi|lo]
__device__ __half g_Q[(size_t)B_ * H_ * S_ * 192];     // scaled q split [hi|lo|hi]
__device__ __half g_K[(size_t)B_ * H_ * S_ * 192];     // k split [hi|hi|lo]
__device__ __half g_Vhi[(size_t)B_ * H_ * S_ * 64];
__device__ __half g_Vlo[(size_t)B_ * H_ * S_ * 64];

// ---------------------------------------------------------------------------
// PTX helpers
// ---------------------------------------------------------------------------
__device__ __forceinline__ uint32_t smem_u32(const void* p) {
    uint32_t a;
    asm("{ .reg .u64 t; cvta.to.shared.u64 t, %1; cvt.u32.u64 %0, t; }"
        : "=r"(a) : "l"(p));
    return a;
}
#define CP_ASYNC16(dst, src) \
    asm volatile("cp.async.cg.shared.global [%0], [%1], 16;" \
                 :: "r"(dst), "l"(src))
#define CP_COMMIT() asm volatile("cp.async.commit_group;")
#define CP_WAIT(n)  asm volatile("cp.async.wait_group %0;" :: "n"(n))

__device__ __forceinline__ void ldsm_x4(uint32_t& r0, uint32_t& r1,
                                        uint32_t& r2, uint32_t& r3,
                                        uint32_t addr) {
    asm volatile("ldmatrix.sync.aligned.m8n8.x4.shared.b16 {%0,%1,%2,%3}, [%4];"
                 : "=r"(r0), "=r"(r1), "=r"(r2), "=r"(r3) : "r"(addr));
}
__device__ __forceinline__ void ldsm_x4_t(uint32_t& r0, uint32_t& r1,
                                          uint32_t& r2, uint32_t& r3,
                                          uint32_t addr) {
    asm volatile("ldmatrix.sync.aligned.m8n8.x4.trans.shared.b16 {%0,%1,%2,%3}, [%4];"
                 : "=r"(r0), "=r"(r1), "=r"(r2), "=r"(r3) : "r"(addr));
}
__device__ __forceinline__ void mma16816(float* c, const uint32_t* a,
                                         uint32_t b0, uint32_t b1) {
    asm volatile(
        "mma.sync.aligned.m16n8k16.row.col.f32.f16.f16.f32 "
        "{%0,%1,%2,%3}, {%4,%5,%6,%7}, {%8,%9}, {%0,%1,%2,%3};"
        : "+f"(c[0]), "+f"(c[1]), "+f"(c[2]), "+f"(c[3])
        : "r"(a[0]), "r"(a[1]), "r"(a[2]), "r"(a[3]), "r"(b0), "r"(b1));
}

// MUFU exp2 (approx, ~2^-21 rel err — plenty for softmax weights)
__device__ __forceinline__ float fexp2(float t) {
    float r;
    asm("ex2.approx.ftz.f32 %0, %1;" : "=f"(r) : "f"(t));
    return r;
}

__device__ __forceinline__ uint32_t packh2(float a, float b) {
    __half2 h = __floats2half2_rn(a, b);
    return *reinterpret_cast<uint32_t*>(&h);
}

// ---------------------------------------------------------------------------
// fp16 split conversion kernels
// ---------------------------------------------------------------------------
__global__ __launch_bounds__(256) void split_a_kernel(
    const float* __restrict__ src, __half* __restrict__ dst)
{
    int i = blockIdx.x * 256 + threadIdx.x;
    float v = src[i];
    __half hi = __float2half_rn(v);
    __half lo = __float2half_rn(v - __half2float(hi));
    int row = i >> 10;
    int col = i & 1023;
    size_t base = (size_t)row * KEFF;
    dst[base + col] = hi;
    dst[base + 1024 + col] = lo;
    dst[base + 2048 + col] = hi;
}

__global__ __launch_bounds__(256) void transpose_split_kernel(
    const float* __restrict__ w, __half* __restrict__ wt, int N)
{
    __shared__ float tile[32][33];
    int bx = blockIdx.x * 32;
    int by = blockIdx.y * 32;
    int tx = threadIdx.x;
    int ty = threadIdx.y;
#pragma unroll
    for (int i = ty; i < 32; i += 8)
        tile[i][tx] = w[(size_t)(by + i) * N + bx + tx];
    __syncthreads();
#pragma unroll
    for (int i = ty; i < 32; i += 8) {
        int n = bx + i;
        int k = by + tx;
        float v = tile[tx][i];
        __half hi = __float2half_rn(v);
        __half lo = __float2half_rn(v - __half2float(hi));
        size_t base = (size_t)n * KEFF;
        wt[base + k] = hi;
        wt[base + 1024 + k] = hi;
        wt[base + 2048 + k] = lo;
    }
}

// ---------------------------------------------------------------------------
// HMMA GEMM: C[m,n] = sum_k A[m,k]*Bt[n,k] (+bias).  A:[M,KEFF] Bt:[N,KEFF].
// CTA 128x128, BK=64, 3-stage cp.async ring, ONE __syncthreads per k-iter.
// 256 thr = 8 warps (2m x 4n), warp 64x32.
// EPI==0: fp32 C + bias.  EPI==1: QKV epilogue -> split g_Q/g_K/g_Vhi/g_Vlo.
// ---------------------------------------------------------------------------
#define GEMM_SMEM (3 * 32768)

template <int EPI>
__global__ __launch_bounds__(256) void gemm_hmma_kernel(
    const __half* __restrict__ A, const __half* __restrict__ Bt,
    const float* __restrict__ bias, float* __restrict__ C, int N)
{
    extern __shared__ char smem[];
    const uint32_t sbase = smem_u32(smem);
    const int t = threadIdx.x;
    const int lane = t & 31;
    const int wid = t >> 5;
    const int wm = wid >> 2;
    const int wn = wid & 3;
    const int row0 = blockIdx.y * 128;
    const int col0 = blockIdx.x * 128;

    const __half* Ag = A + (size_t)row0 * KEFF;
    const __half* Bg = Bt + (size_t)col0 * KEFF;

    float c[4][4][4];
#pragma unroll
    for (int i = 0; i < 4; i++)
#pragma unroll
        for (int j = 0; j < 4; j++)
#pragma unroll
            for (int r = 0; r < 4; r++) c[i][j][r] = 0.0f;

    auto load_stage = [&](int kb, int st) {
        uint32_t sa = sbase + st * 32768;
        uint32_t sb = sa + 16384;
        const __half* Agk = Ag + kb * 64;
        const __half* Bgk = Bg + kb * 64;
#pragma unroll
        for (int i = 0; i < 4; i++) {
            int id = t + 256 * i;
            int r = id >> 3;
            int u = id & 7;
            uint32_t sw = (uint32_t)(r * 128 + ((u ^ (r & 7)) << 4));
            CP_ASYNC16(sa + sw, Agk + (size_t)r * KEFF + u * 8);
            CP_ASYNC16(sb + sw, Bgk + (size_t)r * KEFF + u * 8);
        }
    };

    load_stage(0, 0);
    CP_COMMIT();
    load_stage(1, 1);
    CP_COMMIT();

    const int mat = lane >> 3;
    const int wi = lane & 7;

    for (int kb = 0; kb < NKITER; kb++) {
        if (kb + 1 < NKITER) { CP_WAIT(1); } else { CP_WAIT(0); }
        __syncthreads();           // single barrier per iter (3-stage ring)
        if (kb + 2 < NKITER) {
            load_stage(kb + 2, (kb + 2) % 3);
            CP_COMMIT();
        }

        uint32_t sa = sbase + (kb % 3) * 32768;
        uint32_t sb = sa + 16384;

#pragma unroll
        for (int s = 0; s < 4; s++) {
            uint32_t a[4][4];
#pragma unroll
            for (int mi = 0; mi < 4; mi++) {
                int row = wm * 64 + mi * 16 + (mat & 1) * 8 + wi;
                int u = 2 * s + (mat >> 1);
                ldsm_x4(a[mi][0], a[mi][1], a[mi][2], a[mi][3],
                        sa + row * 128 + (((u ^ wi) & 7) << 4));
            }
            uint32_t b[2][4];
#pragma unroll
            for (int j = 0; j < 2; j++) {
                int row = wn * 32 + j * 16 + (mat & 1) * 8 + wi;
                int u = 2 * s + (mat >> 1);
                ldsm_x4(b[j][0], b[j][1], b[j][2], b[j][3],
                        sb + row * 128 + (((u ^ wi) & 7) << 4));
            }
#pragma unroll
            for (int mi = 0; mi < 4; mi++)
#pragma unroll
                for (int nn = 0; nn < 4; nn++)
                    mma16816(c[mi][nn], a[mi],
                             b[nn >> 1][nn & 1], b[nn >> 1][(nn & 1) + 2]);
        }
    }

    // Epilogue
#pragma unroll
    for (int mi = 0; mi < 4; mi++) {
#pragma unroll
        for (int nn = 0; nn < 4; nn++) {
#pragma unroll
            for (int rp = 0; rp < 2; rp++) {
                int m = row0 + wm * 64 + mi * 16 + (lane >> 2) + rp * 8;
                int n = col0 + wn * 32 + nn * 8 + (lane & 3) * 2;
                float v0 = c[mi][nn][rp * 2 + 0] + bias[n];
                float v1 = c[mi][nn][rp * 2 + 1] + bias[n + 1];
                if (EPI == 0) {
                    float2 v = make_float2(v0, v1);
                    *reinterpret_cast<float2*>(C + (size_t)m * N + n) = v;
                } else {
                    int type = n >> 10;
                    int rr = n & 1023;
                    int h = rr >> 6;
                    int d = rr & 63;
                    int b = m >> 11;
                    int s = m & 2047;
                    if (type == 0) { v0 *= 0.125f; v1 *= 0.125f; }
                    __half h0 = __float2half_rn(v0);
                    __half h1 = __float2half_rn(v1);
                    __half l0 = __float2half_rn(v0 - __half2float(h0));
                    __half l1 = __float2half_rn(v1 - __half2float(h1));
                    __half2 hh = __halves2half2(h0, h1);
                    __half2 ll = __halves2half2(l0, l1);
                    size_t hb = (size_t)(b * H_ + h) * S_ + s;
                    if (type == 0) {            // Q: [hi|lo|hi]
                        __half* p = g_Q + hb * 192 + d;
                        *reinterpret_cast<__half2*>(p)       = hh;
                        *reinterpret_cast<__half2*>(p + 64)  = ll;
                        *reinterpret_cast<__half2*>(p + 128) = hh;
                    } else if (type == 1) {     // K: [hi|hi|lo]
                        __half* p = g_K + hb * 192 + d;
                        *reinterpret_cast<__half2*>(p)       = hh;
                        *reinterpret_cast<__half2*>(p + 64)  = hh;
                        *reinterpret_cast<__half2*>(p + 128) = ll;
                    } else {                    // V: hi / lo arrays
                        *reinterpret_cast<__half2*>(g_Vhi + hb * 64 + d) = hh;
                        *reinterpret_cast<__half2*>(g_Vlo + hb * 64 + d) = ll;
                    }
                }
            }
        }
    }
}

// ---------------------------------------------------------------------------
// Flash attention (HMMA): q-tile 128, key blocks of 64, 256 thr = 8 warps.
// Scores over K=192 (3-term split). PV: 3 passes. 3-stage KV ring, one
// __syncthreads per kv-iter. Output -> g_a2 split [hi|lo|hi].
// Smem: Q 48K + 3 stages x (K 24K + Vhi 8K + Vlo 8K) = 168K.
// ---------------------------------------------------------------------------
#define FA_STAGE  40960
#define FA_SMEM   (49152 + 3 * FA_STAGE)

__global__ __launch_bounds__(256) void flash_kernel(__half* __restrict__ a2out)
{
    extern __shared__ char smem[];
    const uint32_t sQ = smem_u32(smem);
    const uint32_t sKV0 = sQ + 49152;
    const int t = threadIdx.x;
    const int lane = t & 31;
    const int wid = t >> 5;
    const int qb = blockIdx.x;
    const int h = blockIdx.y;
    const int b = blockIdx.z;

    const size_t headbase = (size_t)(b * H_ + h) * S_;
    const __half* Qg = g_Q + (headbase + qb * 128) * 192;
    const __half* Kg = g_K + headbase * 192;
    const __half* Vh = g_Vhi + headbase * 64;
    const __half* Vl = g_Vlo + headbase * 64;

    // Load Q tile (128 x 192 fp16, 384B rows, swizzled)
#pragma unroll
    for (int i = 0; i < 12; i++) {
        int id = t + 256 * i;
        int r = id / 24;
        int u = id % 24;
        int swu = (u & 24) | ((u ^ r) & 7);
        CP_ASYNC16(sQ + r * 384 + swu * 16, Qg + (size_t)r * 192 + u * 8);
    }

    auto loadKV = [&](int kb, int st) {
        uint32_t sk = sKV0 + st * FA_STAGE;
        uint32_t sv = sk + 24576;
        const __half* kg = Kg + (size_t)kb * 64 * 192;
#pragma unroll
        for (int i = 0; i < 6; i++) {
            int id = t + 256 * i;
            int r = id / 24;
            int u = id % 24;
            int swu = (u & 24) | ((u ^ r) & 7);
            CP_ASYNC16(sk + r * 384 + swu * 16, kg + (size_t)r * 192 + u * 8);
        }
        const __half* vh = Vh + (size_t)kb * 64 * 64;
        const __half* vl = Vl + (size_t)kb * 64 * 64;
#pragma unroll
        for (int i = 0; i < 2; i++) {
            int id = t + 256 * i;
            int r = id >> 3;
            int u = id & 7;
            int swu = u ^ (r & 7);
            CP_ASYNC16(sv + r * 128 + swu * 16, vh + (size_t)r * 64 + u * 8);
            CP_ASYNC16(sv + 8192 + r * 128 + swu * 16, vl + (size_t)r * 64 + u * 8);
        }
    };

    loadKV(0, 0);
    CP_COMMIT();
    loadKV(1, 1);
    CP_COMMIT();

    float o[8][4];
#pragma unroll
    for (int i = 0; i < 8; i++)
#pragma unroll
        for (int j = 0; j < 4; j++) o[i][j] = 0.0f;
    float m0 = -1e30f, m1 = -1e30f, l0 = 0.0f, l1 = 0.0f;

    const int mat = lane >> 3;
    const int wi = lane & 7;

    for (int kb = 0; kb < 32; kb++) {
        if (kb + 1 < 32) { CP_WAIT(1); } else { CP_WAIT(0); }
        __syncthreads();           // single barrier per iter (3-stage ring)
        if (kb + 2 < 32) {
            loadKV(kb + 2, (kb + 2) % 3);
            CP_COMMIT();
        }

        int st = kb % 3;
        uint32_t skb = sKV0 + st * FA_STAGE;
        uint32_t sv = skb + 24576;

        // ---- scores: S = Qtile(16x192) @ K'(64x192)^T ----
        float s[8][4];
#pragma unroll
        for (int i = 0; i < 8; i++)
#pragma unroll
            for (int j = 0; j < 4; j++) s[i][j] = 0.0f;

#pragma unroll
        for (int ks = 0; ks < 12; ks++) {
            uint32_t a[4];
            {
                int row = wid * 16 + (mat & 1) * 8 + wi;
                int u = 2 * ks + (mat >> 1);
                int swu = (u & 24) | ((u ^ row) & 7);
                ldsm_x4(a[0], a[1], a[2], a[3], sQ + row * 384 + swu * 16);
            }
#pragma unroll
            for (int j = 0; j < 4; j++) {
                uint32_t bb[4];
                int row = j * 16 + (mat & 1) * 8 + wi;
                int u = 2 * ks + (mat >> 1);
                int swu = (u & 24) | ((u ^ row) & 7);
                ldsm_x4(bb[0], bb[1], bb[2], bb[3], skb + row * 384 + swu * 16);
                mma16816(s[j * 2 + 0], a, bb[0], bb[2]);
                mma16816(s[j * 2 + 1], a, bb[1], bb[3]);
            }
        }

        // ---- online softmax (rows r0 = wid*16 + lane/4, r1 = r0+8) ----
        float nm0 = -1e30f, nm1 = -1e30f;
#pragma unroll
        for (int nn = 0; nn < 8; nn++) {
            nm0 = fmaxf(nm0, fmaxf(s[nn][0], s[nn][1]));
            nm1 = fmaxf(nm1, fmaxf(s[nn][2], s[nn][3]));
        }
        nm0 = fmaxf(nm0, __shfl_xor_sync(0xffffffffu, nm0, 1));
        nm0 = fmaxf(nm0, __shfl_xor_sync(0xffffffffu, nm0, 2));
        nm1 = fmaxf(nm1, __shfl_xor_sync(0xffffffffu, nm1, 1));
        nm1 = fmaxf(nm1, __shfl_xor_sync(0xffffffffu, nm1, 2));
        nm0 = fmaxf(nm0, m0);
        nm1 = fmaxf(nm1, m1);
        float al0 = fexp2((m0 - nm0) * LOG2E);
        float al1 = fexp2((m1 - nm1) * LOG2E);
        m0 = nm0;
        m1 = nm1;

        float sum0 = 0.0f, sum1 = 0.0f;
        uint32_t ph0[8], ph1[8], pl0[8], pl1[8];
#pragma unroll
        for (int nn = 0; nn < 8; nn++) {
            float p00 = fexp2((s[nn][0] - m0) * LOG2E);
            float p01 = fexp2((s[nn][1] - m0) * LOG2E);
            float p10 = fexp2((s[nn][2] - m1) * LOG2E);
            float p11 = fexp2((s[nn][3] - m1) * LOG2E);
            sum0 += p00 + p01;
            sum1 += p10 + p11;
            ph0[nn] = packh2(p00, p01);
            ph1[nn] = packh2(p10, p11);
            __half2 h0 = *reinterpret_cast<__half2*>(&ph0[nn]);
            __half2 h1 = *reinterpret_cast<__half2*>(&ph1[nn]);
            pl0[nn] = packh2(p00 - __low2float(h0), p01 - __high2float(h0));
            pl1[nn] = packh2(p10 - __low2float(h1), p11 - __high2float(h1));
        }
        sum0 += __shfl_xor_sync(0xffffffffu, sum0, 1);
        sum0 += __shfl_xor_sync(0xffffffffu, sum0, 2);
        sum1 += __shfl_xor_sync(0xffffffffu, sum1, 1);
        sum1 += __shfl_xor_sync(0xffffffffu, sum1, 2);
        l0 = l0 * al0 + sum0;
        l1 = l1 * al1 + sum1;
#pragma unroll
        for (int nn = 0; nn < 8; nn++) {
            o[nn][0] *= al0;
            o[nn][1] *= al0;
            o[nn][2] *= al1;
            o[nn][3] *= al1;
        }

        // ---- O += P @ V  (Phi*Vhi, Phi*Vlo, Plo*Vhi) ----
#pragma unroll
        for (int pass = 0; pass < 3; pass++) {
            const uint32_t* A0 = (pass == 2) ? pl0 : ph0;
            const uint32_t* A1 = (pass == 2) ? pl1 : ph1;
            uint32_t vb = (pass == 1) ? sv + 8192 : sv;
#pragma unroll
            for (int ks = 0; ks < 4; ks++) {
                uint32_t a[4] = { A0[2 * ks], A1[2 * ks],
                                  A0[2 * ks + 1], A1[2 * ks + 1] };
#pragma unroll
                for (int j = 0; j < 4; j++) {
                    uint32_t bb[4];
                    int krow = ks * 16 + (mat & 1) * 8 + wi;
                    int u = j * 2 + (mat >> 1);
                    int swu = u ^ (krow & 7);
                    ldsm_x4_t(bb[0], bb[1], bb[2], bb[3],
                              vb + krow * 128 + swu * 16);
                    mma16816(o[j * 2 + 0], a, bb[0], bb[1]);
                    mma16816(o[j * 2 + 1], a, bb[2], bb[3]);
                }
            }
        }
    }

    // ---- epilogue: normalize and write split proj input ----
    float inv0 = 1.0f / l0;
    float inv1 = 1.0f / l1;
    int s0 = qb * 128 + wid * 16 + (lane >> 2);
    int s1 = s0 + 8;
#pragma unroll
    for (int nn = 0; nn < 8; nn++) {
        int d = h * 64 + nn * 8 + (lane & 3) * 2;
#pragma unroll
        for (int rp = 0; rp < 2; rp++) {
            int srow = rp ? s1 : s0;
            float inv = rp ? inv1 : inv0;
            float v0 = o[nn][rp * 2 + 0] * inv;
            float v1 = o[nn][rp * 2 + 1] * inv;
            __half h0 = __float2half_rn(v0);
            __half h1 = __float2half_rn(v1);
            __half l0h = __float2half_rn(v0 - __half2float(h0));
            __half l1h = __float2half_rn(v1 - __half2float(h1));
            __half* p = a2out + (size_t)(b * S_ + srow) * KEFF + d;
            *reinterpret_cast<__half2*>(p)        = __halves2half2(h0, h1);
            *reinterpret_cast<__half2*>(p + 1024) = __halves2half2(l0h, l1h);
            *reinterpret_cast<__half2*>(p + 2048) = __halves2half2(h0, h1);
        }
    }
}

// ---------------------------------------------------------------------------
extern "C" void kernel_launch(void* const* d_in, const int* in_sizes, int n_in,
                              void* d_out, int out_size)
{
    const float* x      = (const float*)d_in[0];
    const float* w_qkv  = (const float*)d_in[1];
    const float* b_qkv  = (const float*)d_in[2];
    const float* w_proj = (const float*)d_in[3];
    const float* b_proj = (const float*)d_in[4];
    float* out = (float*)d_out;

    __half *a1_p, *a2_p, *wq_p, *wp_p;
    cudaGetSymbolAddress((void**)&a1_p, g_a1);
    cudaGetSymbolAddress((void**)&a2_p, g_a2);
    cudaGetSymbolAddress((void**)&wq_p, g_wqkvT);
    cudaGetSymbolAddress((void**)&wp_p, g_wprojT);

    cudaFuncSetAttribute(gemm_hmma_kernel<0>,
                         cudaFuncAttributeMaxDynamicSharedMemorySize, GEMM_SMEM);
    cudaFuncSetAttribute(gemm_hmma_kernel<1>,
                         cudaFuncAttributeMaxDynamicSharedMemorySize, GEMM_SMEM);
    cudaFuncSetAttribute(flash_kernel,
                         cudaFuncAttributeMaxDynamicSharedMemorySize, FA_SMEM);

    // 1) splits
    split_a_kernel<<<(M_TOT * D_) / 256, 256>>>(x, a1_p);
    transpose_split_kernel<<<dim3((3 * D_) / 32, D_ / 32), dim3(32, 8)>>>(
        w_qkv, wq_p, 3 * D_);
    transpose_split_kernel<<<dim3(D_ / 32, D_ / 32), dim3(32, 8)>>>(
        w_proj, wp_p, D_);

    // 2) QKV GEMM (epilogue writes split/scaled Q,K,V directly)
    gemm_hmma_kernel<1><<<dim3((3 * D_) / 128, M_TOT / 128), 256, GEMM_SMEM>>>(
        a1_p, wq_p, b_qkv, nullptr, 3 * D_);

    // 3) flash attention (epilogue writes split proj input)
    flash_kernel<<<dim3(S_ / 128, H_, B_), 256, FA_SMEM>>>(a2_p);

    // 4) projection GEMM
    gemm_hmma_kernel<0><<<dim3(D_ / 128, M_TOT / 128), 256, GEMM_SMEM>>>(
        a2_p, wp_p, b_proj, out, D_);
}

// round 10
// speedup vs baseline: 1.2395x; 1.0203x over previous
#include <cuda_runtime.h>
#include <cuda_fp16.h>
#include <cstdint>

#define B_ 2
#define S_ 2048
#define D_ 1024
#define H_ 16
#define HD_ 64
#define M_TOT 4096
#define KEFF 3072          // 3 * 1024  (fp16 hi/lo split concat)
#define NKITER 48          // KEFF / 64
#define LOG2E 1.44269504f

// ---------------------------------------------------------------------------
// Scratch (device globals; no allocation)
// ---------------------------------------------------------------------------
__device__ __half g_a1[(size_t)M_TOT * KEFF];          // x split [hi|lo|hi]
__device__ __half g_a2[(size_t)M_TOT * KEFF];          // attn-out split [hi|lo|hi]
__device__ __half g_wqkvT[(size_t)(3 * D_) * KEFF];    // w_qkv^T split [hi|hi|lo]
__device__ __half g_wprojT[(size_t)D_ * KEFF];         // w_proj^T split [hi|hi|lo]
__device__ __half g_Q[(size_t)B_ * H_ * S_ * 192];     // scaled q split [hi|lo|hi]
__device__ __half g_K[(size_t)B_ * H_ * S_ * 192];     // k split [hi|hi|lo]
__device__ __half g_Vhi[(size_t)B_ * H_ * S_ * 64];
__device__ __half g_Vlo[(size_t)B_ * H_ * S_ * 64];

// ---------------------------------------------------------------------------
// PTX helpers
// ---------------------------------------------------------------------------
__device__ __forceinline__ uint32_t smem_u32(const void* p) {
    uint32_t a;
    asm("{ .reg .u64 t; cvta.to.shared.u64 t, %1; cvt.u32.u64 %0, t; }"
        : "=r"(a) : "l"(p));
    return a;
}
#define CP_ASYNC16(dst, src) \
    asm volatile("cp.async.cg.shared.global [%0], [%1], 16;" \
                 :: "r"(dst), "l"(src))
#define CP_COMMIT() asm volatile("cp.async.commit_group;")
#define CP_WAIT(n)  asm volatile("cp.async.wait_group %0;" :: "n"(n))

__device__ __forceinline__ void ldsm_x4(uint32_t& r0, uint32_t& r1,
                                        uint32_t& r2, uint32_t& r3,
                                        uint32_t addr) {
    asm volatile("ldmatrix.sync.aligned.m8n8.x4.shared.b16 {%0,%1,%2,%3}, [%4];"
                 : "=r"(r0), "=r"(r1), "=r"(r2), "=r"(r3) : "r"(addr));
}
__device__ __forceinline__ void ldsm_x4_t(uint32_t& r0, uint32_t& r1,
                                          uint32_t& r2, uint32_t& r3,
                                          uint32_t addr) {
    asm volatile("ldmatrix.sync.aligned.m8n8.x4.trans.shared.b16 {%0,%1,%2,%3}, [%4];"
                 : "=r"(r0), "=r"(r1), "=r"(r2), "=r"(r3) : "r"(addr));
}
__device__ __forceinline__ void mma16816(float* c, const uint32_t* a,
                                         uint32_t b0, uint32_t b1) {
    asm volatile(
        "mma.sync.aligned.m16n8k16.row.col.f32.f16.f16.f32 "
        "{%0,%1,%2,%3}, {%4,%5,%6,%7}, {%8,%9}, {%0,%1,%2,%3};"
        : "+f"(c[0]), "+f"(c[1]), "+f"(c[2]), "+f"(c[3])
        : "r"(a[0]), "r"(a[1]), "r"(a[2]), "r"(a[3]), "r"(b0), "r"(b1));
}

// MUFU exp2 (approx — plenty for softmax weights)
__device__ __forceinline__ float fexp2(float t) {
    float r;
    asm("ex2.approx.ftz.f32 %0, %1;" : "=f"(r) : "f"(t));
    return r;
}

__device__ __forceinline__ uint32_t packh2(float a, float b) {
    __half2 h = __floats2half2_rn(a, b);
    return *reinterpret_cast<uint32_t*>(&h);
}

// ---------------------------------------------------------------------------
// fp16 split conversion kernels
// ---------------------------------------------------------------------------
__global__ __launch_bounds__(256) void split_a_kernel(
    const float* __restrict__ src, __half* __restrict__ dst)
{
    int i = blockIdx.x * 256 + threadIdx.x;
    float v = src[i];
    __half hi = __float2half_rn(v);
    __half lo = __float2half_rn(v - __half2float(hi));
    int row = i >> 10;
    int col = i & 1023;
    size_t base = (size_t)row * KEFF;
    dst[base + col] = hi;
    dst[base + 1024 + col] = lo;
    dst[base + 2048 + col] = hi;
}

__global__ __launch_bounds__(256) void transpose_split_kernel(
    const float* __restrict__ w, __half* __restrict__ wt, int N)
{
    __shared__ float tile[32][33];
    int bx = blockIdx.x * 32;
    int by = blockIdx.y * 32;
    int tx = threadIdx.x;
    int ty = threadIdx.y;
#pragma unroll
    for (int i = ty; i < 32; i += 8)
        tile[i][tx] = w[(size_t)(by + i) * N + bx + tx];
    __syncthreads();
#pragma unroll
    for (int i = ty; i < 32; i += 8) {
        int n = bx + i;
        int k = by + tx;
        float v = tile[tx][i];
        __half hi = __float2half_rn(v);
        __half lo = __float2half_rn(v - __half2float(hi));
        size_t base = (size_t)n * KEFF;
        wt[base + k] = hi;
        wt[base + 1024 + k] = hi;
        wt[base + 2048 + k] = lo;
    }
}

// ---------------------------------------------------------------------------
// HMMA GEMM: C[m,n] = sum_k A[m,k]*Bt[n,k] (+bias).  A:[M,KEFF] Bt:[N,KEFF].
// CTA 128x128, BK=64, 3-stage cp.async ring, ONE __syncthreads per k-iter.
// 128 thr = 4 warps (2m x 2n), warp tile 64x64 -> 8 LDSM : 32 MMA per ks.
// EPI==0: fp32 C + bias.  EPI==1: QKV epilogue -> split g_Q/g_K/g_Vhi/g_Vlo.
// ---------------------------------------------------------------------------
#define GEMM_SMEM (3 * 32768)

template <int EPI>
__global__ __launch_bounds__(128) void gemm_hmma_kernel(
    const __half* __restrict__ A, const __half* __restrict__ Bt,
    const float* __restrict__ bias, float* __restrict__ C, int N)
{
    extern __shared__ char smem[];
    const uint32_t sbase = smem_u32(smem);
    const int t = threadIdx.x;
    const int lane = t & 31;
    const int wid = t >> 5;
    const int wm = wid >> 1;          // 0..1
    const int wn = wid & 1;           // 0..1
    const int row0 = blockIdx.y * 128;
    const int col0 = blockIdx.x * 128;

    const __half* Ag = A + (size_t)row0 * KEFF;
    const __half* Bg = Bt + (size_t)col0 * KEFF;

    float c[4][8][4];
#pragma unroll
    for (int i = 0; i < 4; i++)
#pragma unroll
        for (int j = 0; j < 8; j++)
#pragma unroll
            for (int r = 0; r < 4; r++) c[i][j][r] = 0.0f;

    auto load_stage = [&](int kb, int st) {
        uint32_t sa = sbase + st * 32768;
        uint32_t sb = sa + 16384;
        const __half* Agk = Ag + kb * 64;
        const __half* Bgk = Bg + kb * 64;
#pragma unroll
        for (int i = 0; i < 8; i++) {
            int id = t + 128 * i;          // 0..1023
            int r = id >> 3;               // 0..127
            int u = id & 7;
            uint32_t sw = (uint32_t)(r * 128 + ((u ^ (r & 7)) << 4));
            CP_ASYNC16(sa + sw, Agk + (size_t)r * KEFF + u * 8);
            CP_ASYNC16(sb + sw, Bgk + (size_t)r * KEFF + u * 8);
        }
    };

    load_stage(0, 0);
    CP_COMMIT();
    load_stage(1, 1);
    CP_COMMIT();

    const int mat = lane >> 3;
    const int wi = lane & 7;

    for (int kb = 0; kb < NKITER; kb++) {
        if (kb + 1 < NKITER) { CP_WAIT(1); } else { CP_WAIT(0); }
        __syncthreads();
        if (kb + 2 < NKITER) {
            load_stage(kb + 2, (kb + 2) % 3);
            CP_COMMIT();
        }

        uint32_t sa = sbase + (kb % 3) * 32768;
        uint32_t sb = sa + 16384;

#pragma unroll
        for (int s = 0; s < 4; s++) {
            uint32_t a[4][4];
#pragma unroll
            for (int mi = 0; mi < 4; mi++) {
                int row = wm * 64 + mi * 16 + (mat & 1) * 8 + wi;
                int u = 2 * s + (mat >> 1);
                ldsm_x4(a[mi][0], a[mi][1], a[mi][2], a[mi][3],
                        sa + row * 128 + (((u ^ wi) & 7) << 4));
            }
            uint32_t b[4][4];
#pragma unroll
            for (int j = 0; j < 4; j++) {
                int row = wn * 64 + j * 16 + (mat & 1) * 8 + wi;
                int u = 2 * s + (mat >> 1);
                ldsm_x4(b[j][0], b[j][1], b[j][2], b[j][3],
                        sb + row * 128 + (((u ^ wi) & 7) << 4));
            }
#pragma unroll
            for (int mi = 0; mi < 4; mi++)
#pragma unroll
                for (int nn = 0; nn < 8; nn++)
                    mma16816(c[mi][nn], a[mi],
                             b[nn >> 1][nn & 1], b[nn >> 1][(nn & 1) + 2]);
        }
    }

    // Epilogue
#pragma unroll
    for (int mi = 0; mi < 4; mi++) {
#pragma unroll
        for (int nn = 0; nn < 8; nn++) {
#pragma unroll
            for (int rp = 0; rp < 2; rp++) {
                int m = row0 + wm * 64 + mi * 16 + (lane >> 2) + rp * 8;
                int n = col0 + wn * 64 + nn * 8 + (lane & 3) * 2;
                float v0 = c[mi][nn][rp * 2 + 0] + bias[n];
                float v1 = c[mi][nn][rp * 2 + 1] + bias[n + 1];
                if (EPI == 0) {
                    float2 v = make_float2(v0, v1);
                    *reinterpret_cast<float2*>(C + (size_t)m * N + n) = v;
                } else {
                    int type = n >> 10;
                    int rr = n & 1023;
                    int h = rr >> 6;
                    int d = rr & 63;
                    int b = m >> 11;
                    int s = m & 2047;
                    if (type == 0) { v0 *= 0.125f; v1 *= 0.125f; }
                    __half h0 = __float2half_rn(v0);
                    __half h1 = __float2half_rn(v1);
                    __half l0 = __float2half_rn(v0 - __half2float(h0));
                    __half l1 = __float2half_rn(v1 - __half2float(h1));
                    __half2 hh = __halves2half2(h0, h1);
                    __half2 ll = __halves2half2(l0, l1);
                    size_t hb = (size_t)(b * H_ + h) * S_ + s;
                    if (type == 0) {            // Q: [hi|lo|hi]
                        __half* p = g_Q + hb * 192 + d;
                        *reinterpret_cast<__half2*>(p)       = hh;
                        *reinterpret_cast<__half2*>(p + 64)  = ll;
                        *reinterpret_cast<__half2*>(p + 128) = hh;
                    } else if (type == 1) {     // K: [hi|hi|lo]
                        __half* p = g_K + hb * 192 + d;
                        *reinterpret_cast<__half2*>(p)       = hh;
                        *reinterpret_cast<__half2*>(p + 64)  = hh;
                        *reinterpret_cast<__half2*>(p + 128) = ll;
                    } else {                    // V: hi / lo arrays
                        *reinterpret_cast<__half2*>(g_Vhi + hb * 64 + d) = hh;
                        *reinterpret_cast<__half2*>(g_Vlo + hb * 64 + d) = ll;
                    }
                }
            }
        }
    }
}

// ---------------------------------------------------------------------------
// Flash attention (HMMA): unchanged from round 8.
// ---------------------------------------------------------------------------
#define FA_STAGE  40960
#define FA_SMEM   (49152 + 3 * FA_STAGE)

__global__ __launch_bounds__(256) void flash_kernel(__half* __restrict__ a2out)
{
    extern __shared__ char smem[];
    const uint32_t sQ = smem_u32(smem);
    const uint32_t sKV0 = sQ + 49152;
    const int t = threadIdx.x;
    const int lane = t & 31;
    const int wid = t >> 5;
    const int qb = blockIdx.x;
    const int h = blockIdx.y;
    const int b = blockIdx.z;

    const size_t headbase = (size_t)(b * H_ + h) * S_;
    const __half* Qg = g_Q + (headbase + qb * 128) * 192;
    const __half* Kg = g_K + headbase * 192;
    const __half* Vh = g_Vhi + headbase * 64;
    const __half* Vl = g_Vlo + headbase * 64;

#pragma unroll
    for (int i = 0; i < 12; i++) {
        int id = t + 256 * i;
        int r = id / 24;
        int u = id % 24;
        int swu = (u & 24) | ((u ^ r) & 7);
        CP_ASYNC16(sQ + r * 384 + swu * 16, Qg + (size_t)r * 192 + u * 8);
    }

    auto loadKV = [&](int kb, int st) {
        uint32_t sk = sKV0 + st * FA_STAGE;
        uint32_t sv = sk + 24576;
        const __half* kg = Kg + (size_t)kb * 64 * 192;
#pragma unroll
        for (int i = 0; i < 6; i++) {
            int id = t + 256 * i;
            int r = id / 24;
            int u = id % 24;
            int swu = (u & 24) | ((u ^ r) & 7);
            CP_ASYNC16(sk + r * 384 + swu * 16, kg + (size_t)r * 192 + u * 8);
        }
        const __half* vh = Vh + (size_t)kb * 64 * 64;
        const __half* vl = Vl + (size_t)kb * 64 * 64;
#pragma unroll
        for (int i = 0; i < 2; i++) {
            int id = t + 256 * i;
            int r = id >> 3;
            int u = id & 7;
            int swu = u ^ (r & 7);
            CP_ASYNC16(sv + r * 128 + swu * 16, vh + (size_t)r * 64 + u * 8);
            CP_ASYNC16(sv + 8192 + r * 128 + swu * 16, vl + (size_t)r * 64 + u * 8);
        }
    };

    loadKV(0, 0);
    CP_COMMIT();
    loadKV(1, 1);
    CP_COMMIT();

    float o[8][4];
#pragma unroll
    for (int i = 0; i < 8; i++)
#pragma unroll
        for (int j = 0; j < 4; j++) o[i][j] = 0.0f;
    float m0 = -1e30f, m1 = -1e30f, l0 = 0.0f, l1 = 0.0f;

    const int mat = lane >> 3;
    const int wi = lane & 7;

    for (int kb = 0; kb < 32; kb++) {
        if (kb + 1 < 32) { CP_WAIT(1); } else { CP_WAIT(0); }
        __syncthreads();
        if (kb + 2 < 32) {
            loadKV(kb + 2, (kb + 2) % 3);
            CP_COMMIT();
        }

        int st = kb % 3;
        uint32_t skb = sKV0 + st * FA_STAGE;
        uint32_t sv = skb + 24576;

        float s[8][4];
#pragma unroll
        for (int i = 0; i < 8; i++)
#pragma unroll
            for (int j = 0; j < 4; j++) s[i][j] = 0.0f;

#pragma unroll
        for (int ks = 0; ks < 12; ks++) {
            uint32_t a[4];
            {
                int row = wid * 16 + (mat & 1) * 8 + wi;
                int u = 2 * ks + (mat >> 1);
                int swu = (u & 24) | ((u ^ row) & 7);
                ldsm_x4(a[0], a[1], a[2], a[3], sQ + row * 384 + swu * 16);
            }
#pragma unroll
            for (int j = 0; j < 4; j++) {
                uint32_t bb[4];
                int row = j * 16 + (mat & 1) * 8 + wi;
                int u = 2 * ks + (mat >> 1);
                int swu = (u & 24) | ((u ^ row) & 7);
                ldsm_x4(bb[0], bb[1], bb[2], bb[3], skb + row * 384 + swu * 16);
                mma16816(s[j * 2 + 0], a, bb[0], bb[2]);
                mma16816(s[j * 2 + 1], a, bb[1], bb[3]);
            }
        }

        float nm0 = -1e30f, nm1 = -1e30f;
#pragma unroll
        for (int nn = 0; nn < 8; nn++) {
            nm0 = fmaxf(nm0, fmaxf(s[nn][0], s[nn][1]));
            nm1 = fmaxf(nm1, fmaxf(s[nn][2], s[nn][3]));
        }
        nm0 = fmaxf(nm0, __shfl_xor_sync(0xffffffffu, nm0, 1));
        nm0 = fmaxf(nm0, __shfl_xor_sync(0xffffffffu, nm0, 2));
        nm1 = fmaxf(nm1, __shfl_xor_sync(0xffffffffu, nm1, 1));
        nm1 = fmaxf(nm1, __shfl_xor_sync(0xffffffffu, nm1, 2));
        nm0 = fmaxf(nm0, m0);
        nm1 = fmaxf(nm1, m1);
        float al0 = fexp2((m0 - nm0) * LOG2E);
        float al1 = fexp2((m1 - nm1) * LOG2E);
        m0 = nm0;
        m1 = nm1;

        float sum0 = 0.0f, sum1 = 0.0f;
        uint32_t ph0[8], ph1[8], pl0[8], pl1[8];
#pragma unroll
        for (int nn = 0; nn < 8; nn++) {
            float p00 = fexp2((s[nn][0] - m0) * LOG2E);
            float p01 = fexp2((s[nn][1] - m0) * LOG2E);
            float p10 = fexp2((s[nn][2] - m1) * LOG2E);
            float p11 = fexp2((s[nn][3] - m1) * LOG2E);
            sum0 += p00 + p01;
            sum1 += p10 + p11;
            ph0[nn] = packh2(p00, p01);
            ph1[nn] = packh2(p10, p11);
            __half2 h0 = *reinterpret_cast<__half2*>(&ph0[nn]);
            __half2 h1 = *reinterpret_cast<__half2*>(&ph1[nn]);
            pl0[nn] = packh2(p00 - __low2float(h0), p01 - __high2float(h0));
            pl1[nn] = packh2(p10 - __low2float(h1), p11 - __high2float(h1));
        }
        sum0 += __shfl_xor_sync(0xffffffffu, sum0, 1);
        sum0 += __shfl_xor_sync(0xffffffffu, sum0, 2);
        sum1 += __shfl_xor_sync(0xffffffffu, sum1, 1);
        sum1 += __shfl_xor_sync(0xffffffffu, sum1, 2);
        l0 = l0 * al0 + sum0;
        l1 = l1 * al1 + sum1;
#pragma unroll
        for (int nn = 0; nn < 8; nn++) {
            o[nn][0] *= al0;
            o[nn][1] *= al0;
            o[nn][2] *= al1;
            o[nn][3] *= al1;
        }

#pragma unroll
        for (int pass = 0; pass < 3; pass++) {
            const uint32_t* A0 = (pass == 2) ? pl0 : ph0;
            const uint32_t* A1 = (pass == 2) ? pl1 : ph1;
            uint32_t vb = (pass == 1) ? sv + 8192 : sv;
#pragma unroll
            for (int ks = 0; ks < 4; ks++) {
                uint32_t a[4] = { A0[2 * ks], A1[2 * ks],
                                  A0[2 * ks + 1], A1[2 * ks + 1] };
#pragma unroll
                for (int j = 0; j < 4; j++) {
                    uint32_t bb[4];
                    int krow = ks * 16 + (mat & 1) * 8 + wi;
                    int u = j * 2 + (mat >> 1);
                    int swu = u ^ (krow & 7);
                    ldsm_x4_t(bb[0], bb[1], bb[2], bb[3],
                              vb + krow * 128 + swu * 16);
                    mma16816(o[j * 2 + 0], a, bb[0], bb[1]);
                    mma16816(o[j * 2 + 1], a, bb[2], bb[3]);
                }
            }
        }
    }

    float inv0 = 1.0f / l0;
    float inv1 = 1.0f / l1;
    int s0 = qb * 128 + wid * 16 + (lane >> 2);
    int s1 = s0 + 8;
#pragma unroll
    for (int nn = 0; nn < 8; nn++) {
        int d = h * 64 + nn * 8 + (lane & 3) * 2;
#pragma unroll
        for (int rp = 0; rp < 2; rp++) {
            int srow = rp ? s1 : s0;
            float inv = rp ? inv1 : inv0;
            float v0 = o[nn][rp * 2 + 0] * inv;
            float v1 = o[nn][rp * 2 + 1] * inv;
            __half h0 = __float2half_rn(v0);
            __half h1 = __float2half_rn(v1);
            __half l0h = __float2half_rn(v0 - __half2float(h0));
            __half l1h = __float2half_rn(v1 - __half2float(h1));
            __half* p = a2out + (size_t)(b * S_ + srow) * KEFF + d;
            *reinterpret_cast<__half2*>(p)        = __halves2half2(h0, h1);
            *reinterpret_cast<__half2*>(p + 1024) = __halves2half2(l0h, l1h);
            *reinterpret_cast<__half2*>(p + 2048) = __halves2half2(h0, h1);
        }
    }
}

// ---------------------------------------------------------------------------
extern "C" void kernel_launch(void* const* d_in, const int* in_sizes, int n_in,
                              void* d_out, int out_size)
{
    const float* x      = (const float*)d_in[0];
    const float* w_qkv  = (const float*)d_in[1];
    const float* b_qkv  = (const float*)d_in[2];
    const float* w_proj = (const float*)d_in[3];
    const float* b_proj = (const float*)d_in[4];
    float* out = (float*)d_out;

    __half *a1_p, *a2_p, *wq_p, *wp_p;
    cudaGetSymbolAddress((void**)&a1_p, g_a1);
    cudaGetSymbolAddress((void**)&a2_p, g_a2);
    cudaGetSymbolAddress((void**)&wq_p, g_wqkvT);
    cudaGetSymbolAddress((void**)&wp_p, g_wprojT);

    cudaFuncSetAttribute(gemm_hmma_kernel<0>,
                         cudaFuncAttributeMaxDynamicSharedMemorySize, GEMM_SMEM);
    cudaFuncSetAttribute(gemm_hmma_kernel<1>,
                         cudaFuncAttributeMaxDynamicSharedMemorySize, GEMM_SMEM);
    cudaFuncSetAttribute(flash_kernel,
                         cudaFuncAttributeMaxDynamicSharedMemorySize, FA_SMEM);

    // 1) splits
    split_a_kernel<<<(M_TOT * D_) / 256, 256>>>(x, a1_p);
    transpose_split_kernel<<<dim3((3 * D_) / 32, D_ / 32), dim3(32, 8)>>>(
        w_qkv, wq_p, 3 * D_);
    transpose_split_kernel<<<dim3(D_ / 32, D_ / 32), dim3(32, 8)>>>(
        w_proj, wp_p, D_);

    // 2) QKV GEMM (epilogue writes split/scaled Q,K,V directly)
    gemm_hmma_kernel<1><<<dim3((3 * D_) / 128, M_TOT / 128), 128, GEMM_SMEM>>>(
        a1_p, wq_p, b_qkv, nullptr, 3 * D_);

    // 3) flash attention (epilogue writes split proj input)
    flash_kernel<<<dim3(S_ / 128, H_, B_), 256, FA_SMEM>>>(a2_p);

    // 4) projection GEMM
    gemm_hmma_kernel<0><<<dim3(D_ / 128, M_TOT / 128), 128, GEMM_SMEM>>>(
        a2_p, wp_p, b_proj, out, D_);
}

// round 11
// speedup vs baseline: 1.6374x; 1.3211x over previous
#include <cuda_runtime.h>
#include <cuda_fp16.h>
#include <cstdint>

#define B_ 2
#define S_ 2048
#define D_ 1024
#define H_ 16
#define HD_ 64
#define M_TOT 4096
#define KEFF 2048          // [hi|lo] split concat for A-side
#define NKITER 32          // KEFF / 64
#define LOG2E 1.44269504f

// ---------------------------------------------------------------------------
// Scratch (device globals; no allocation)
// ---------------------------------------------------------------------------
__device__ __half g_a1[(size_t)M_TOT * KEFF];          // x split [hi|lo]
__device__ __half g_a2[(size_t)M_TOT * KEFF];          // attn-out split [hi|lo]
__device__ __half g_wqkvT[(size_t)(3 * D_) * D_];      // w_qkv^T hi [3072,1024]
__device__ __half g_wprojT[(size_t)D_ * D_];           // w_proj^T hi [1024,1024]
__device__ __half g_Q[(size_t)B_ * H_ * S_ * 128];     // scaled q split [hi|lo]
__device__ __half g_K[(size_t)B_ * H_ * S_ * 64];      // k hi
__device__ __half g_Vhi[(size_t)B_ * H_ * S_ * 64];
__device__ __half g_Vlo[(size_t)B_ * H_ * S_ * 64];

// ---------------------------------------------------------------------------
// PTX helpers
// ---------------------------------------------------------------------------
__device__ __forceinline__ uint32_t smem_u32(const void* p) {
    uint32_t a;
    asm("{ .reg .u64 t; cvta.to.shared.u64 t, %1; cvt.u32.u64 %0, t; }"
        : "=r"(a) : "l"(p));
    return a;
}
#define CP_ASYNC16(dst, src) \
    asm volatile("cp.async.cg.shared.global [%0], [%1], 16;" \
                 :: "r"(dst), "l"(src))
#define CP_COMMIT() asm volatile("cp.async.commit_group;")
#define CP_WAIT(n)  asm volatile("cp.async.wait_group %0;" :: "n"(n))

__device__ __forceinline__ void ldsm_x4(uint32_t& r0, uint32_t& r1,
                                        uint32_t& r2, uint32_t& r3,
                                        uint32_t addr) {
    asm volatile("ldmatrix.sync.aligned.m8n8.x4.shared.b16 {%0,%1,%2,%3}, [%4];"
                 : "=r"(r0), "=r"(r1), "=r"(r2), "=r"(r3) : "r"(addr));
}
__device__ __forceinline__ void ldsm_x4_t(uint32_t& r0, uint32_t& r1,
                                          uint32_t& r2, uint32_t& r3,
                                          uint32_t addr) {
    asm volatile("ldmatrix.sync.aligned.m8n8.x4.trans.shared.b16 {%0,%1,%2,%3}, [%4];"
                 : "=r"(r0), "=r"(r1), "=r"(r2), "=r"(r3) : "r"(addr));
}
__device__ __forceinline__ void mma16816(float* c, const uint32_t* a,
                                         uint32_t b0, uint32_t b1) {
    asm volatile(
        "mma.sync.aligned.m16n8k16.row.col.f32.f16.f16.f32 "
        "{%0,%1,%2,%3}, {%4,%5,%6,%7}, {%8,%9}, {%0,%1,%2,%3};"
        : "+f"(c[0]), "+f"(c[1]), "+f"(c[2]), "+f"(c[3])
        : "r"(a[0]), "r"(a[1]), "r"(a[2]), "r"(a[3]), "r"(b0), "r"(b1));
}

// MUFU exp2 (approx — plenty for softmax weights)
__device__ __forceinline__ float fexp2(float t) {
    float r;
    asm("ex2.approx.ftz.f32 %0, %1;" : "=f"(r) : "f"(t));
    return r;
}

__device__ __forceinline__ uint32_t packh2(float a, float b) {
    __half2 h = __floats2half2_rn(a, b);
    return *reinterpret_cast<uint32_t*>(&h);
}

// ---------------------------------------------------------------------------
// fp16 split conversion kernels
// ---------------------------------------------------------------------------
__global__ __launch_bounds__(256) void split_a_kernel(
    const float* __restrict__ src, __half* __restrict__ dst)
{
    int i = blockIdx.x * 256 + threadIdx.x;
    float v = src[i];
    __half hi = __float2half_rn(v);
    __half lo = __float2half_rn(v - __half2float(hi));
    int row = i >> 10;
    int col = i & 1023;
    size_t base = (size_t)row * KEFF;
    dst[base + col] = hi;
    dst[base + 1024 + col] = lo;
}

__global__ __launch_bounds__(256) void transpose_hi_kernel(
    const float* __restrict__ w, __half* __restrict__ wt, int N)
{
    __shared__ float tile[32][33];
    int bx = blockIdx.x * 32;
    int by = blockIdx.y * 32;
    int tx = threadIdx.x;
    int ty = threadIdx.y;
#pragma unroll
    for (int i = ty; i < 32; i += 8)
        tile[i][tx] = w[(size_t)(by + i) * N + bx + tx];
    __syncthreads();
#pragma unroll
    for (int i = ty; i < 32; i += 8) {
        int n = bx + i;
        int k = by + tx;
        wt[(size_t)n * D_ + k] = __float2half_rn(tile[tx][i]);
    }
}

// ---------------------------------------------------------------------------
// HMMA GEMM: C[m,n] = sum_k (A_hi+A_lo)[m,k]*Bt_hi[n,k] (+bias)
// A:[M,2048] ([hi|lo]), Bt:[N,1024] hi. B k-index wraps (kb & 15).
// CTA 128x128, BK=64, 3-stage ring, ONE sync/iter, 128 thr = 4 warps 64x64.
// EPI==0: fp32 C + bias.  EPI==1: QKV epilogue -> g_Q/g_K/g_Vhi/g_Vlo.
// ---------------------------------------------------------------------------
#define GEMM_SMEM (3 * 32768)

template <int EPI>
__global__ __launch_bounds__(128) void gemm_hmma_kernel(
    const __half* __restrict__ A, const __half* __restrict__ Bt,
    const float* __restrict__ bias, float* __restrict__ C, int N)
{
    extern __shared__ char smem[];
    const uint32_t sbase = smem_u32(smem);
    const int t = threadIdx.x;
    const int lane = t & 31;
    const int wid = t >> 5;
    const int wm = wid >> 1;          // 0..1
    const int wn = wid & 1;           // 0..1
    const int row0 = blockIdx.y * 128;
    const int col0 = blockIdx.x * 128;

    const __half* Ag = A + (size_t)row0 * KEFF;
    const __half* Bg = Bt + (size_t)col0 * D_;

    float c[4][8][4];
#pragma unroll
    for (int i = 0; i < 4; i++)
#pragma unroll
        for (int j = 0; j < 8; j++)
#pragma unroll
            for (int r = 0; r < 4; r++) c[i][j][r] = 0.0f;

    auto load_stage = [&](int kb, int st) {
        uint32_t sa = sbase + st * 32768;
        uint32_t sb = sa + 16384;
        const __half* Agk = Ag + kb * 64;
        const __half* Bgk = Bg + (kb & 15) * 64;
#pragma unroll
        for (int i = 0; i < 8; i++) {
            int id = t + 128 * i;          // 0..1023
            int r = id >> 3;               // 0..127
            int u = id & 7;
            uint32_t sw = (uint32_t)(r * 128 + ((u ^ (r & 7)) << 4));
            CP_ASYNC16(sa + sw, Agk + (size_t)r * KEFF + u * 8);
            CP_ASYNC16(sb + sw, Bgk + (size_t)r * D_ + u * 8);
        }
    };

    load_stage(0, 0);
    CP_COMMIT();
    load_stage(1, 1);
    CP_COMMIT();

    const int mat = lane >> 3;
    const int wi = lane & 7;

    for (int kb = 0; kb < NKITER; kb++) {
        if (kb + 1 < NKITER) { CP_WAIT(1); } else { CP_WAIT(0); }
        __syncthreads();
        if (kb + 2 < NKITER) {
            load_stage(kb + 2, (kb + 2) % 3);
            CP_COMMIT();
        }

        uint32_t sa = sbase + (kb % 3) * 32768;
        uint32_t sb = sa + 16384;

#pragma unroll
        for (int s = 0; s < 4; s++) {
            uint32_t a[4][4];
#pragma unroll
            for (int mi = 0; mi < 4; mi++) {
                int row = wm * 64 + mi * 16 + (mat & 1) * 8 + wi;
                int u = 2 * s + (mat >> 1);
                ldsm_x4(a[mi][0], a[mi][1], a[mi][2], a[mi][3],
                        sa + row * 128 + (((u ^ wi) & 7) << 4));
            }
            uint32_t b[4][4];
#pragma unroll
            for (int j = 0; j < 4; j++) {
                int row = wn * 64 + j * 16 + (mat & 1) * 8 + wi;
                int u = 2 * s + (mat >> 1);
                ldsm_x4(b[j][0], b[j][1], b[j][2], b[j][3],
                        sb + row * 128 + (((u ^ wi) & 7) << 4));
            }
#pragma unroll
            for (int mi = 0; mi < 4; mi++)
#pragma unroll
                for (int nn = 0; nn < 8; nn++)
                    mma16816(c[mi][nn], a[mi],
                             b[nn >> 1][nn & 1], b[nn >> 1][(nn & 1) + 2]);
        }
    }

    // Epilogue
#pragma unroll
    for (int mi = 0; mi < 4; mi++) {
#pragma unroll
        for (int nn = 0; nn < 8; nn++) {
#pragma unroll
            for (int rp = 0; rp < 2; rp++) {
                int m = row0 + wm * 64 + mi * 16 + (lane >> 2) + rp * 8;
                int n = col0 + wn * 64 + nn * 8 + (lane & 3) * 2;
                float v0 = c[mi][nn][rp * 2 + 0] + bias[n];
                float v1 = c[mi][nn][rp * 2 + 1] + bias[n + 1];
                if (EPI == 0) {
                    float2 v = make_float2(v0, v1);
                    *reinterpret_cast<float2*>(C + (size_t)m * N + n) = v;
                } else {
                    int type = n >> 10;
                    int rr = n & 1023;
                    int h = rr >> 6;
                    int d = rr & 63;
                    int b = m >> 11;
                    int s = m & 2047;
                    if (type == 0) { v0 *= 0.125f; v1 *= 0.125f; }
                    __half h0 = __float2half_rn(v0);
                    __half h1 = __float2half_rn(v1);
                    __half2 hh = __halves2half2(h0, h1);
                    size_t hb = (size_t)(b * H_ + h) * S_ + s;
                    if (type == 0) {            // Q: [hi|lo], pre-scaled
                        __half l0 = __float2half_rn(v0 - __half2float(h0));
                        __half l1 = __float2half_rn(v1 - __half2float(h1));
                        __half* p = g_Q + hb * 128 + d;
                        *reinterpret_cast<__half2*>(p)      = hh;
                        *reinterpret_cast<__half2*>(p + 64) = __halves2half2(l0, l1);
                    } else if (type == 1) {     // K: hi only
                        *reinterpret_cast<__half2*>(g_K + hb * 64 + d) = hh;
                    } else {                    // V: hi / lo arrays
                        __half l0 = __float2half_rn(v0 - __half2float(h0));
                        __half l1 = __float2half_rn(v1 - __half2float(h1));
                        *reinterpret_cast<__half2*>(g_Vhi + hb * 64 + d) = hh;
                        *reinterpret_cast<__half2*>(g_Vlo + hb * 64 + d) =
                            __halves2half2(l0, l1);
                    }
                }
            }
        }
    }
}

// ---------------------------------------------------------------------------
// Flash attention (HMMA): q-tile 128 (Q [hi|lo] = 128 cols), key blocks of 64
// (K hi only, reused for both Q halves). PV: 3 passes. 3-stage KV ring, one
// sync per iter, MUFU exp2.  Smem: Q 32K + 3 x 24K = 104K -> 2 CTAs/SM.
// ---------------------------------------------------------------------------
#define FA_STAGE  24576
#define FA_SMEM   (32768 + 3 * FA_STAGE)

__global__ __launch_bounds__(256) void flash_kernel(__half* __restrict__ a2out)
{
    extern __shared__ char smem[];
    const uint32_t sQ = smem_u32(smem);
    const uint32_t sKV0 = sQ + 32768;
    const int t = threadIdx.x;
    const int lane = t & 31;
    const int wid = t >> 5;
    const int qb = blockIdx.x;
    const int h = blockIdx.y;
    const int b = blockIdx.z;

    const size_t headbase = (size_t)(b * H_ + h) * S_;
    const __half* Qg = g_Q + (headbase + qb * 128) * 128;
    const __half* Kg = g_K + headbase * 64;
    const __half* Vh = g_Vhi + headbase * 64;
    const __half* Vl = g_Vlo + headbase * 64;

    // Load Q tile (128 x 128 fp16, 256B rows, swizzled within 128B halves)
#pragma unroll
    for (int i = 0; i < 8; i++) {
        int id = t + 256 * i;
        int r = id >> 4;
        int u = id & 15;
        int swu = (u & 8) | ((u ^ r) & 7);
        CP_ASYNC16(sQ + r * 256 + swu * 16, Qg + (size_t)r * 128 + u * 8);
    }

    auto loadKV = [&](int kb, int st) {
        uint32_t sk = sKV0 + st * FA_STAGE;
        uint32_t sv = sk + 8192;
        const __half* kg = Kg + (size_t)kb * 64 * 64;
        const __half* vh = Vh + (size_t)kb * 64 * 64;
        const __half* vl = Vl + (size_t)kb * 64 * 64;
#pragma unroll
        for (int i = 0; i < 2; i++) {
            int id = t + 256 * i;
            int r = id >> 3;
            int u = id & 7;
            int swu = u ^ (r & 7);
            CP_ASYNC16(sk + r * 128 + swu * 16, kg + (size_t)r * 64 + u * 8);
            CP_ASYNC16(sv + r * 128 + swu * 16, vh + (size_t)r * 64 + u * 8);
            CP_ASYNC16(sv + 8192 + r * 128 + swu * 16, vl + (size_t)r * 64 + u * 8);
        }
    };

    loadKV(0, 0);
    CP_COMMIT();
    loadKV(1, 1);
    CP_COMMIT();

    float o[8][4];
#pragma unroll
    for (int i = 0; i < 8; i++)
#pragma unroll
        for (int j = 0; j < 4; j++) o[i][j] = 0.0f;
    float m0 = -1e30f, m1 = -1e30f, l0 = 0.0f, l1 = 0.0f;

    const int mat = lane >> 3;
    const int wi = lane & 7;

    for (int kb = 0; kb < 32; kb++) {
        if (kb + 1 < 32) { CP_WAIT(1); } else { CP_WAIT(0); }
        __syncthreads();
        if (kb + 2 < 32) {
            loadKV(kb + 2, (kb + 2) % 3);
            CP_COMMIT();
        }

        int st = kb % 3;
        uint32_t skb = sKV0 + st * FA_STAGE;
        uint32_t sv = skb + 8192;

        // ---- scores: S = (Qhi + Qlo) @ Khi^T  (two passes over same K) ----
        float s[8][4];
#pragma unroll
        for (int i = 0; i < 8; i++)
#pragma unroll
            for (int j = 0; j < 4; j++) s[i][j] = 0.0f;

#pragma unroll
        for (int half = 0; half < 2; half++) {
#pragma unroll
            for (int ks = 0; ks < 4; ks++) {
                uint32_t a[4];
                {
                    int row = wid * 16 + (mat & 1) * 8 + wi;
                    int u = half * 8 + 2 * ks + (mat >> 1);
                    int swu = (u & 8) | ((u ^ row) & 7);
                    ldsm_x4(a[0], a[1], a[2], a[3], sQ + row * 256 + swu * 16);
                }
#pragma unroll
                for (int j = 0; j < 4; j++) {
                    uint32_t bb[4];
                    int row = j * 16 + (mat & 1) * 8 + wi;
                    int u = 2 * ks + (mat >> 1);
                    ldsm_x4(bb[0], bb[1], bb[2], bb[3],
                            skb + row * 128 + (((u ^ row) & 7) << 4));
                    mma16816(s[j * 2 + 0], a, bb[0], bb[2]);
                    mma16816(s[j * 2 + 1], a, bb[1], bb[3]);
                }
            }
        }

        // ---- online softmax ----
        float nm0 = -1e30f, nm1 = -1e30f;
#pragma unroll
        for (int nn = 0; nn < 8; nn++) {
            nm0 = fmaxf(nm0, fmaxf(s[nn][0], s[nn][1]));
            nm1 = fmaxf(nm1, fmaxf(s[nn][2], s[nn][3]));
        }
        nm0 = fmaxf(nm0, __shfl_xor_sync(0xffffffffu, nm0, 1));
        nm0 = fmaxf(nm0, __shfl_xor_sync(0xffffffffu, nm0, 2));
        nm1 = fmaxf(nm1, __shfl_xor_sync(0xffffffffu, nm1, 1));
        nm1 = fmaxf(nm1, __shfl_xor_sync(0xffffffffu, nm1, 2));
        nm0 = fmaxf(nm0, m0);
        nm1 = fmaxf(nm1, m1);
        float al0 = fexp2((m0 - nm0) * LOG2E);
        float al1 = fexp2((m1 - nm1) * LOG2E);
        m0 = nm0;
        m1 = nm1;

        float sum0 = 0.0f, sum1 = 0.0f;
        uint32_t ph0[8], ph1[8], pl0[8], pl1[8];
#pragma unroll
        for (int nn = 0; nn < 8; nn++) {
            float p00 = fexp2((s[nn][0] - m0) * LOG2E);
            float p01 = fexp2((s[nn][1] - m0) * LOG2E);
            float p10 = fexp2((s[nn][2] - m1) * LOG2E);
            float p11 = fexp2((s[nn][3] - m1) * LOG2E);
            sum0 += p00 + p01;
            sum1 += p10 + p11;
            ph0[nn] = packh2(p00, p01);
            ph1[nn] = packh2(p10, p11);
            __half2 h0 = *reinterpret_cast<__half2*>(&ph0[nn]);
            __half2 h1 = *reinterpret_cast<__half2*>(&ph1[nn]);
            pl0[nn] = packh2(p00 - __low2float(h0), p01 - __high2float(h0));
            pl1[nn] = packh2(p10 - __low2float(h1), p11 - __high2float(h1));
        }
        sum0 += __shfl_xor_sync(0xffffffffu, sum0, 1);
        sum0 += __shfl_xor_sync(0xffffffffu, sum0, 2);
        sum1 += __shfl_xor_sync(0xffffffffu, sum1, 1);
        sum1 += __shfl_xor_sync(0xffffffffu, sum1, 2);
        l0 = l0 * al0 + sum0;
        l1 = l1 * al1 + sum1;
#pragma unroll
        for (int nn = 0; nn < 8; nn++) {
            o[nn][0] *= al0;
            o[nn][1] *= al0;
            o[nn][2] *= al1;
            o[nn][3] *= al1;
        }

        // ---- O += P @ V  (Phi*Vhi, Phi*Vlo, Plo*Vhi) ----
#pragma unroll
        for (int pass = 0; pass < 3; pass++) {
            const uint32_t* A0 = (pass == 2) ? pl0 : ph0;
            const uint32_t* A1 = (pass == 2) ? pl1 : ph1;
            uint32_t vb = (pass == 1) ? sv + 8192 : sv;
#pragma unroll
            for (int ks = 0; ks < 4; ks++) {
                uint32_t a[4] = { A0[2 * ks], A1[2 * ks],
                                  A0[2 * ks + 1], A1[2 * ks + 1] };
#pragma unroll
                for (int j = 0; j < 4; j++) {
                    uint32_t bb[4];
                    int krow = ks * 16 + (mat & 1) * 8 + wi;
                    int u = j * 2 + (mat >> 1);
                    int swu = u ^ (krow & 7);
                    ldsm_x4_t(bb[0], bb[1], bb[2], bb[3],
                              vb + krow * 128 + swu * 16);
                    mma16816(o[j * 2 + 0], a, bb[0], bb[1]);
                    mma16816(o[j * 2 + 1], a, bb[2], bb[3]);
                }
            }
        }
    }

    // ---- epilogue: normalize, write split [hi|lo] proj input ----
    float inv0 = 1.0f / l0;
    float inv1 = 1.0f / l1;
    int s0 = qb * 128 + wid * 16 + (lane >> 2);
    int s1 = s0 + 8;
#pragma unroll
    for (int nn = 0; nn < 8; nn++) {
        int d = h * 64 + nn * 8 + (lane & 3) * 2;
#pragma unroll
        for (int rp = 0; rp < 2; rp++) {
            int srow = rp ? s1 : s0;
            float inv = rp ? inv1 : inv0;
            float v0 = o[nn][rp * 2 + 0] * inv;
            float v1 = o[nn][rp * 2 + 1] * inv;
            __half h0 = __float2half_rn(v0);
            __half h1 = __float2half_rn(v1);
            __half l0h = __float2half_rn(v0 - __half2float(h0));
            __half l1h = __float2half_rn(v1 - __half2float(h1));
            __half* p = a2out + (size_t)(b * S_ + srow) * KEFF + d;
            *reinterpret_cast<__half2*>(p)        = __halves2half2(h0, h1);
            *reinterpret_cast<__half2*>(p + 1024) = __halves2half2(l0h, l1h);
        }
    }
}

// ---------------------------------------------------------------------------
extern "C" void kernel_launch(void* const* d_in, const int* in_sizes, int n_in,
                              void* d_out, int out_size)
{
    const float* x      = (const float*)d_in[0];
    const float* w_qkv  = (const float*)d_in[1];
    const float* b_qkv  = (const float*)d_in[2];
    const float* w_proj = (const float*)d_in[3];
    const float* b_proj = (const float*)d_in[4];
    float* out = (float*)d_out;

    __half *a1_p, *a2_p, *wq_p, *wp_p;
    cudaGetSymbolAddress((void**)&a1_p, g_a1);
    cudaGetSymbolAddress((void**)&a2_p, g_a2);
    cudaGetSymbolAddress((void**)&wq_p, g_wqkvT);
    cudaGetSymbolAddress((void**)&wp_p, g_wprojT);

    cudaFuncSetAttribute(gemm_hmma_kernel<0>,
                         cudaFuncAttributeMaxDynamicSharedMemorySize, GEMM_SMEM);
    cudaFuncSetAttribute(gemm_hmma_kernel<1>,
                         cudaFuncAttributeMaxDynamicSharedMemorySize, GEMM_SMEM);
    cudaFuncSetAttribute(flash_kernel,
                         cudaFuncAttributeMaxDynamicSharedMemorySize, FA_SMEM);

    // 1) splits
    split_a_kernel<<<(M_TOT * D_) / 256, 256>>>(x, a1_p);
    transpose_hi_kernel<<<dim3((3 * D_) / 32, D_ / 32), dim3(32, 8)>>>(
        w_qkv, wq_p, 3 * D_);
    transpose_hi_kernel<<<dim3(D_ / 32, D_ / 32), dim3(32, 8)>>>(
        w_proj, wp_p, D_);

    // 2) QKV GEMM (epilogue writes split/scaled Q,K,V directly)
    gemm_hmma_kernel<1><<<dim3((3 * D_) / 128, M_TOT / 128), 128, GEMM_SMEM>>>(
        a1_p, wq_p, b_qkv, nullptr, 3 * D_);

    // 3) flash attention (epilogue writes split proj input)
    flash_kernel<<<dim3(S_ / 128, H_, B_), 256, FA_SMEM>>>(a2_p);

    // 4) projection GEMM
    gemm_hmma_kernel<0><<<dim3(D_ / 128, M_TOT / 128), 128, GEMM_SMEM>>>(
        a2_p, wp_p, b_proj, out, D_);
}

// round 12
// speedup vs baseline: 1.7304x; 1.0568x over previous
#include <cuda_runtime.h>
#include <cuda_fp16.h>
#include <cstdint>

#define B_ 2
#define S_ 2048
#define D_ 1024
#define H_ 16
#define HD_ 64
#define M_TOT 4096
#define KEFF 2048          // [hi|lo] split concat for A-side
#define NKITER 32          // KEFF / 64
#define LOG2E 1.44269504f

// ---------------------------------------------------------------------------
// Scratch (device globals; no allocation)
// ---------------------------------------------------------------------------
__device__ __half g_a1[(size_t)M_TOT * KEFF];          // x split [hi|lo]
__device__ __half g_a2[(size_t)M_TOT * KEFF];          // attn-out split [hi|lo]
__device__ __half g_wqkvT[(size_t)(3 * D_) * D_];      // w_qkv^T hi [3072,1024]
__device__ __half g_wprojT[(size_t)D_ * D_];           // w_proj^T hi [1024,1024]
__device__ __half g_Q[(size_t)B_ * H_ * S_ * 128];     // scaled q split [hi|lo]
__device__ __half g_K[(size_t)B_ * H_ * S_ * 64];      // k hi
__device__ __half g_Vhi[(size_t)B_ * H_ * S_ * 64];
__device__ __half g_Vlo[(size_t)B_ * H_ * S_ * 64];

// ---------------------------------------------------------------------------
// PTX helpers
// ---------------------------------------------------------------------------
__device__ __forceinline__ uint32_t smem_u32(const void* p) {
    uint32_t a;
    asm("{ .reg .u64 t; cvta.to.shared.u64 t, %1; cvt.u32.u64 %0, t; }"
        : "=r"(a) : "l"(p));
    return a;
}
#define CP_ASYNC16(dst, src) \
    asm volatile("cp.async.cg.shared.global [%0], [%1], 16;" \
                 :: "r"(dst), "l"(src))
#define CP_COMMIT() asm volatile("cp.async.commit_group;")
#define CP_WAIT(n)  asm volatile("cp.async.wait_group %0;" :: "n"(n))

__device__ __forceinline__ void ldsm_x4(uint32_t& r0, uint32_t& r1,
                                        uint32_t& r2, uint32_t& r3,
                                        uint32_t addr) {
    asm volatile("ldmatrix.sync.aligned.m8n8.x4.shared.b16 {%0,%1,%2,%3}, [%4];"
                 : "=r"(r0), "=r"(r1), "=r"(r2), "=r"(r3) : "r"(addr));
}
__device__ __forceinline__ void ldsm_x4_t(uint32_t& r0, uint32_t& r1,
                                          uint32_t& r2, uint32_t& r3,
                                          uint32_t addr) {
    asm volatile("ldmatrix.sync.aligned.m8n8.x4.trans.shared.b16 {%0,%1,%2,%3}, [%4];"
                 : "=r"(r0), "=r"(r1), "=r"(r2), "=r"(r3) : "r"(addr));
}
__device__ __forceinline__ void mma16816(float* c, const uint32_t* a,
                                         uint32_t b0, uint32_t b1) {
    asm volatile(
        "mma.sync.aligned.m16n8k16.row.col.f32.f16.f16.f32 "
        "{%0,%1,%2,%3}, {%4,%5,%6,%7}, {%8,%9}, {%0,%1,%2,%3};"
        : "+f"(c[0]), "+f"(c[1]), "+f"(c[2]), "+f"(c[3])
        : "r"(a[0]), "r"(a[1]), "r"(a[2]), "r"(a[3]), "r"(b0), "r"(b1));
}

// MUFU exp2 (approx — plenty for softmax weights)
__device__ __forceinline__ float fexp2(float t) {
    float r;
    asm("ex2.approx.ftz.f32 %0, %1;" : "=f"(r) : "f"(t));
    return r;
}

__device__ __forceinline__ uint32_t packh2(float a, float b) {
    __half2 h = __floats2half2_rn(a, b);
    return *reinterpret_cast<uint32_t*>(&h);
}

// ---------------------------------------------------------------------------
// fp16 split conversion kernels
// ---------------------------------------------------------------------------
__global__ __launch_bounds__(256) void split_a_kernel(
    const float* __restrict__ src, __half* __restrict__ dst)
{
    int i = blockIdx.x * 256 + threadIdx.x;
    float v = src[i];
    __half hi = __float2half_rn(v);
    __half lo = __float2half_rn(v - __half2float(hi));
    int row = i >> 10;
    int col = i & 1023;
    size_t base = (size_t)row * KEFF;
    dst[base + col] = hi;
    dst[base + 1024 + col] = lo;
}

__global__ __launch_bounds__(256) void transpose_hi_kernel(
    const float* __restrict__ w, __half* __restrict__ wt, int N)
{
    __shared__ float tile[32][33];
    int bx = blockIdx.x * 32;
    int by = blockIdx.y * 32;
    int tx = threadIdx.x;
    int ty = threadIdx.y;
#pragma unroll
    for (int i = ty; i < 32; i += 8)
        tile[i][tx] = w[(size_t)(by + i) * N + bx + tx];
    __syncthreads();
#pragma unroll
    for (int i = ty; i < 32; i += 8) {
        int n = bx + i;
        int k = by + tx;
        wt[(size_t)n * D_ + k] = __float2half_rn(tile[tx][i]);
    }
}

// ---------------------------------------------------------------------------
// HMMA GEMM: C[m,n] = sum_k (A_hi+A_lo)[m,k]*Bt_hi[n,k] (+bias)
// A:[M,2048] ([hi|lo]), Bt:[N,1024] hi. B k-index wraps (kb & 15).
// CTA 128x128, BK=64, 3-stage ring, ONE sync/iter, 128 thr = 4 warps 64x64.
// EPI==0: fp32 C + bias.  EPI==1: QKV epilogue -> g_Q/g_K/g_Vhi/g_Vlo.
// ---------------------------------------------------------------------------
#define GEMM_SMEM (3 * 32768)

template <int EPI>
__global__ __launch_bounds__(128) void gemm_hmma_kernel(
    const __half* __restrict__ A, const __half* __restrict__ Bt,
    const float* __restrict__ bias, float* __restrict__ C, int N)
{
    extern __shared__ char smem[];
    const uint32_t sbase = smem_u32(smem);
    const int t = threadIdx.x;
    const int lane = t & 31;
    const int wid = t >> 5;
    const int wm = wid >> 1;          // 0..1
    const int wn = wid & 1;           // 0..1
    const int row0 = blockIdx.y * 128;
    const int col0 = blockIdx.x * 128;

    const __half* Ag = A + (size_t)row0 * KEFF;
    const __half* Bg = Bt + (size_t)col0 * D_;

    float c[4][8][4];
#pragma unroll
    for (int i = 0; i < 4; i++)
#pragma unroll
        for (int j = 0; j < 8; j++)
#pragma unroll
            for (int r = 0; r < 4; r++) c[i][j][r] = 0.0f;

    auto load_stage = [&](int kb, int st) {
        uint32_t sa = sbase + st * 32768;
        uint32_t sb = sa + 16384;
        const __half* Agk = Ag + kb * 64;
        const __half* Bgk = Bg + (kb & 15) * 64;
#pragma unroll
        for (int i = 0; i < 8; i++) {
            int id = t + 128 * i;          // 0..1023
            int r = id >> 3;               // 0..127
            int u = id & 7;
            uint32_t sw = (uint32_t)(r * 128 + ((u ^ (r & 7)) << 4));
            CP_ASYNC16(sa + sw, Agk + (size_t)r * KEFF + u * 8);
            CP_ASYNC16(sb + sw, Bgk + (size_t)r * D_ + u * 8);
        }
    };

    load_stage(0, 0);
    CP_COMMIT();
    load_stage(1, 1);
    CP_COMMIT();

    const int mat = lane >> 3;
    const int wi = lane & 7;

    for (int kb = 0; kb < NKITER; kb++) {
        if (kb + 1 < NKITER) { CP_WAIT(1); } else { CP_WAIT(0); }
        __syncthreads();
        if (kb + 2 < NKITER) {
            load_stage(kb + 2, (kb + 2) % 3);
            CP_COMMIT();
        }

        uint32_t sa = sbase + (kb % 3) * 32768;
        uint32_t sb = sa + 16384;

#pragma unroll
        for (int s = 0; s < 4; s++) {
            uint32_t a[4][4];
#pragma unroll
            for (int mi = 0; mi < 4; mi++) {
                int row = wm * 64 + mi * 16 + (mat & 1) * 8 + wi;
                int u = 2 * s + (mat >> 1);
                ldsm_x4(a[mi][0], a[mi][1], a[mi][2], a[mi][3],
                        sa + row * 128 + (((u ^ wi) & 7) << 4));
            }
            uint32_t b[4][4];
#pragma unroll
            for (int j = 0; j < 4; j++) {
                int row = wn * 64 + j * 16 + (mat & 1) * 8 + wi;
                int u = 2 * s + (mat >> 1);
                ldsm_x4(b[j][0], b[j][1], b[j][2], b[j][3],
                        sb + row * 128 + (((u ^ wi) & 7) << 4));
            }
#pragma unroll
            for (int mi = 0; mi < 4; mi++)
#pragma unroll
                for (int nn = 0; nn < 8; nn++)
                    mma16816(c[mi][nn], a[mi],
                             b[nn >> 1][nn & 1], b[nn >> 1][(nn & 1) + 2]);
        }
    }

    // Epilogue
#pragma unroll
    for (int mi = 0; mi < 4; mi++) {
#pragma unroll
        for (int nn = 0; nn < 8; nn++) {
#pragma unroll
            for (int rp = 0; rp < 2; rp++) {
                int m = row0 + wm * 64 + mi * 16 + (lane >> 2) + rp * 8;
                int n = col0 + wn * 64 + nn * 8 + (lane & 3) * 2;
                float v0 = c[mi][nn][rp * 2 + 0] + bias[n];
                float v1 = c[mi][nn][rp * 2 + 1] + bias[n + 1];
                if (EPI == 0) {
                    float2 v = make_float2(v0, v1);
                    *reinterpret_cast<float2*>(C + (size_t)m * N + n) = v;
                } else {
                    int type = n >> 10;
                    int rr = n & 1023;
                    int h = rr >> 6;
                    int d = rr & 63;
                    int b = m >> 11;
                    int s = m & 2047;
                    if (type == 0) { v0 *= 0.125f; v1 *= 0.125f; }
                    __half h0 = __float2half_rn(v0);
                    __half h1 = __float2half_rn(v1);
                    __half2 hh = __halves2half2(h0, h1);
                    size_t hb = (size_t)(b * H_ + h) * S_ + s;
                    if (type == 0) {            // Q: [hi|lo], pre-scaled
                        __half l0 = __float2half_rn(v0 - __half2float(h0));
                        __half l1 = __float2half_rn(v1 - __half2float(h1));
                        __half* p = g_Q + hb * 128 + d;
                        *reinterpret_cast<__half2*>(p)      = hh;
                        *reinterpret_cast<__half2*>(p + 64) = __halves2half2(l0, l1);
                    } else if (type == 1) {     // K: hi only
                        *reinterpret_cast<__half2*>(g_K + hb * 64 + d) = hh;
                    } else {                    // V: hi / lo arrays
                        __half l0 = __float2half_rn(v0 - __half2float(h0));
                        __half l1 = __float2half_rn(v1 - __half2float(h1));
                        *reinterpret_cast<__half2*>(g_Vhi + hb * 64 + d) = hh;
                        *reinterpret_cast<__half2*>(g_Vlo + hb * 64 + d) =
                            __halves2half2(l0, l1);
                    }
                }
            }
        }
    }
}

// ---------------------------------------------------------------------------
// Flash attention (HMMA): q-tile 128 (Q [hi|lo]), key blocks of 64 (K hi,
// one ldsm feeds BOTH Q halves). PV: Vhi frag feeds Phi & Plo passes, Vlo
// frag feeds Phi pass -> 2 ldsm : 6 mma per (ks,j). 3-stage KV ring, one
// sync/iter, MUFU exp2.  Smem: Q 32K + 3 x 24K = 104K -> 2 CTAs/SM.
// ---------------------------------------------------------------------------
#define FA_STAGE  24576
#define FA_SMEM   (32768 + 3 * FA_STAGE)

__global__ __launch_bounds__(256) void flash_kernel(__half* __restrict__ a2out)
{
    extern __shared__ char smem[];
    const uint32_t sQ = smem_u32(smem);
    const uint32_t sKV0 = sQ + 32768;
    const int t = threadIdx.x;
    const int lane = t & 31;
    const int wid = t >> 5;
    const int qb = blockIdx.x;
    const int h = blockIdx.y;
    const int b = blockIdx.z;

    const size_t headbase = (size_t)(b * H_ + h) * S_;
    const __half* Qg = g_Q + (headbase + qb * 128) * 128;
    const __half* Kg = g_K + headbase * 64;
    const __half* Vh = g_Vhi + headbase * 64;
    const __half* Vl = g_Vlo + headbase * 64;

    // Load Q tile (128 x 128 fp16, 256B rows, swizzled within 128B halves)
#pragma unroll
    for (int i = 0; i < 8; i++) {
        int id = t + 256 * i;
        int r = id >> 4;
        int u = id & 15;
        int swu = (u & 8) | ((u ^ r) & 7);
        CP_ASYNC16(sQ + r * 256 + swu * 16, Qg + (size_t)r * 128 + u * 8);
    }

    auto loadKV = [&](int kb, int st) {
        uint32_t sk = sKV0 + st * FA_STAGE;
        uint32_t sv = sk + 8192;
        const __half* kg = Kg + (size_t)kb * 64 * 64;
        const __half* vh = Vh + (size_t)kb * 64 * 64;
        const __half* vl = Vl + (size_t)kb * 64 * 64;
#pragma unroll
        for (int i = 0; i < 2; i++) {
            int id = t + 256 * i;
            int r = id >> 3;
            int u = id & 7;
            int swu = u ^ (r & 7);
            CP_ASYNC16(sk + r * 128 + swu * 16, kg + (size_t)r * 64 + u * 8);
            CP_ASYNC16(sv + r * 128 + swu * 16, vh + (size_t)r * 64 + u * 8);
            CP_ASYNC16(sv + 8192 + r * 128 + swu * 16, vl + (size_t)r * 64 + u * 8);
        }
    };

    loadKV(0, 0);
    CP_COMMIT();
    loadKV(1, 1);
    CP_COMMIT();

    float o[8][4];
#pragma unroll
    for (int i = 0; i < 8; i++)
#pragma unroll
        for (int j = 0; j < 4; j++) o[i][j] = 0.0f;
    float m0 = -1e30f, m1 = -1e30f, l0 = 0.0f, l1 = 0.0f;

    const int mat = lane >> 3;
    const int wi = lane & 7;

    for (int kb = 0; kb < 32; kb++) {
        if (kb + 1 < 32) { CP_WAIT(1); } else { CP_WAIT(0); }
        __syncthreads();
        if (kb + 2 < 32) {
            loadKV(kb + 2, (kb + 2) % 3);
            CP_COMMIT();
        }

        int st = kb % 3;
        uint32_t skb = sKV0 + st * FA_STAGE;
        uint32_t sv = skb + 8192;

        // ---- scores: S = (Qhi + Qlo) @ Khi^T  (K frag shared by halves) ----
        float s[8][4];
#pragma unroll
        for (int i = 0; i < 8; i++)
#pragma unroll
            for (int j = 0; j < 4; j++) s[i][j] = 0.0f;

#pragma unroll
        for (int ks = 0; ks < 4; ks++) {
            uint32_t a0[4], a1[4];
            {
                int row = wid * 16 + (mat & 1) * 8 + wi;
                int u0 = 2 * ks + (mat >> 1);          // hi half
                int u1 = 8 + 2 * ks + (mat >> 1);      // lo half
                int swu0 = (u0 & 8) | ((u0 ^ row) & 7);
                int swu1 = (u1 & 8) | ((u1 ^ row) & 7);
                ldsm_x4(a0[0], a0[1], a0[2], a0[3], sQ + row * 256 + swu0 * 16);
                ldsm_x4(a1[0], a1[1], a1[2], a1[3], sQ + row * 256 + swu1 * 16);
            }
#pragma unroll
            for (int j = 0; j < 4; j++) {
                uint32_t bb[4];
                int row = j * 16 + (mat & 1) * 8 + wi;
                int u = 2 * ks + (mat >> 1);
                ldsm_x4(bb[0], bb[1], bb[2], bb[3],
                        skb + row * 128 + (((u ^ row) & 7) << 4));
                mma16816(s[j * 2 + 0], a0, bb[0], bb[2]);
                mma16816(s[j * 2 + 1], a0, bb[1], bb[3]);
                mma16816(s[j * 2 + 0], a1, bb[0], bb[2]);
                mma16816(s[j * 2 + 1], a1, bb[1], bb[3]);
            }
        }

        // ---- online softmax ----
        float nm0 = -1e30f, nm1 = -1e30f;
#pragma unroll
        for (int nn = 0; nn < 8; nn++) {
            nm0 = fmaxf(nm0, fmaxf(s[nn][0], s[nn][1]));
            nm1 = fmaxf(nm1, fmaxf(s[nn][2], s[nn][3]));
        }
        nm0 = fmaxf(nm0, __shfl_xor_sync(0xffffffffu, nm0, 1));
        nm0 = fmaxf(nm0, __shfl_xor_sync(0xffffffffu, nm0, 2));
        nm1 = fmaxf(nm1, __shfl_xor_sync(0xffffffffu, nm1, 1));
        nm1 = fmaxf(nm1, __shfl_xor_sync(0xffffffffu, nm1, 2));
        nm0 = fmaxf(nm0, m0);
        nm1 = fmaxf(nm1, m1);
        float al0 = fexp2((m0 - nm0) * LOG2E);
        float al1 = fexp2((m1 - nm1) * LOG2E);
        m0 = nm0;
        m1 = nm1;

        float sum0 = 0.0f, sum1 = 0.0f;
        uint32_t ph0[8], ph1[8], pl0[8], pl1[8];
#pragma unroll
        for (int nn = 0; nn < 8; nn++) {
            float p00 = fexp2((s[nn][0] - m0) * LOG2E);
            float p01 = fexp2((s[nn][1] - m0) * LOG2E);
            float p10 = fexp2((s[nn][2] - m1) * LOG2E);
            float p11 = fexp2((s[nn][3] - m1) * LOG2E);
            sum0 += p00 + p01;
            sum1 += p10 + p11;
            ph0[nn] = packh2(p00, p01);
            ph1[nn] = packh2(p10, p11);
            __half2 h0 = *reinterpret_cast<__half2*>(&ph0[nn]);
            __half2 h1 = *reinterpret_cast<__half2*>(&ph1[nn]);
            pl0[nn] = packh2(p00 - __low2float(h0), p01 - __high2float(h0));
            pl1[nn] = packh2(p10 - __low2float(h1), p11 - __high2float(h1));
        }
        sum0 += __shfl_xor_sync(0xffffffffu, sum0, 1);
        sum0 += __shfl_xor_sync(0xffffffffu, sum0, 2);
        sum1 += __shfl_xor_sync(0xffffffffu, sum1, 1);
        sum1 += __shfl_xor_sync(0xffffffffu, sum1, 2);
        l0 = l0 * al0 + sum0;
        l1 = l1 * al1 + sum1;
#pragma unroll
        for (int nn = 0; nn < 8; nn++) {
            o[nn][0] *= al0;
            o[nn][1] *= al0;
            o[nn][2] *= al1;
            o[nn][3] *= al1;
        }

        // ---- O += P @ V  (Vhi frag shared by Phi & Plo; Vlo with Phi) ----
#pragma unroll
        for (int ks = 0; ks < 4; ks++) {
            uint32_t ah[4] = { ph0[2 * ks], ph1[2 * ks],
                               ph0[2 * ks + 1], ph1[2 * ks + 1] };
            uint32_t al[4] = { pl0[2 * ks], pl1[2 * ks],
                               pl0[2 * ks + 1], pl1[2 * ks + 1] };
#pragma unroll
            for (int j = 0; j < 4; j++) {
                int krow = ks * 16 + (mat & 1) * 8 + wi;
                int u = j * 2 + (mat >> 1);
                int swu = u ^ (krow & 7);
                uint32_t vhi[4];
                ldsm_x4_t(vhi[0], vhi[1], vhi[2], vhi[3],
                          sv + krow * 128 + swu * 16);
                mma16816(o[j * 2 + 0], ah, vhi[0], vhi[1]);
                mma16816(o[j * 2 + 1], ah, vhi[2], vhi[3]);
                mma16816(o[j * 2 + 0], al, vhi[0], vhi[1]);
                mma16816(o[j * 2 + 1], al, vhi[2], vhi[3]);
                uint32_t vlo[4];
                ldsm_x4_t(vlo[0], vlo[1], vlo[2], vlo[3],
                          sv + 8192 + krow * 128 + swu * 16);
                mma16816(o[j * 2 + 0], ah, vlo[0], vlo[1]);
                mma16816(o[j * 2 + 1], ah, vlo[2], vlo[3]);
            }
        }
    }

    // ---- epilogue: normalize, write split [hi|lo] proj input ----
    float inv0 = 1.0f / l0;
    float inv1 = 1.0f / l1;
    int s0 = qb * 128 + wid * 16 + (lane >> 2);
    int s1 = s0 + 8;
#pragma unroll
    for (int nn = 0; nn < 8; nn++) {
        int d = h * 64 + nn * 8 + (lane & 3) * 2;
#pragma unroll
        for (int rp = 0; rp < 2; rp++) {
            int srow = rp ? s1 : s0;
            float inv = rp ? inv1 : inv0;
            float v0 = o[nn][rp * 2 + 0] * inv;
            float v1 = o[nn][rp * 2 + 1] * inv;
            __half h0 = __float2half_rn(v0);
            __half h1 = __float2half_rn(v1);
            __half l0h = __float2half_rn(v0 - __half2float(h0));
            __half l1h = __float2half_rn(v1 - __half2float(h1));
            __half* p = a2out + (size_t)(b * S_ + srow) * KEFF + d;
            *reinterpret_cast<__half2*>(p)        = __halves2half2(h0, h1);
            *reinterpret_cast<__half2*>(p + 1024) = __halves2half2(l0h, l1h);
        }
    }
}

// ---------------------------------------------------------------------------
extern "C" void kernel_launch(void* const* d_in, const int* in_sizes, int n_in,
                              void* d_out, int out_size)
{
    const float* x      = (const float*)d_in[0];
    const float* w_qkv  = (const float*)d_in[1];
    const float* b_qkv  = (const float*)d_in[2];
    const float* w_proj = (const float*)d_in[3];
    const float* b_proj = (const float*)d_in[4];
    float* out = (float*)d_out;

    __half *a1_p, *a2_p, *wq_p, *wp_p;
    cudaGetSymbolAddress((void**)&a1_p, g_a1);
    cudaGetSymbolAddress((void**)&a2_p, g_a2);
    cudaGetSymbolAddress((void**)&wq_p, g_wqkvT);
    cudaGetSymbolAddress((void**)&wp_p, g_wprojT);

    cudaFuncSetAttribute(gemm_hmma_kernel<0>,
                         cudaFuncAttributeMaxDynamicSharedMemorySize, GEMM_SMEM);
    cudaFuncSetAttribute(gemm_hmma_kernel<1>,
                         cudaFuncAttributeMaxDynamicSharedMemorySize, GEMM_SMEM);
    cudaFuncSetAttribute(flash_kernel,
                         cudaFuncAttributeMaxDynamicSharedMemorySize, FA_SMEM);

    // 1) splits
    split_a_kernel<<<(M_TOT * D_) / 256, 256>>>(x, a1_p);
    transpose_hi_kernel<<<dim3((3 * D_) / 32, D_ / 32), dim3(32, 8)>>>(
        w_qkv, wq_p, 3 * D_);
    transpose_hi_kernel<<<dim3(D_ / 32, D_ / 32), dim3(32, 8)>>>(
        w_proj, wp_p, D_);

    // 2) QKV GEMM (epilogue writes split/scaled Q,K,V directly)
    gemm_hmma_kernel<1><<<dim3((3 * D_) / 128, M_TOT / 128), 128, GEMM_SMEM>>>(
        a1_p, wq_p, b_qkv, nullptr, 3 * D_);

    // 3) flash attention (epilogue writes split proj input)
    flash_kernel<<<dim3(S_ / 128, H_, B_), 256, FA_SMEM>>>(a2_p);

    // 4) projection GEMM
    gemm_hmma_kernel<0><<<dim3(D_ / 128, M_TOT / 128), 128, GEMM_SMEM>>>(
        a2_p, wp_p, b_proj, out, D_);
}

// round 14
// speedup vs baseline: 1.8941x; 1.0946x over previous
#include <cuda_runtime.h>
#include <cuda_fp16.h>
#include <cstdint>

#define B_ 2
#define S_ 2048
#define D_ 1024
#define H_ 16
#define HD_ 64
#define M_TOT 4096
#define KEFF 2048          // [hi|lo] split concat for A-side
#define NKITER 32          // KEFF / 64
#define LOG2E 1.44269504f

// ---------------------------------------------------------------------------
// Scratch (device globals; no allocation)
// ---------------------------------------------------------------------------
__device__ __half g_a1[(size_t)M_TOT * KEFF];          // x split [hi|lo]
__device__ __half g_a2[(size_t)M_TOT * KEFF];          // attn-out split [hi|lo]
__device__ __half g_wqkvT[(size_t)(3 * D_) * D_];      // w_qkv^T hi [3072,1024]
__device__ __half g_wprojT[(size_t)D_ * D_];           // w_proj^T hi [1024,1024]
__device__ __half g_Q[(size_t)B_ * H_ * S_ * 128];     // scaled q split [hi|lo]
__device__ __half g_K[(size_t)B_ * H_ * S_ * 64];      // k hi
__device__ __half g_Vhi[(size_t)B_ * H_ * S_ * 64];    // v hi (lo dropped)

// ---------------------------------------------------------------------------
// PTX helpers
// ---------------------------------------------------------------------------
__device__ __forceinline__ uint32_t smem_u32(const void* p) {
    uint32_t a;
    asm("{ .reg .u64 t; cvta.to.shared.u64 t, %1; cvt.u32.u64 %0, t; }"
        : "=r"(a) : "l"(p));
    return a;
}
#define CP_ASYNC16(dst, src) \
    asm volatile("cp.async.cg.shared.global [%0], [%1], 16;" \
                 :: "r"(dst), "l"(src))
#define CP_COMMIT() asm volatile("cp.async.commit_group;")
#define CP_WAIT(n)  asm volatile("cp.async.wait_group %0;" :: "n"(n))

__device__ __forceinline__ void ldsm_x4(uint32_t& r0, uint32_t& r1,
                                        uint32_t& r2, uint32_t& r3,
                                        uint32_t addr) {
    asm volatile("ldmatrix.sync.aligned.m8n8.x4.shared.b16 {%0,%1,%2,%3}, [%4];"
                 : "=r"(r0), "=r"(r1), "=r"(r2), "=r"(r3) : "r"(addr));
}
__device__ __forceinline__ void ldsm_x4_t(uint32_t& r0, uint32_t& r1,
                                          uint32_t& r2, uint32_t& r3,
                                          uint32_t addr) {
    asm volatile("ldmatrix.sync.aligned.m8n8.x4.trans.shared.b16 {%0,%1,%2,%3}, [%4];"
                 : "=r"(r0), "=r"(r1), "=r"(r2), "=r"(r3) : "r"(addr));
}
__device__ __forceinline__ void mma16816(float* c, const uint32_t* a,
                                         uint32_t b0, uint32_t b1) {
    asm volatile(
        "mma.sync.aligned.m16n8k16.row.col.f32.f16.f16.f32 "
        "{%0,%1,%2,%3}, {%4,%5,%6,%7}, {%8,%9}, {%0,%1,%2,%3};"
        : "+f"(c[0]), "+f"(c[1]), "+f"(c[2]), "+f"(c[3])
        : "r"(a[0]), "r"(a[1]), "r"(a[2]), "r"(a[3]), "r"(b0), "r"(b1));
}

// MUFU exp2 (approx — plenty for softmax weights)
__device__ __forceinline__ float fexp2(float t) {
    float r;
    asm("ex2.approx.ftz.f32 %0, %1;" : "=f"(r) : "f"(t));
    return r;
}

__device__ __forceinline__ uint32_t packh2(float a, float b) {
    __half2 h = __floats2half2_rn(a, b);
    return *reinterpret_cast<uint32_t*>(&h);
}

// ---------------------------------------------------------------------------
// fp16 split conversion kernels
// ---------------------------------------------------------------------------
__global__ __launch_bounds__(256) void split_a_kernel(
    const float* __restrict__ src, __half* __restrict__ dst)
{
    int i = blockIdx.x * 256 + threadIdx.x;
    float v = src[i];
    __half hi = __float2half_rn(v);
    __half lo = __float2half_rn(v - __half2float(hi));
    int row = i >> 10;
    int col = i & 1023;
    size_t base = (size_t)row * KEFF;
    dst[base + col] = hi;
    dst[base + 1024 + col] = lo;
}

__global__ __launch_bounds__(256) void transpose_hi_kernel(
    const float* __restrict__ w, __half* __restrict__ wt, int N)
{
    __shared__ float tile[32][33];
    int bx = blockIdx.x * 32;
    int by = blockIdx.y * 32;
    int tx = threadIdx.x;
    int ty = threadIdx.y;
#pragma unroll
    for (int i = ty; i < 32; i += 8)
        tile[i][tx] = w[(size_t)(by + i) * N + bx + tx];
    __syncthreads();
#pragma unroll
    for (int i = ty; i < 32; i += 8) {
        int n = bx + i;
        int k = by + tx;
        wt[(size_t)n * D_ + k] = __float2half_rn(tile[tx][i]);
    }
}

// ---------------------------------------------------------------------------
// HMMA GEMM: C[m,n] = sum_k (A_hi+A_lo)[m,k]*Bt_hi[n,k] (+bias)
// A:[M,2048] ([hi|lo]), Bt:[N,1024] hi. B k-index wraps (kb & 15).
// CTA 128x128, BK=64, 3-stage ring, ONE sync/iter, 128 thr = 4 warps 64x64.
// EPI==0: fp32 C + bias.  EPI==1: QKV epilogue -> g_Q/g_K/g_Vhi.
// ---------------------------------------------------------------------------
#define GEMM_SMEM (3 * 32768)

template <int EPI>
__global__ __launch_bounds__(128) void gemm_hmma_kernel(
    const __half* __restrict__ A, const __half* __restrict__ Bt,
    const float* __restrict__ bias, float* __restrict__ C, int N)
{
    extern __shared__ char smem[];
    const uint32_t sbase = smem_u32(smem);
    const int t = threadIdx.x;
    const int lane = t & 31;
    const int wid = t >> 5;
    const int wm = wid >> 1;          // 0..1
    const int wn = wid & 1;           // 0..1
    const int row0 = blockIdx.y * 128;
    const int col0 = blockIdx.x * 128;

    const __half* Ag = A + (size_t)row0 * KEFF;
    const __half* Bg = Bt + (size_t)col0 * D_;

    float c[4][8][4];
#pragma unroll
    for (int i = 0; i < 4; i++)
#pragma unroll
        for (int j = 0; j < 8; j++)
#pragma unroll
            for (int r = 0; r < 4; r++) c[i][j][r] = 0.0f;

    auto load_stage = [&](int kb, int st) {
        uint32_t sa = sbase + st * 32768;
        uint32_t sb = sa + 16384;
        const __half* Agk = Ag + kb * 64;
        const __half* Bgk = Bg + (kb & 15) * 64;
#pragma unroll
        for (int i = 0; i < 8; i++) {
            int id = t + 128 * i;          // 0..1023
            int r = id >> 3;               // 0..127
            int u = id & 7;
            uint32_t sw = (uint32_t)(r * 128 + ((u ^ (r & 7)) << 4));
            CP_ASYNC16(sa + sw, Agk + (size_t)r * KEFF + u * 8);
            CP_ASYNC16(sb + sw, Bgk + (size_t)r * D_ + u * 8);
        }
    };

    load_stage(0, 0);
    CP_COMMIT();
    load_stage(1, 1);
    CP_COMMIT();

    const int mat = lane >> 3;
    const int wi = lane & 7;

    for (int kb = 0; kb < NKITER; kb++) {
        if (kb + 1 < NKITER) { CP_WAIT(1); } else { CP_WAIT(0); }
        __syncthreads();
        if (kb + 2 < NKITER) {
            load_stage(kb + 2, (kb + 2) % 3);
            CP_COMMIT();
        }

        uint32_t sa = sbase + (kb % 3) * 32768;
        uint32_t sb = sa + 16384;

#pragma unroll
        for (int s = 0; s < 4; s++) {
            uint32_t a[4][4];
#pragma unroll
            for (int mi = 0; mi < 4; mi++) {
                int row = wm * 64 + mi * 16 + (mat & 1) * 8 + wi;
                int u = 2 * s + (mat >> 1);
                ldsm_x4(a[mi][0], a[mi][1], a[mi][2], a[mi][3],
                        sa + row * 128 + (((u ^ wi) & 7) << 4));
            }
            uint32_t b[4][4];
#pragma unroll
            for (int j = 0; j < 4; j++) {
                int row = wn * 64 + j * 16 + (mat & 1) * 8 + wi;
                int u = 2 * s + (mat >> 1);
                ldsm_x4(b[j][0], b[j][1], b[j][2], b[j][3],
                        sb + row * 128 + (((u ^ wi) & 7) << 4));
            }
#pragma unroll
            for (int mi = 0; mi < 4; mi++)
#pragma unroll
                for (int nn = 0; nn < 8; nn++)
                    mma16816(c[mi][nn], a[mi],
                             b[nn >> 1][nn & 1], b[nn >> 1][(nn & 1) + 2]);
        }
    }

    // Epilogue
#pragma unroll
    for (int mi = 0; mi < 4; mi++) {
#pragma unroll
        for (int nn = 0; nn < 8; nn++) {
#pragma unroll
            for (int rp = 0; rp < 2; rp++) {
                int m = row0 + wm * 64 + mi * 16 + (lane >> 2) + rp * 8;
                int n = col0 + wn * 64 + nn * 8 + (lane & 3) * 2;
                float v0 = c[mi][nn][rp * 2 + 0] + bias[n];
                float v1 = c[mi][nn][rp * 2 + 1] + bias[n + 1];
                if (EPI == 0) {
                    float2 v = make_float2(v0, v1);
                    *reinterpret_cast<float2*>(C + (size_t)m * N + n) = v;
                } else {
                    int type = n >> 10;
                    int rr = n & 1023;
                    int h = rr >> 6;
                    int d = rr & 63;
                    int b = m >> 11;
                    int s = m & 2047;
                    if (type == 0) { v0 *= 0.125f; v1 *= 0.125f; }
                    __half h0 = __float2half_rn(v0);
                    __half h1 = __float2half_rn(v1);
                    __half2 hh = __halves2half2(h0, h1);
                    size_t hb = (size_t)(b * H_ + h) * S_ + s;
                    if (type == 0) {            // Q: [hi|lo], pre-scaled
                        __half l0 = __float2half_rn(v0 - __half2float(h0));
                        __half l1 = __float2half_rn(v1 - __half2float(h1));
                        __half* p = g_Q + hb * 128 + d;
                        *reinterpret_cast<__half2*>(p)      = hh;
                        *reinterpret_cast<__half2*>(p + 64) = __halves2half2(l0, l1);
                    } else if (type == 1) {     // K: hi only
                        *reinterpret_cast<__half2*>(g_K + hb * 64 + d) = hh;
                    } else {                    // V: hi only
                        *reinterpret_cast<__half2*>(g_Vhi + hb * 64 + d) = hh;
                    }
                }
            }
        }
    }
}

// ---------------------------------------------------------------------------
// Flash attention (HMMA): q-tile 128 (Q [hi|lo]), key blocks of 64 (K hi,
// one ldsm feeds BOTH Q halves). PV: (Phi + Plo) @ Vhi — one Vhi frag feeds
// both P terms (1 ldsm : 4 mma per (ks,j)). 3-stage KV ring, one sync/iter,
// MUFU exp2.  Smem: Q 32K + 3 x 16K = 80K -> 2 CTAs/SM.
// ---------------------------------------------------------------------------
#define FA_STAGE  16384
#define FA_SMEM   (32768 + 3 * FA_STAGE)

__global__ __launch_bounds__(256) void flash_kernel(__half* __restrict__ a2out)
{
    extern __shared__ char smem[];
    const uint32_t sQ = smem_u32(smem);
    const uint32_t sKV0 = sQ + 32768;
    const int t = threadIdx.x;
    const int lane = t & 31;
    const int wid = t >> 5;
    const int qb = blockIdx.x;
    const int h = blockIdx.y;
    const int b = blockIdx.z;

    const size_t headbase = (size_t)(b * H_ + h) * S_;
    const __half* Qg = g_Q + (headbase + qb * 128) * 128;
    const __half* Kg = g_K + headbase * 64;
    const __half* Vh = g_Vhi + headbase * 64;

    // Load Q tile (128 x 128 fp16, 256B rows, swizzled within 128B halves)
#pragma unroll
    for (int i = 0; i < 8; i++) {
        int id = t + 256 * i;
        int r = id >> 4;
        int u = id & 15;
        int swu = (u & 8) | ((u ^ r) & 7);
        CP_ASYNC16(sQ + r * 256 + swu * 16, Qg + (size_t)r * 128 + u * 8);
    }

    auto loadKV = [&](int kb, int st) {
        uint32_t sk = sKV0 + st * FA_STAGE;
        uint32_t sv = sk + 8192;
        const __half* kg = Kg + (size_t)kb * 64 * 64;
        const __half* vh = Vh + (size_t)kb * 64 * 64;
#pragma unroll
        for (int i = 0; i < 2; i++) {
            int id = t + 256 * i;
            int r = id >> 3;
            int u = id & 7;
            int swu = u ^ (r & 7);
            CP_ASYNC16(sk + r * 128 + swu * 16, kg + (size_t)r * 64 + u * 8);
            CP_ASYNC16(sv + r * 128 + swu * 16, vh + (size_t)r * 64 + u * 8);
        }
    };

    loadKV(0, 0);
    CP_COMMIT();
    loadKV(1, 1);
    CP_COMMIT();

    float o[8][4];
#pragma unroll
    for (int i = 0; i < 8; i++)
#pragma unroll
        for (int j = 0; j < 4; j++) o[i][j] = 0.0f;
    float m0 = -1e30f, m1 = -1e30f, l0 = 0.0f, l1 = 0.0f;

    const int mat = lane >> 3;
    const int wi = lane & 7;

    for (int kb = 0; kb < 32; kb++) {
        if (kb + 1 < 32) { CP_WAIT(1); } else { CP_WAIT(0); }
        __syncthreads();
        if (kb + 2 < 32) {
            loadKV(kb + 2, (kb + 2) % 3);
            CP_COMMIT();
        }

        int st = kb % 3;
        uint32_t skb = sKV0 + st * FA_STAGE;
        uint32_t sv = skb + 8192;

        // ---- scores: S = (Qhi + Qlo) @ Khi^T  (K frag shared by halves) ----
        float s[8][4];
#pragma unroll
        for (int i = 0; i < 8; i++)
#pragma unroll
            for (int j = 0; j < 4; j++) s[i][j] = 0.0f;

#pragma unroll
        for (int ks = 0; ks < 4; ks++) {
            uint32_t a0[4], a1[4];
            {
                int row = wid * 16 + (mat & 1) * 8 + wi;
                int u0 = 2 * ks + (mat >> 1);          // hi half
                int u1 = 8 + 2 * ks + (mat >> 1);      // lo half
                int swu0 = (u0 & 8) | ((u0 ^ row) & 7);
                int swu1 = (u1 & 8) | ((u1 ^ row) & 7);
                ldsm_x4(a0[0], a0[1], a0[2], a0[3], sQ + row * 256 + swu0 * 16);
                ldsm_x4(a1[0], a1[1], a1[2], a1[3], sQ + row * 256 + swu1 * 16);
            }
#pragma unroll
            for (int j = 0; j < 4; j++) {
                uint32_t bb[4];
                int row = j * 16 + (mat & 1) * 8 + wi;
                int u = 2 * ks + (mat >> 1);
                ldsm_x4(bb[0], bb[1], bb[2], bb[3],
                        skb + row * 128 + (((u ^ row) & 7) << 4));
                mma16816(s[j * 2 + 0], a0, bb[0], bb[2]);
                mma16816(s[j * 2 + 1], a0, bb[1], bb[3]);
                mma16816(s[j * 2 + 0], a1, bb[0], bb[2]);
                mma16816(s[j * 2 + 1], a1, bb[1], bb[3]);
            }
        }

        // ---- online softmax ----
        float nm0 = -1e30f, nm1 = -1e30f;
#pragma unroll
        for (int nn = 0; nn < 8; nn++) {
            nm0 = fmaxf(nm0, fmaxf(s[nn][0], s[nn][1]));
            nm1 = fmaxf(nm1, fmaxf(s[nn][2], s[nn][3]));
        }
        nm0 = fmaxf(nm0, __shfl_xor_sync(0xffffffffu, nm0, 1));
        nm0 = fmaxf(nm0, __shfl_xor_sync(0xffffffffu, nm0, 2));
        nm1 = fmaxf(nm1, __shfl_xor_sync(0xffffffffu, nm1, 1));
        nm1 = fmaxf(nm1, __shfl_xor_sync(0xffffffffu, nm1, 2));
        nm0 = fmaxf(nm0, m0);
        nm1 = fmaxf(nm1, m1);
        float al0 = fexp2((m0 - nm0) * LOG2E);
        float al1 = fexp2((m1 - nm1) * LOG2E);
        m0 = nm0;
        m1 = nm1;

        float sum0 = 0.0f, sum1 = 0.0f;
        uint32_t ph0[8], ph1[8], pl0[8], pl1[8];
#pragma unroll
        for (int nn = 0; nn < 8; nn++) {
            float p00 = fexp2((s[nn][0] - m0) * LOG2E);
            float p01 = fexp2((s[nn][1] - m0) * LOG2E);
            float p10 = fexp2((s[nn][2] - m1) * LOG2E);
            float p11 = fexp2((s[nn][3] - m1) * LOG2E);
            sum0 += p00 + p01;
            sum1 += p10 + p11;
            ph0[nn] = packh2(p00, p01);
            ph1[nn] = packh2(p10, p11);
            __half2 h0 = *reinterpret_cast<__half2*>(&ph0[nn]);
            __half2 h1 = *reinterpret_cast<__half2*>(&ph1[nn]);
            pl0[nn] = packh2(p00 - __low2float(h0), p01 - __high2float(h0));
            pl1[nn] = packh2(p10 - __low2float(h1), p11 - __high2float(h1));
        }
        sum0 += __shfl_xor_sync(0xffffffffu, sum0, 1);
        sum0 += __shfl_xor_sync(0xffffffffu, sum0, 2);
        sum1 += __shfl_xor_sync(0xffffffffu, sum1, 1);
        sum1 += __shfl_xor_sync(0xffffffffu, sum1, 2);
        l0 = l0 * al0 + sum0;
        l1 = l1 * al1 + sum1;
#pragma unroll
        for (int nn = 0; nn < 8; nn++) {
            o[nn][0] *= al0;
            o[nn][1] *= al0;
            o[nn][2] *= al1;
            o[nn][3] *= al1;
        }

        // ---- O += (Phi + Plo) @ Vhi  (one Vhi frag feeds both P terms) ----
#pragma unroll
        for (int ks = 0; ks < 4; ks++) {
            uint32_t ah[4] = { ph0[2 * ks], ph1[2 * ks],
                               ph0[2 * ks + 1], ph1[2 * ks + 1] };
            uint32_t al[4] = { pl0[2 * ks], pl1[2 * ks],
                               pl0[2 * ks + 1], pl1[2 * ks + 1] };
#pragma unroll
            for (int j = 0; j < 4; j++) {
                int krow = ks * 16 + (mat & 1) * 8 + wi;
                int u = j * 2 + (mat >> 1);
                int swu = u ^ (krow & 7);
                uint32_t vhi[4];
                ldsm_x4_t(vhi[0], vhi[1], vhi[2], vhi[3],
                          sv + krow * 128 + swu * 16);
                mma16816(o[j * 2 + 0], ah, vhi[0], vhi[1]);
                mma16816(o[j * 2 + 1], ah, vhi[2], vhi[3]);
                mma16816(o[j * 2 + 0], al, vhi[0], vhi[1]);
                mma16816(o[j * 2 + 1], al, vhi[2], vhi[3]);
            }
        }
    }

    // ---- epilogue: normalize, write split [hi|lo] proj input ----
    float inv0 = 1.0f / l0;
    float inv1 = 1.0f / l1;
    int s0 = qb * 128 + wid * 16 + (lane >> 2);
    int s1 = s0 + 8;
#pragma unroll
    for (int nn = 0; nn < 8; nn++) {
        int d = h * 64 + nn * 8 + (lane & 3) * 2;
#pragma unroll
        for (int rp = 0; rp < 2; rp++) {
            int srow = rp ? s1 : s0;
            float inv = rp ? inv1 : inv0;
            float v0 = o[nn][rp * 2 + 0] * inv;
            float v1 = o[nn][rp * 2 + 1] * inv;
            __half h0 = __float2half_rn(v0);
            __half h1 = __float2half_rn(v1);
            __half l0h = __float2half_rn(v0 - __half2float(h0));
            __half l1h = __float2half_rn(v1 - __half2float(h1));
            __half* p = a2out + (size_t)(b * S_ + srow) * KEFF + d;
            *reinterpret_cast<__half2*>(p)        = __halves2half2(h0, h1);
            *reinterpret_cast<__half2*>(p + 1024) = __halves2half2(l0h, l1h);
        }
    }
}

// ---------------------------------------------------------------------------
extern "C" void kernel_launch(void* const* d_in, const int* in_sizes, int n_in,
                              void* d_out, int out_size)
{
    const float* x      = (const float*)d_in[0];
    const float* w_qkv  = (const float*)d_in[1];
    const float* b_qkv  = (const float*)d_in[2];
    const float* w_proj = (const float*)d_in[3];
    const float* b_proj = (const float*)d_in[4];
    float* out = (float*)d_out;

    __half *a1_p, *a2_p, *wq_p, *wp_p;
    cudaGetSymbolAddress((void**)&a1_p, g_a1);
    cudaGetSymbolAddress((void**)&a2_p, g_a2);
    cudaGetSymbolAddress((void**)&wq_p, g_wqkvT);
    cudaGetSymbolAddress((void**)&wp_p, g_wprojT);

    cudaFuncSetAttribute(gemm_hmma_kernel<0>,
                         cudaFuncAttributeMaxDynamicSharedMemorySize, GEMM_SMEM);
    cudaFuncSetAttribute(gemm_hmma_kernel<1>,
                         cudaFuncAttributeMaxDynamicSharedMemorySize, GEMM_SMEM);
    cudaFuncSetAttribute(flash_kernel,
                         cudaFuncAttributeMaxDynamicSharedMemorySize, FA_SMEM);

    // 1) splits
    split_a_kernel<<<(M_TOT * D_) / 256, 256>>>(x, a1_p);
    transpose_hi_kernel<<<dim3((3 * D_) / 32, D_ / 32), dim3(32, 8)>>>(
        w_qkv, wq_p, 3 * D_);
    transpose_hi_kernel<<<dim3(D_ / 32, D_ / 32), dim3(32, 8)>>>(
        w_proj, wp_p, D_);

    // 2) QKV GEMM (epilogue writes split/scaled Q,K,V directly)
    gemm_hmma_kernel<1><<<dim3((3 * D_) / 128, M_TOT / 128), 128, GEMM_SMEM>>>(
        a1_p, wq_p, b_qkv, nullptr, 3 * D_);

    // 3) flash attention (epilogue writes split proj input)
    flash_kernel<<<dim3(S_ / 128, H_, B_), 256, FA_SMEM>>>(a2_p);

    // 4) projection GEMM
    gemm_hmma_kernel<0><<<dim3(D_ / 128, M_TOT / 128), 128, GEMM_SMEM>>>(
        a2_p, wp_p, b_proj, out, D_);
}

// round 15
// speedup vs baseline: 2.1458x; 1.1329x over previous
#include <cuda_runtime.h>
#include <cuda_fp16.h>
#include <cstdint>

#define B_ 2
#define S_ 2048
#define D_ 1024
#define H_ 16
#define HD_ 64
#define M_TOT 4096
#define KEFF 2048          // [hi|lo] split concat for A-side
#define NKITER 32          // KEFF / 64
#define LOG2E 1.44269504f

// ---------------------------------------------------------------------------
// Scratch (device globals; no allocation)
// ---------------------------------------------------------------------------
__device__ __half g_a1[(size_t)M_TOT * KEFF];          // x split [hi|lo]
__device__ __half g_a2[(size_t)M_TOT * KEFF];          // attn-out split [hi|lo]
__device__ __half g_wqkvT[(size_t)(3 * D_) * D_];      // w_qkv^T hi [3072,1024]
__device__ __half g_wprojT[(size_t)D_ * D_];           // w_proj^T hi [1024,1024]
__device__ __half g_Q[(size_t)B_ * H_ * S_ * 64];      // scaled q hi
__device__ __half g_K[(size_t)B_ * H_ * S_ * 64];      // k hi
__device__ __half g_Vhi[(size_t)B_ * H_ * S_ * 64];    // v hi

// ---------------------------------------------------------------------------
// PTX helpers
// ---------------------------------------------------------------------------
__device__ __forceinline__ uint32_t smem_u32(const void* p) {
    uint32_t a;
    asm("{ .reg .u64 t; cvta.to.shared.u64 t, %1; cvt.u32.u64 %0, t; }"
        : "=r"(a) : "l"(p));
    return a;
}
#define CP_ASYNC16(dst, src) \
    asm volatile("cp.async.cg.shared.global [%0], [%1], 16;" \
                 :: "r"(dst), "l"(src))
#define CP_COMMIT() asm volatile("cp.async.commit_group;")
#define CP_WAIT(n)  asm volatile("cp.async.wait_group %0;" :: "n"(n))

__device__ __forceinline__ void ldsm_x4(uint32_t& r0, uint32_t& r1,
                                        uint32_t& r2, uint32_t& r3,
                                        uint32_t addr) {
    asm volatile("ldmatrix.sync.aligned.m8n8.x4.shared.b16 {%0,%1,%2,%3}, [%4];"
                 : "=r"(r0), "=r"(r1), "=r"(r2), "=r"(r3) : "r"(addr));
}
__device__ __forceinline__ void ldsm_x4_t(uint32_t& r0, uint32_t& r1,
                                          uint32_t& r2, uint32_t& r3,
                                          uint32_t addr) {
    asm volatile("ldmatrix.sync.aligned.m8n8.x4.trans.shared.b16 {%0,%1,%2,%3}, [%4];"
                 : "=r"(r0), "=r"(r1), "=r"(r2), "=r"(r3) : "r"(addr));
}
__device__ __forceinline__ void mma16816(float* c, const uint32_t* a,
                                         uint32_t b0, uint32_t b1) {
    asm volatile(
        "mma.sync.aligned.m16n8k16.row.col.f32.f16.f16.f32 "
        "{%0,%1,%2,%3}, {%4,%5,%6,%7}, {%8,%9}, {%0,%1,%2,%3};"
        : "+f"(c[0]), "+f"(c[1]), "+f"(c[2]), "+f"(c[3])
        : "r"(a[0]), "r"(a[1]), "r"(a[2]), "r"(a[3]), "r"(b0), "r"(b1));
}

// MUFU exp2 (approx — plenty for softmax weights)
__device__ __forceinline__ float fexp2(float t) {
    float r;
    asm("ex2.approx.ftz.f32 %0, %1;" : "=f"(r) : "f"(t));
    return r;
}

__device__ __forceinline__ uint32_t packh2(float a, float b) {
    __half2 h = __floats2half2_rn(a, b);
    return *reinterpret_cast<uint32_t*>(&h);
}

// ---------------------------------------------------------------------------
// fp16 split conversion kernels
// ---------------------------------------------------------------------------
__global__ __launch_bounds__(256) void split_a_kernel(
    const float4* __restrict__ src, __half* __restrict__ dst)
{
    int i = blockIdx.x * 256 + threadIdx.x;    // over M*D/4 = 1M
    float4 v = src[i];
    int idx = i << 2;
    int row = idx >> 10;
    int col = idx & 1023;
    __half h0 = __float2half_rn(v.x);
    __half h1 = __float2half_rn(v.y);
    __half h2 = __float2half_rn(v.z);
    __half h3 = __float2half_rn(v.w);
    __half l0 = __float2half_rn(v.x - __half2float(h0));
    __half l1 = __float2half_rn(v.y - __half2float(h1));
    __half l2 = __float2half_rn(v.z - __half2float(h2));
    __half l3 = __float2half_rn(v.w - __half2float(h3));
    size_t base = (size_t)row * KEFF + col;
    __half2* ph = reinterpret_cast<__half2*>(dst + base);
    ph[0] = __halves2half2(h0, h1);
    ph[1] = __halves2half2(h2, h3);
    __half2* pl = reinterpret_cast<__half2*>(dst + base + 1024);
    pl[0] = __halves2half2(l0, l1);
    pl[1] = __halves2half2(l2, l3);
}

__global__ __launch_bounds__(256) void transpose_hi_kernel(
    const float* __restrict__ w, __half* __restrict__ wt, int N)
{
    __shared__ float tile[32][33];
    int bx = blockIdx.x * 32;
    int by = blockIdx.y * 32;
    int tx = threadIdx.x;
    int ty = threadIdx.y;
#pragma unroll
    for (int i = ty; i < 32; i += 8)
        tile[i][tx] = w[(size_t)(by + i) * N + bx + tx];
    __syncthreads();
#pragma unroll
    for (int i = ty; i < 32; i += 8) {
        int n = bx + i;
        int k = by + tx;
        wt[(size_t)n * D_ + k] = __float2half_rn(tile[tx][i]);
    }
}

// ---------------------------------------------------------------------------
// HMMA GEMM: C[m,n] = sum_k (A_hi+A_lo)[m,k]*Bt_hi[n,k] (+bias)
// A:[M,2048] ([hi|lo]), Bt:[N,1024] hi. B k-index wraps (kb & 15).
// CTA 128x128, BK=64, 3-stage ring, ONE sync/iter, 128 thr = 4 warps 64x64.
// EPI==0: fp32 C + bias.  EPI==1: QKV epilogue -> g_Q/g_K/g_Vhi (all hi).
// ---------------------------------------------------------------------------
#define GEMM_SMEM (3 * 32768)

template <int EPI>
__global__ __launch_bounds__(128) void gemm_hmma_kernel(
    const __half* __restrict__ A, const __half* __restrict__ Bt,
    const float* __restrict__ bias, float* __restrict__ C, int N)
{
    extern __shared__ char smem[];
    const uint32_t sbase = smem_u32(smem);
    const int t = threadIdx.x;
    const int lane = t & 31;
    const int wid = t >> 5;
    const int wm = wid >> 1;          // 0..1
    const int wn = wid & 1;           // 0..1
    const int row0 = blockIdx.y * 128;
    const int col0 = blockIdx.x * 128;

    const __half* Ag = A + (size_t)row0 * KEFF;
    const __half* Bg = Bt + (size_t)col0 * D_;

    float c[4][8][4];
#pragma unroll
    for (int i = 0; i < 4; i++)
#pragma unroll
        for (int j = 0; j < 8; j++)
#pragma unroll
            for (int r = 0; r < 4; r++) c[i][j][r] = 0.0f;

    auto load_stage = [&](int kb, int st) {
        uint32_t sa = sbase + st * 32768;
        uint32_t sb = sa + 16384;
        const __half* Agk = Ag + kb * 64;
        const __half* Bgk = Bg + (kb & 15) * 64;
#pragma unroll
        for (int i = 0; i < 8; i++) {
            int id = t + 128 * i;          // 0..1023
            int r = id >> 3;               // 0..127
            int u = id & 7;
            uint32_t sw = (uint32_t)(r * 128 + ((u ^ (r & 7)) << 4));
            CP_ASYNC16(sa + sw, Agk + (size_t)r * KEFF + u * 8);
            CP_ASYNC16(sb + sw, Bgk + (size_t)r * D_ + u * 8);
        }
    };

    load_stage(0, 0);
    CP_COMMIT();
    load_stage(1, 1);
    CP_COMMIT();

    const int mat = lane >> 3;
    const int wi = lane & 7;

    for (int kb = 0; kb < NKITER; kb++) {
        if (kb + 1 < NKITER) { CP_WAIT(1); } else { CP_WAIT(0); }
        __syncthreads();
        if (kb + 2 < NKITER) {
            load_stage(kb + 2, (kb + 2) % 3);
            CP_COMMIT();
        }

        uint32_t sa = sbase + (kb % 3) * 32768;
        uint32_t sb = sa + 16384;

#pragma unroll
        for (int s = 0; s < 4; s++) {
            uint32_t a[4][4];
#pragma unroll
            for (int mi = 0; mi < 4; mi++) {
                int row = wm * 64 + mi * 16 + (mat & 1) * 8 + wi;
                int u = 2 * s + (mat >> 1);
                ldsm_x4(a[mi][0], a[mi][1], a[mi][2], a[mi][3],
                        sa + row * 128 + (((u ^ wi) & 7) << 4));
            }
            uint32_t b[4][4];
#pragma unroll
            for (int j = 0; j < 4; j++) {
                int row = wn * 64 + j * 16 + (mat & 1) * 8 + wi;
                int u = 2 * s + (mat >> 1);
                ldsm_x4(b[j][0], b[j][1], b[j][2], b[j][3],
                        sb + row * 128 + (((u ^ wi) & 7) << 4));
            }
#pragma unroll
            for (int mi = 0; mi < 4; mi++)
#pragma unroll
                for (int nn = 0; nn < 8; nn++)
                    mma16816(c[mi][nn], a[mi],
                             b[nn >> 1][nn & 1], b[nn >> 1][(nn & 1) + 2]);
        }
    }

    // Epilogue
#pragma unroll
    for (int mi = 0; mi < 4; mi++) {
#pragma unroll
        for (int nn = 0; nn < 8; nn++) {
#pragma unroll
            for (int rp = 0; rp < 2; rp++) {
                int m = row0 + wm * 64 + mi * 16 + (lane >> 2) + rp * 8;
                int n = col0 + wn * 64 + nn * 8 + (lane & 3) * 2;
                float v0 = c[mi][nn][rp * 2 + 0] + bias[n];
                float v1 = c[mi][nn][rp * 2 + 1] + bias[n + 1];
                if (EPI == 0) {
                    float2 v = make_float2(v0, v1);
                    *reinterpret_cast<float2*>(C + (size_t)m * N + n) = v;
                } else {
                    int type = n >> 10;
                    int rr = n & 1023;
                    int h = rr >> 6;
                    int d = rr & 63;
                    int b = m >> 11;
                    int s = m & 2047;
                    if (type == 0) { v0 *= 0.125f; v1 *= 0.125f; }
                    __half h0 = __float2half_rn(v0);
                    __half h1 = __float2half_rn(v1);
                    __half2 hh = __halves2half2(h0, h1);
                    size_t hb = (size_t)(b * H_ + h) * S_ + s;
                    if (type == 0) {            // Q: hi only, pre-scaled
                        *reinterpret_cast<__half2*>(g_Q + hb * 64 + d) = hh;
                    } else if (type == 1) {     // K: hi only
                        *reinterpret_cast<__half2*>(g_K + hb * 64 + d) = hh;
                    } else {                    // V: hi only
                        *reinterpret_cast<__half2*>(g_Vhi + hb * 64 + d) = hh;
                    }
                }
            }
        }
    }
}

// ---------------------------------------------------------------------------
// Flash attention (HMMA): q-tile 128 (Q hi only, 64 cols), key blocks of 64
// (K hi). PV: (Phi + Plo) @ Vhi — one Vhi frag feeds both P terms.
// 3-stage KV ring, one sync/iter, MUFU exp2.
// Smem: Q 16K + 3 x 16K = 64K -> 3 CTAs/SM.
// ---------------------------------------------------------------------------
#define FA_STAGE  16384
#define FA_SMEM   (16384 + 3 * FA_STAGE)

__global__ __launch_bounds__(256) void flash_kernel(__half* __restrict__ a2out)
{
    extern __shared__ char smem[];
    const uint32_t sQ = smem_u32(smem);
    const uint32_t sKV0 = sQ + 16384;
    const int t = threadIdx.x;
    const int lane = t & 31;
    const int wid = t >> 5;
    const int qb = blockIdx.x;
    const int h = blockIdx.y;
    const int b = blockIdx.z;

    const size_t headbase = (size_t)(b * H_ + h) * S_;
    const __half* Qg = g_Q + (headbase + qb * 128) * 64;
    const __half* Kg = g_K + headbase * 64;
    const __half* Vh = g_Vhi + headbase * 64;

    // Load Q tile (128 x 64 fp16, 128B rows, swizzled)
#pragma unroll
    for (int i = 0; i < 4; i++) {
        int id = t + 256 * i;          // 0..1023
        int r = id >> 3;               // 0..127
        int u = id & 7;
        int swu = u ^ (r & 7);
        CP_ASYNC16(sQ + r * 128 + swu * 16, Qg + (size_t)r * 64 + u * 8);
    }

    auto loadKV = [&](int kb, int st) {
        uint32_t sk = sKV0 + st * FA_STAGE;
        uint32_t sv = sk + 8192;
        const __half* kg = Kg + (size_t)kb * 64 * 64;
        const __half* vh = Vh + (size_t)kb * 64 * 64;
#pragma unroll
        for (int i = 0; i < 2; i++) {
            int id = t + 256 * i;
            int r = id >> 3;
            int u = id & 7;
            int swu = u ^ (r & 7);
            CP_ASYNC16(sk + r * 128 + swu * 16, kg + (size_t)r * 64 + u * 8);
            CP_ASYNC16(sv + r * 128 + swu * 16, vh + (size_t)r * 64 + u * 8);
        }
    };

    loadKV(0, 0);
    CP_COMMIT();
    loadKV(1, 1);
    CP_COMMIT();

    float o[8][4];
#pragma unroll
    for (int i = 0; i < 8; i++)
#pragma unroll
        for (int j = 0; j < 4; j++) o[i][j] = 0.0f;
    float m0 = -1e30f, m1 = -1e30f, l0 = 0.0f, l1 = 0.0f;

    const int mat = lane >> 3;
    const int wi = lane & 7;

    for (int kb = 0; kb < 32; kb++) {
        if (kb + 1 < 32) { CP_WAIT(1); } else { CP_WAIT(0); }
        __syncthreads();
        if (kb + 2 < 32) {
            loadKV(kb + 2, (kb + 2) % 3);
            CP_COMMIT();
        }

        int st = kb % 3;
        uint32_t skb = sKV0 + st * FA_STAGE;
        uint32_t sv = skb + 8192;

        // ---- scores: S = Qhi @ Khi^T ----
        float s[8][4];
#pragma unroll
        for (int i = 0; i < 8; i++)
#pragma unroll
            for (int j = 0; j < 4; j++) s[i][j] = 0.0f;

#pragma unroll
        for (int ks = 0; ks < 4; ks++) {
            uint32_t a0[4];
            {
                int row = wid * 16 + (mat & 1) * 8 + wi;
                int u = 2 * ks + (mat >> 1);
                ldsm_x4(a0[0], a0[1], a0[2], a0[3],
                        sQ + row * 128 + (((u ^ row) & 7) << 4));
            }
#pragma unroll
            for (int j = 0; j < 4; j++) {
                uint32_t bb[4];
                int row = j * 16 + (mat & 1) * 8 + wi;
                int u = 2 * ks + (mat >> 1);
                ldsm_x4(bb[0], bb[1], bb[2], bb[3],
                        skb + row * 128 + (((u ^ row) & 7) << 4));
                mma16816(s[j * 2 + 0], a0, bb[0], bb[2]);
                mma16816(s[j * 2 + 1], a0, bb[1], bb[3]);
            }
        }

        // ---- online softmax ----
        float nm0 = -1e30f, nm1 = -1e30f;
#pragma unroll
        for (int nn = 0; nn < 8; nn++) {
            nm0 = fmaxf(nm0, fmaxf(s[nn][0], s[nn][1]));
            nm1 = fmaxf(nm1, fmaxf(s[nn][2], s[nn][3]));
        }
        nm0 = fmaxf(nm0, __shfl_xor_sync(0xffffffffu, nm0, 1));
        nm0 = fmaxf(nm0, __shfl_xor_sync(0xffffffffu, nm0, 2));
        nm1 = fmaxf(nm1, __shfl_xor_sync(0xffffffffu, nm1, 1));
        nm1 = fmaxf(nm1, __shfl_xor_sync(0xffffffffu, nm1, 2));
        nm0 = fmaxf(nm0, m0);
        nm1 = fmaxf(nm1, m1);
        float al0 = fexp2((m0 - nm0) * LOG2E);
        float al1 = fexp2((m1 - nm1) * LOG2E);
        m0 = nm0;
        m1 = nm1;

        float sum0 = 0.0f, sum1 = 0.0f;
        uint32_t ph0[8], ph1[8], pl0[8], pl1[8];
#pragma unroll
        for (int nn = 0; nn < 8; nn++) {
            float p00 = fexp2((s[nn][0] - m0) * LOG2E);
            float p01 = fexp2((s[nn][1] - m0) * LOG2E);
            float p10 = fexp2((s[nn][2] - m1) * LOG2E);
            float p11 = fexp2((s[nn][3] - m1) * LOG2E);
            sum0 += p00 + p01;
            sum1 += p10 + p11;
            ph0[nn] = packh2(p00, p01);
            ph1[nn] = packh2(p10, p11);
            __half2 h0 = *reinterpret_cast<__half2*>(&ph0[nn]);
            __half2 h1 = *reinterpret_cast<__half2*>(&ph1[nn]);
            pl0[nn] = packh2(p00 - __low2float(h0), p01 - __high2float(h0));
            pl1[nn] = packh2(p10 - __low2float(h1), p11 - __high2float(h1));
        }
        sum0 += __shfl_xor_sync(0xffffffffu, sum0, 1);
        sum0 += __shfl_xor_sync(0xffffffffu, sum0, 2);
        sum1 += __shfl_xor_sync(0xffffffffu, sum1, 1);
        sum1 += __shfl_xor_sync(0xffffffffu, sum1, 2);
        l0 = l0 * al0 + sum0;
        l1 = l1 * al1 + sum1;
#pragma unroll
        for (int nn = 0; nn < 8; nn++) {
            o[nn][0] *= al0;
            o[nn][1] *= al0;
            o[nn][2] *= al1;
            o[nn][3] *= al1;
        }

        // ---- O += (Phi + Plo) @ Vhi  (one Vhi frag feeds both P terms) ----
#pragma unroll
        for (int ks = 0; ks < 4; ks++) {
            uint32_t ah[4] = { ph0[2 * ks], ph1[2 * ks],
                               ph0[2 * ks + 1], ph1[2 * ks + 1] };
            uint32_t al[4] = { pl0[2 * ks], pl1[2 * ks],
                               pl0[2 * ks + 1], pl1[2 * ks + 1] };
#pragma unroll
            for (int j = 0; j < 4; j++) {
                int krow = ks * 16 + (mat & 1) * 8 + wi;
                int u = j * 2 + (mat >> 1);
                int swu = u ^ (krow & 7);
                uint32_t vhi[4];
                ldsm_x4_t(vhi[0], vhi[1], vhi[2], vhi[3],
                          sv + krow * 128 + swu * 16);
                mma16816(o[j * 2 + 0], ah, vhi[0], vhi[1]);
                mma16816(o[j * 2 + 1], ah, vhi[2], vhi[3]);
                mma16816(o[j * 2 + 0], al, vhi[0], vhi[1]);
                mma16816(o[j * 2 + 1], al, vhi[2], vhi[3]);
            }
        }
    }

    // ---- epilogue: normalize, write split [hi|lo] proj input ----
    float inv0 = 1.0f / l0;
    float inv1 = 1.0f / l1;
    int s0 = qb * 128 + wid * 16 + (lane >> 2);
    int s1 = s0 + 8;
#pragma unroll
    for (int nn = 0; nn < 8; nn++) {
        int d = h * 64 + nn * 8 + (lane & 3) * 2;
#pragma unroll
        for (int rp = 0; rp < 2; rp++) {
            int srow = rp ? s1 : s0;
            float inv = rp ? inv1 : inv0;
            float v0 = o[nn][rp * 2 + 0] * inv;
            float v1 = o[nn][rp * 2 + 1] * inv;
            __half h0 = __float2half_rn(v0);
            __half h1 = __float2half_rn(v1);
            __half l0h = __float2half_rn(v0 - __half2float(h0));
            __half l1h = __float2half_rn(v1 - __half2float(h1));
            __half* p = a2out + (size_t)(b * S_ + srow) * KEFF + d;
            *reinterpret_cast<__half2*>(p)        = __halves2half2(h0, h1);
            *reinterpret_cast<__half2*>(p + 1024) = __halves2half2(l0h, l1h);
        }
    }
}

// ---------------------------------------------------------------------------
extern "C" void kernel_launch(void* const* d_in, const int* in_sizes, int n_in,
                              void* d_out, int out_size)
{
    const float* x      = (const float*)d_in[0];
    const float* w_qkv  = (const float*)d_in[1];
    const float* b_qkv  = (const float*)d_in[2];
    const float* w_proj = (const float*)d_in[3];
    const float* b_proj = (const float*)d_in[4];
    float* out = (float*)d_out;

    __half *a1_p, *a2_p, *wq_p, *wp_p;
    cudaGetSymbolAddress((void**)&a1_p, g_a1);
    cudaGetSymbolAddress((void**)&a2_p, g_a2);
    cudaGetSymbolAddress((void**)&wq_p, g_wqkvT);
    cudaGetSymbolAddress((void**)&wp_p, g_wprojT);

    cudaFuncSetAttribute(gemm_hmma_kernel<0>,
                         cudaFuncAttributeMaxDynamicSharedMemorySize, GEMM_SMEM);
    cudaFuncSetAttribute(gemm_hmma_kernel<1>,
                         cudaFuncAttributeMaxDynamicSharedMemorySize, GEMM_SMEM);
    cudaFuncSetAttribute(flash_kernel,
                         cudaFuncAttributeMaxDynamicSharedMemorySize, FA_SMEM);

    // 1) splits
    split_a_kernel<<<(M_TOT * D_) / 1024, 256>>>(
        reinterpret_cast<const float4*>(x), a1_p);
    transpose_hi_kernel<<<dim3((3 * D_) / 32, D_ / 32), dim3(32, 8)>>>(
        w_qkv, wq_p, 3 * D_);
    transpose_hi_kernel<<<dim3(D_ / 32, D_ / 32), dim3(32, 8)>>>(
        w_proj, wp_p, D_);

    // 2) QKV GEMM (epilogue writes scaled Q/K/V hi directly)
    gemm_hmma_kernel<1><<<dim3((3 * D_) / 128, M_TOT / 128), 128, GEMM_SMEM>>>(
        a1_p, wq_p, b_qkv, nullptr, 3 * D_);

    // 3) flash attention (epilogue writes split proj input)
    flash_kernel<<<dim3(S_ / 128, H_, B_), 256, FA_SMEM>>>(a2_p);

    // 4) projection GEMM
    gemm_hmma_kernel<0><<<dim3(D_ / 128, M_TOT / 128), 128, GEMM_SMEM>>>(
        a2_p, wp_p, b_proj, out, D_);
}

// round 16
// speedup vs baseline: 2.9108x; 1.3565x over previous
#include <cuda_runtime.h>
#include <cuda_fp16.h>
#include <cstdint>

#define B_ 2
#define S_ 2048
#define D_ 1024
#define H_ 16
#define HD_ 64
#define M_TOT 4096
#define NKITER 16          // D_ / 64  (pure hi x hi GEMM)
#define LOG2E 1.44269504f

// ---------------------------------------------------------------------------
// Scratch (device globals; no allocation)
// ---------------------------------------------------------------------------
__device__ __half g_a1[(size_t)M_TOT * D_];            // x hi [4096,1024]
__device__ __half g_a2[(size_t)M_TOT * D_];            // attn-out hi [4096,1024]
__device__ __half g_wqkvT[(size_t)(3 * D_) * D_];      // w_qkv^T hi [3072,1024]
__device__ __half g_wprojT[(size_t)D_ * D_];           // w_proj^T hi [1024,1024]
__device__ __half g_Q[(size_t)B_ * H_ * S_ * 64];      // scaled q hi
__device__ __half g_K[(size_t)B_ * H_ * S_ * 64];      // k hi
__device__ __half g_Vhi[(size_t)B_ * H_ * S_ * 64];    // v hi

// ---------------------------------------------------------------------------
// PTX helpers
// ---------------------------------------------------------------------------
__device__ __forceinline__ uint32_t smem_u32(const void* p) {
    uint32_t a;
    asm("{ .reg .u64 t; cvta.to.shared.u64 t, %1; cvt.u32.u64 %0, t; }"
        : "=r"(a) : "l"(p));
    return a;
}
#define CP_ASYNC16(dst, src) \
    asm volatile("cp.async.cg.shared.global [%0], [%1], 16;" \
                 :: "r"(dst), "l"(src))
#define CP_COMMIT() asm volatile("cp.async.commit_group;")
#define CP_WAIT(n)  asm volatile("cp.async.wait_group %0;" :: "n"(n))

__device__ __forceinline__ void ldsm_x4(uint32_t& r0, uint32_t& r1,
                                        uint32_t& r2, uint32_t& r3,
                                        uint32_t addr) {
    asm volatile("ldmatrix.sync.aligned.m8n8.x4.shared.b16 {%0,%1,%2,%3}, [%4];"
                 : "=r"(r0), "=r"(r1), "=r"(r2), "=r"(r3) : "r"(addr));
}
__device__ __forceinline__ void ldsm_x4_t(uint32_t& r0, uint32_t& r1,
                                          uint32_t& r2, uint32_t& r3,
                                          uint32_t addr) {
    asm volatile("ldmatrix.sync.aligned.m8n8.x4.trans.shared.b16 {%0,%1,%2,%3}, [%4];"
                 : "=r"(r0), "=r"(r1), "=r"(r2), "=r"(r3) : "r"(addr));
}
__device__ __forceinline__ void mma16816(float* c, const uint32_t* a,
                                         uint32_t b0, uint32_t b1) {
    asm volatile(
        "mma.sync.aligned.m16n8k16.row.col.f32.f16.f16.f32 "
        "{%0,%1,%2,%3}, {%4,%5,%6,%7}, {%8,%9}, {%0,%1,%2,%3};"
        : "+f"(c[0]), "+f"(c[1]), "+f"(c[2]), "+f"(c[3])
        : "r"(a[0]), "r"(a[1]), "r"(a[2]), "r"(a[3]), "r"(b0), "r"(b1));
}

// MUFU exp2 (approx — plenty for softmax weights)
__device__ __forceinline__ float fexp2(float t) {
    float r;
    asm("ex2.approx.ftz.f32 %0, %1;" : "=f"(r) : "f"(t));
    return r;
}

__device__ __forceinline__ uint32_t packh2(float a, float b) {
    __half2 h = __floats2half2_rn(a, b);
    return *reinterpret_cast<uint32_t*>(&h);
}

// ---------------------------------------------------------------------------
// Conversion kernels
// ---------------------------------------------------------------------------
__global__ __launch_bounds__(256) void convert_hi_kernel(
    const float4* __restrict__ src, __half2* __restrict__ dst)
{
    int i = blockIdx.x * 256 + threadIdx.x;    // over M*D/4
    float4 v = src[i];
    dst[i * 2 + 0] = __floats2half2_rn(v.x, v.y);
    dst[i * 2 + 1] = __floats2half2_rn(v.z, v.w);
}

__global__ __launch_bounds__(256) void transpose_hi_kernel(
    const float* __restrict__ w, __half* __restrict__ wt, int N)
{
    __shared__ float tile[32][33];
    int bx = blockIdx.x * 32;
    int by = blockIdx.y * 32;
    int tx = threadIdx.x;
    int ty = threadIdx.y;
#pragma unroll
    for (int i = ty; i < 32; i += 8)
        tile[i][tx] = w[(size_t)(by + i) * N + bx + tx];
    __syncthreads();
#pragma unroll
    for (int i = ty; i < 32; i += 8) {
        int n = bx + i;
        int k = by + tx;
        wt[(size_t)n * D_ + k] = __float2half_rn(tile[tx][i]);
    }
}

// ---------------------------------------------------------------------------
// HMMA GEMM: C[m,n] = sum_k A_hi[m,k]*Bt_hi[n,k] (+bias)
// A:[M,1024] hi, Bt:[N,1024] hi.
// CTA 128x128, BK=64, 3-stage ring, ONE sync/iter, 128 thr = 4 warps 64x64.
// EPI==0: fp32 C + bias.  EPI==1: QKV epilogue -> g_Q/g_K/g_Vhi (all hi).
// ---------------------------------------------------------------------------
#define GEMM_SMEM (3 * 32768)

template <int EPI>
__global__ __launch_bounds__(128) void gemm_hmma_kernel(
    const __half* __restrict__ A, const __half* __restrict__ Bt,
    const float* __restrict__ bias, float* __restrict__ C, int N)
{
    extern __shared__ char smem[];
    const uint32_t sbase = smem_u32(smem);
    const int t = threadIdx.x;
    const int lane = t & 31;
    const int wid = t >> 5;
    const int wm = wid >> 1;          // 0..1
    const int wn = wid & 1;           // 0..1
    const int row0 = blockIdx.y * 128;
    const int col0 = blockIdx.x * 128;

    const __half* Ag = A + (size_t)row0 * D_;
    const __half* Bg = Bt + (size_t)col0 * D_;

    float c[4][8][4];
#pragma unroll
    for (int i = 0; i < 4; i++)
#pragma unroll
        for (int j = 0; j < 8; j++)
#pragma unroll
            for (int r = 0; r < 4; r++) c[i][j][r] = 0.0f;

    auto load_stage = [&](int kb, int st) {
        uint32_t sa = sbase + st * 32768;
        uint32_t sb = sa + 16384;
        const __half* Agk = Ag + kb * 64;
        const __half* Bgk = Bg + kb * 64;
#pragma unroll
        for (int i = 0; i < 8; i++) {
            int id = t + 128 * i;          // 0..1023
            int r = id >> 3;               // 0..127
            int u = id & 7;
            uint32_t sw = (uint32_t)(r * 128 + ((u ^ (r & 7)) << 4));
            CP_ASYNC16(sa + sw, Agk + (size_t)r * D_ + u * 8);
            CP_ASYNC16(sb + sw, Bgk + (size_t)r * D_ + u * 8);
        }
    };

    load_stage(0, 0);
    CP_COMMIT();
    load_stage(1, 1);
    CP_COMMIT();

    const int mat = lane >> 3;
    const int wi = lane & 7;

    for (int kb = 0; kb < NKITER; kb++) {
        if (kb + 1 < NKITER) { CP_WAIT(1); } else { CP_WAIT(0); }
        __syncthreads();
        if (kb + 2 < NKITER) {
            load_stage(kb + 2, (kb + 2) % 3);
            CP_COMMIT();
        }

        uint32_t sa = sbase + (kb % 3) * 32768;
        uint32_t sb = sa + 16384;

#pragma unroll
        for (int s = 0; s < 4; s++) {
            uint32_t a[4][4];
#pragma unroll
            for (int mi = 0; mi < 4; mi++) {
                int row = wm * 64 + mi * 16 + (mat & 1) * 8 + wi;
                int u = 2 * s + (mat >> 1);
                ldsm_x4(a[mi][0], a[mi][1], a[mi][2], a[mi][3],
                        sa + row * 128 + (((u ^ wi) & 7) << 4));
            }
            uint32_t b[4][4];
#pragma unroll
            for (int j = 0; j < 4; j++) {
                int row = wn * 64 + j * 16 + (mat & 1) * 8 + wi;
                int u = 2 * s + (mat >> 1);
                ldsm_x4(b[j][0], b[j][1], b[j][2], b[j][3],
                        sb + row * 128 + (((u ^ wi) & 7) << 4));
            }
#pragma unroll
            for (int mi = 0; mi < 4; mi++)
#pragma unroll
                for (int nn = 0; nn < 8; nn++)
                    mma16816(c[mi][nn], a[mi],
                             b[nn >> 1][nn & 1], b[nn >> 1][(nn & 1) + 2]);
        }
    }

    // Epilogue
#pragma unroll
    for (int mi = 0; mi < 4; mi++) {
#pragma unroll
        for (int nn = 0; nn < 8; nn++) {
#pragma unroll
            for (int rp = 0; rp < 2; rp++) {
                int m = row0 + wm * 64 + mi * 16 + (lane >> 2) + rp * 8;
                int n = col0 + wn * 64 + nn * 8 + (lane & 3) * 2;
                float v0 = c[mi][nn][rp * 2 + 0] + bias[n];
                float v1 = c[mi][nn][rp * 2 + 1] + bias[n + 1];
                if (EPI == 0) {
                    float2 v = make_float2(v0, v1);
                    *reinterpret_cast<float2*>(C + (size_t)m * N + n) = v;
                } else {
                    int type = n >> 10;
                    int rr = n & 1023;
                    int h = rr >> 6;
                    int d = rr & 63;
                    int b = m >> 11;
                    int s = m & 2047;
                    if (type == 0) { v0 *= 0.125f; v1 *= 0.125f; }
                    __half2 hh = __floats2half2_rn(v0, v1);
                    size_t hb = (size_t)(b * H_ + h) * S_ + s;
                    if (type == 0) {            // Q: hi only, pre-scaled
                        *reinterpret_cast<__half2*>(g_Q + hb * 64 + d) = hh;
                    } else if (type == 1) {     // K: hi only
                        *reinterpret_cast<__half2*>(g_K + hb * 64 + d) = hh;
                    } else {                    // V: hi only
                        *reinterpret_cast<__half2*>(g_Vhi + hb * 64 + d) = hh;
                    }
                }
            }
        }
    }
}

// ---------------------------------------------------------------------------
// Flash attention (HMMA): q-tile 128 (Q hi, 64 cols), key blocks of 64
// (K hi). PV: (Phi + Plo) @ Vhi — one Vhi frag feeds both P terms.
// 3-stage KV ring, one sync/iter, MUFU exp2.
// Smem: Q 16K + 3 x 16K = 64K -> 3 CTAs/SM.  Epilogue: hi-only a2.
// ---------------------------------------------------------------------------
#define FA_STAGE  16384
#define FA_SMEM   (16384 + 3 * FA_STAGE)

__global__ __launch_bounds__(256) void flash_kernel(__half* __restrict__ a2out)
{
    extern __shared__ char smem[];
    const uint32_t sQ = smem_u32(smem);
    const uint32_t sKV0 = sQ + 16384;
    const int t = threadIdx.x;
    const int lane = t & 31;
    const int wid = t >> 5;
    const int qb = blockIdx.x;
    const int h = blockIdx.y;
    const int b = blockIdx.z;

    const size_t headbase = (size_t)(b * H_ + h) * S_;
    const __half* Qg = g_Q + (headbase + qb * 128) * 64;
    const __half* Kg = g_K + headbase * 64;
    const __half* Vh = g_Vhi + headbase * 64;

    // Load Q tile (128 x 64 fp16, 128B rows, swizzled)
#pragma unroll
    for (int i = 0; i < 4; i++) {
        int id = t + 256 * i;          // 0..1023
        int r = id >> 3;               // 0..127
        int u = id & 7;
        int swu = u ^ (r & 7);
        CP_ASYNC16(sQ + r * 128 + swu * 16, Qg + (size_t)r * 64 + u * 8);
    }

    auto loadKV = [&](int kb, int st) {
        uint32_t sk = sKV0 + st * FA_STAGE;
        uint32_t sv = sk + 8192;
        const __half* kg = Kg + (size_t)kb * 64 * 64;
        const __half* vh = Vh + (size_t)kb * 64 * 64;
#pragma unroll
        for (int i = 0; i < 2; i++) {
            int id = t + 256 * i;
            int r = id >> 3;
            int u = id & 7;
            int swu = u ^ (r & 7);
            CP_ASYNC16(sk + r * 128 + swu * 16, kg + (size_t)r * 64 + u * 8);
            CP_ASYNC16(sv + r * 128 + swu * 16, vh + (size_t)r * 64 + u * 8);
        }
    };

    loadKV(0, 0);
    CP_COMMIT();
    loadKV(1, 1);
    CP_COMMIT();

    float o[8][4];
#pragma unroll
    for (int i = 0; i < 8; i++)
#pragma unroll
        for (int j = 0; j < 4; j++) o[i][j] = 0.0f;
    float m0 = -1e30f, m1 = -1e30f, l0 = 0.0f, l1 = 0.0f;

    const int mat = lane >> 3;
    const int wi = lane & 7;

    for (int kb = 0; kb < 32; kb++) {
        if (kb + 1 < 32) { CP_WAIT(1); } else { CP_WAIT(0); }
        __syncthreads();
        if (kb + 2 < 32) {
            loadKV(kb + 2, (kb + 2) % 3);
            CP_COMMIT();
        }

        int st = kb % 3;
        uint32_t skb = sKV0 + st * FA_STAGE;
        uint32_t sv = skb + 8192;

        // ---- scores: S = Qhi @ Khi^T ----
        float s[8][4];
#pragma unroll
        for (int i = 0; i < 8; i++)
#pragma unroll
            for (int j = 0; j < 4; j++) s[i][j] = 0.0f;

#pragma unroll
        for (int ks = 0; ks < 4; ks++) {
            uint32_t a0[4];
            {
                int row = wid * 16 + (mat & 1) * 8 + wi;
                int u = 2 * ks + (mat >> 1);
                ldsm_x4(a0[0], a0[1], a0[2], a0[3],
                        sQ + row * 128 + (((u ^ row) & 7) << 4));
            }
#pragma unroll
            for (int j = 0; j < 4; j++) {
                uint32_t bb[4];
                int row = j * 16 + (mat & 1) * 8 + wi;
                int u = 2 * ks + (mat >> 1);
                ldsm_x4(bb[0], bb[1], bb[2], bb[3],
                        skb + row * 128 + (((u ^ row) & 7) << 4));
                mma16816(s[j * 2 + 0], a0, bb[0], bb[2]);
                mma16816(s[j * 2 + 1], a0, bb[1], bb[3]);
            }
        }

        // ---- online softmax ----
        float nm0 = -1e30f, nm1 = -1e30f;
#pragma unroll
        for (int nn = 0; nn < 8; nn++) {
            nm0 = fmaxf(nm0, fmaxf(s[nn][0], s[nn][1]));
            nm1 = fmaxf(nm1, fmaxf(s[nn][2], s[nn][3]));
        }
        nm0 = fmaxf(nm0, __shfl_xor_sync(0xffffffffu, nm0, 1));
        nm0 = fmaxf(nm0, __shfl_xor_sync(0xffffffffu, nm0, 2));
        nm1 = fmaxf(nm1, __shfl_xor_sync(0xffffffffu, nm1, 1));
        nm1 = fmaxf(nm1, __shfl_xor_sync(0xffffffffu, nm1, 2));
        nm0 = fmaxf(nm0, m0);
        nm1 = fmaxf(nm1, m1);
        float al0 = fexp2((m0 - nm0) * LOG2E);
        float al1 = fexp2((m1 - nm1) * LOG2E);
        m0 = nm0;
        m1 = nm1;

        float sum0 = 0.0f, sum1 = 0.0f;
        uint32_t ph0[8], ph1[8], pl0[8], pl1[8];
#pragma unroll
        for (int nn = 0; nn < 8; nn++) {
            float p00 = fexp2((s[nn][0] - m0) * LOG2E);
            float p01 = fexp2((s[nn][1] - m0) * LOG2E);
            float p10 = fexp2((s[nn][2] - m1) * LOG2E);
            float p11 = fexp2((s[nn][3] - m1) * LOG2E);
            sum0 += p00 + p01;
            sum1 += p10 + p11;
            ph0[nn] = packh2(p00, p01);
            ph1[nn] = packh2(p10, p11);
            __half2 h0 = *reinterpret_cast<__half2*>(&ph0[nn]);
            __half2 h1 = *reinterpret_cast<__half2*>(&ph1[nn]);
            pl0[nn] = packh2(p00 - __low2float(h0), p01 - __high2float(h0));
            pl1[nn] = packh2(p10 - __low2float(h1), p11 - __high2float(h1));
        }
        sum0 += __shfl_xor_sync(0xffffffffu, sum0, 1);
        sum0 += __shfl_xor_sync(0xffffffffu, sum0, 2);
        sum1 += __shfl_xor_sync(0xffffffffu, sum1, 1);
        sum1 += __shfl_xor_sync(0xffffffffu, sum1, 2);
        l0 = l0 * al0 + sum0;
        l1 = l1 * al1 + sum1;
#pragma unroll
        for (int nn = 0; nn < 8; nn++) {
            o[nn][0] *= al0;
            o[nn][1] *= al0;
            o[nn][2] *= al1;
            o[nn][3] *= al1;
        }

        // ---- O += (Phi + Plo) @ Vhi  (one Vhi frag feeds both P terms) ----
#pragma unroll
        for (int ks = 0; ks < 4; ks++) {
            uint32_t ah[4] = { ph0[2 * ks], ph1[2 * ks],
                               ph0[2 * ks + 1], ph1[2 * ks + 1] };
            uint32_t al[4] = { pl0[2 * ks], pl1[2 * ks],
                               pl0[2 * ks + 1], pl1[2 * ks + 1] };
#pragma unroll
            for (int j = 0; j < 4; j++) {
                int krow = ks * 16 + (mat & 1) * 8 + wi;
                int u = j * 2 + (mat >> 1);
                int swu = u ^ (krow & 7);
                uint32_t vhi[4];
                ldsm_x4_t(vhi[0], vhi[1], vhi[2], vhi[3],
                          sv + krow * 128 + swu * 16);
                mma16816(o[j * 2 + 0], ah, vhi[0], vhi[1]);
                mma16816(o[j * 2 + 1], ah, vhi[2], vhi[3]);
                mma16816(o[j * 2 + 0], al, vhi[0], vhi[1]);
                mma16816(o[j * 2 + 1], al, vhi[2], vhi[3]);
            }
        }
    }

    // ---- epilogue: normalize, write hi-only proj input ----
    float inv0 = 1.0f / l0;
    float inv1 = 1.0f / l1;
    int s0 = qb * 128 + wid * 16 + (lane >> 2);
    int s1 = s0 + 8;
#pragma unroll
    for (int nn = 0; nn < 8; nn++) {
        int d = h * 64 + nn * 8 + (lane & 3) * 2;
#pragma unroll
        for (int rp = 0; rp < 2; rp++) {
            int srow = rp ? s1 : s0;
            float inv = rp ? inv1 : inv0;
            float v0 = o[nn][rp * 2 + 0] * inv;
            float v1 = o[nn][rp * 2 + 1] * inv;
            __half* p = a2out + (size_t)(b * S_ + srow) * D_ + d;
            *reinterpret_cast<__half2*>(p) = __floats2half2_rn(v0, v1);
        }
    }
}

// ---------------------------------------------------------------------------
extern "C" void kernel_launch(void* const* d_in, const int* in_sizes, int n_in,
                              void* d_out, int out_size)
{
    const float* x      = (const float*)d_in[0];
    const float* w_qkv  = (const float*)d_in[1];
    const float* b_qkv  = (const float*)d_in[2];
    const float* w_proj = (const float*)d_in[3];
    const float* b_proj = (const float*)d_in[4];
    float* out = (float*)d_out;

    __half *a1_p, *a2_p, *wq_p, *wp_p;
    cudaGetSymbolAddress((void**)&a1_p, g_a1);
    cudaGetSymbolAddress((void**)&a2_p, g_a2);
    cudaGetSymbolAddress((void**)&wq_p, g_wqkvT);
    cudaGetSymbolAddress((void**)&wp_p, g_wprojT);

    cudaFuncSetAttribute(gemm_hmma_kernel<0>,
                         cudaFuncAttributeMaxDynamicSharedMemorySize, GEMM_SMEM);
    cudaFuncSetAttribute(gemm_hmma_kernel<1>,
                         cudaFuncAttributeMaxDynamicSharedMemorySize, GEMM_SMEM);
    cudaFuncSetAttribute(flash_kernel,
                         cudaFuncAttributeMaxDynamicSharedMemorySize, FA_SMEM);

    // 1) converts
    convert_hi_kernel<<<(M_TOT * D_) / 1024, 256>>>(
        reinterpret_cast<const float4*>(x),
        reinterpret_cast<__half2*>(a1_p));
    transpose_hi_kernel<<<dim3((3 * D_) / 32, D_ / 32), dim3(32, 8)>>>(
        w_qkv, wq_p, 3 * D_);
    transpose_hi_kernel<<<dim3(D_ / 32, D_ / 32), dim3(32, 8)>>>(
        w_proj, wp_p, D_);

    // 2) QKV GEMM (epilogue writes scaled Q/K/V hi directly)
    gemm_hmma_kernel<1><<<dim3((3 * D_) / 128, M_TOT / 128), 128, GEMM_SMEM>>>(
        a1_p, wq_p, b_qkv, nullptr, 3 * D_);

    // 3) flash attention (epilogue writes hi-only proj input)
    flash_kernel<<<dim3(S_ / 128, H_, B_), 256, FA_SMEM>>>(a2_p);

    // 4) projection GEMM
    gemm_hmma_kernel<0><<<dim3(D_ / 128, M_TOT / 128), 128, GEMM_SMEM>>>(
        a2_p, wp_p, b_proj, out, D_);
}

// round 17
// speedup vs baseline: 3.3175x; 1.1397x over previous
#include <cuda_runtime.h>
#include <cuda_fp16.h>
#include <cstdint>

#define B_ 2
#define S_ 2048
#define D_ 1024
#define H_ 16
#define HD_ 64
#define M_TOT 4096
#define NKITER 16          // D_ / 64  (pure hi x hi GEMM)
#define LOG2E 1.44269504f

// ---------------------------------------------------------------------------
// Scratch (device globals; no allocation)
// ---------------------------------------------------------------------------
__device__ __half g_a1[(size_t)M_TOT * D_];            // x hi [4096,1024]
__device__ __half g_a2[(size_t)M_TOT * D_];            // attn-out hi [4096,1024]
__device__ __half g_wqkvT[(size_t)(3 * D_) * D_];      // w_qkv^T hi [3072,1024]
__device__ __half g_wprojT[(size_t)D_ * D_];           // w_proj^T hi [1024,1024]
__device__ __half g_Q[(size_t)B_ * H_ * S_ * 64];      // scaled q hi
__device__ __half g_K[(size_t)B_ * H_ * S_ * 64];      // k hi
__device__ __half g_Vhi[(size_t)B_ * H_ * S_ * 64];    // v hi

// ---------------------------------------------------------------------------
// PTX helpers
// ---------------------------------------------------------------------------
__device__ __forceinline__ uint32_t smem_u32(const void* p) {
    uint32_t a;
    asm("{ .reg .u64 t; cvta.to.shared.u64 t, %1; cvt.u32.u64 %0, t; }"
        : "=r"(a) : "l"(p));
    return a;
}
#define CP_ASYNC16(dst, src) \
    asm volatile("cp.async.cg.shared.global [%0], [%1], 16;" \
                 :: "r"(dst), "l"(src))
#define CP_COMMIT() asm volatile("cp.async.commit_group;")
#define CP_WAIT(n)  asm volatile("cp.async.wait_group %0;" :: "n"(n))

__device__ __forceinline__ void ldsm_x4(uint32_t& r0, uint32_t& r1,
                                        uint32_t& r2, uint32_t& r3,
                                        uint32_t addr) {
    asm volatile("ldmatrix.sync.aligned.m8n8.x4.shared.b16 {%0,%1,%2,%3}, [%4];"
                 : "=r"(r0), "=r"(r1), "=r"(r2), "=r"(r3) : "r"(addr));
}
__device__ __forceinline__ void ldsm_x4_t(uint32_t& r0, uint32_t& r1,
                                          uint32_t& r2, uint32_t& r3,
                                          uint32_t addr) {
    asm volatile("ldmatrix.sync.aligned.m8n8.x4.trans.shared.b16 {%0,%1,%2,%3}, [%4];"
                 : "=r"(r0), "=r"(r1), "=r"(r2), "=r"(r3) : "r"(addr));
}
__device__ __forceinline__ void mma16816(float* c, const uint32_t* a,
                                         uint32_t b0, uint32_t b1) {
    asm volatile(
        "mma.sync.aligned.m16n8k16.row.col.f32.f16.f16.f32 "
        "{%0,%1,%2,%3}, {%4,%5,%6,%7}, {%8,%9}, {%0,%1,%2,%3};"
        : "+f"(c[0]), "+f"(c[1]), "+f"(c[2]), "+f"(c[3])
        : "r"(a[0]), "r"(a[1]), "r"(a[2]), "r"(a[3]), "r"(b0), "r"(b1));
}

// MUFU exp2 (approx — plenty for softmax weights)
__device__ __forceinline__ float fexp2(float t) {
    float r;
    asm("ex2.approx.ftz.f32 %0, %1;" : "=f"(r) : "f"(t));
    return r;
}

__device__ __forceinline__ uint32_t packh2(float a, float b) {
    __half2 h = __floats2half2_rn(a, b);
    return *reinterpret_cast<uint32_t*>(&h);
}

// ---------------------------------------------------------------------------
// Conversion kernels
// ---------------------------------------------------------------------------
__global__ __launch_bounds__(256) void convert_hi_kernel(
    const float4* __restrict__ src, __half2* __restrict__ dst)
{
    int i = blockIdx.x * 256 + threadIdx.x;    // over M*D/4
    float4 v = src[i];
    dst[i * 2 + 0] = __floats2half2_rn(v.x, v.y);
    dst[i * 2 + 1] = __floats2half2_rn(v.z, v.w);
}

// Transposes BOTH weights in one launch: x-tiles 0..95 -> w_qkv (N=3072),
// x-tiles 96..127 -> w_proj (N=1024).
__global__ __launch_bounds__(256) void transpose_both_kernel(
    const float* __restrict__ wqkv, const float* __restrict__ wproj,
    __half* __restrict__ wqkvT, __half* __restrict__ wprojT)
{
    __shared__ float tile[32][33];
    const float* w;
    __half* wt;
    int N, bx;
    if (blockIdx.x < 96) {
        w = wqkv; wt = wqkvT; N = 3 * D_; bx = blockIdx.x * 32;
    } else {
        w = wproj; wt = wprojT; N = D_; bx = (blockIdx.x - 96) * 32;
    }
    int by = blockIdx.y * 32;
    int tx = threadIdx.x;
    int ty = threadIdx.y;
#pragma unroll
    for (int i = ty; i < 32; i += 8)
        tile[i][tx] = w[(size_t)(by + i) * N + bx + tx];
    __syncthreads();
#pragma unroll
    for (int i = ty; i < 32; i += 8) {
        int n = bx + i;
        int k = by + tx;
        wt[(size_t)n * D_ + k] = __float2half_rn(tile[tx][i]);
    }
}

// ---------------------------------------------------------------------------
// HMMA GEMM: C[m,n] = sum_k A_hi[m,k]*Bt_hi[n,k] (+bias)
// A:[M,1024] hi, Bt:[N,1024] hi.
// CTA 128x128, BK=64, 3-stage ring, ONE sync/iter, 128 thr = 4 warps 64x64.
// EPI==0: fp32 C + bias.  EPI==1: QKV epilogue -> g_Q/g_K/g_Vhi (all hi).
// ---------------------------------------------------------------------------
#define GEMM_SMEM (3 * 32768)

template <int EPI>
__global__ __launch_bounds__(128) void gemm_hmma_kernel(
    const __half* __restrict__ A, const __half* __restrict__ Bt,
    const float* __restrict__ bias, float* __restrict__ C, int N)
{
    extern __shared__ char smem[];
    const uint32_t sbase = smem_u32(smem);
    const int t = threadIdx.x;
    const int lane = t & 31;
    const int wid = t >> 5;
    const int wm = wid >> 1;          // 0..1
    const int wn = wid & 1;           // 0..1
    const int row0 = blockIdx.y * 128;
    const int col0 = blockIdx.x * 128;

    const __half* Ag = A + (size_t)row0 * D_;
    const __half* Bg = Bt + (size_t)col0 * D_;

    float c[4][8][4];
#pragma unroll
    for (int i = 0; i < 4; i++)
#pragma unroll
        for (int j = 0; j < 8; j++)
#pragma unroll
            for (int r = 0; r < 4; r++) c[i][j][r] = 0.0f;

    auto load_stage = [&](int kb, int st) {
        uint32_t sa = sbase + st * 32768;
        uint32_t sb = sa + 16384;
        const __half* Agk = Ag + kb * 64;
        const __half* Bgk = Bg + kb * 64;
#pragma unroll
        for (int i = 0; i < 8; i++) {
            int id = t + 128 * i;          // 0..1023
            int r = id >> 3;               // 0..127
            int u = id & 7;
            uint32_t sw = (uint32_t)(r * 128 + ((u ^ (r & 7)) << 4));
            CP_ASYNC16(sa + sw, Agk + (size_t)r * D_ + u * 8);
            CP_ASYNC16(sb + sw, Bgk + (size_t)r * D_ + u * 8);
        }
    };

    load_stage(0, 0);
    CP_COMMIT();
    load_stage(1, 1);
    CP_COMMIT();

    const int mat = lane >> 3;
    const int wi = lane & 7;

    for (int kb = 0; kb < NKITER; kb++) {
        if (kb + 1 < NKITER) { CP_WAIT(1); } else { CP_WAIT(0); }
        __syncthreads();
        if (kb + 2 < NKITER) {
            load_stage(kb + 2, (kb + 2) % 3);
            CP_COMMIT();
        }

        uint32_t sa = sbase + (kb % 3) * 32768;
        uint32_t sb = sa + 16384;

#pragma unroll
        for (int s = 0; s < 4; s++) {
            uint32_t a[4][4];
#pragma unroll
            for (int mi = 0; mi < 4; mi++) {
                int row = wm * 64 + mi * 16 + (mat & 1) * 8 + wi;
                int u = 2 * s + (mat >> 1);
                ldsm_x4(a[mi][0], a[mi][1], a[mi][2], a[mi][3],
                        sa + row * 128 + (((u ^ wi) & 7) << 4));
            }
            uint32_t b[4][4];
#pragma unroll
            for (int j = 0; j < 4; j++) {
                int row = wn * 64 + j * 16 + (mat & 1) * 8 + wi;
                int u = 2 * s + (mat >> 1);
                ldsm_x4(b[j][0], b[j][1], b[j][2], b[j][3],
                        sb + row * 128 + (((u ^ wi) & 7) << 4));
            }
#pragma unroll
            for (int mi = 0; mi < 4; mi++)
#pragma unroll
                for (int nn = 0; nn < 8; nn++)
                    mma16816(c[mi][nn], a[mi],
                             b[nn >> 1][nn & 1], b[nn >> 1][(nn & 1) + 2]);
        }
    }

    // Epilogue
#pragma unroll
    for (int mi = 0; mi < 4; mi++) {
#pragma unroll
        for (int nn = 0; nn < 8; nn++) {
#pragma unroll
            for (int rp = 0; rp < 2; rp++) {
                int m = row0 + wm * 64 + mi * 16 + (lane >> 2) + rp * 8;
                int n = col0 + wn * 64 + nn * 8 + (lane & 3) * 2;
                float v0 = c[mi][nn][rp * 2 + 0] + bias[n];
                float v1 = c[mi][nn][rp * 2 + 1] + bias[n + 1];
                if (EPI == 0) {
                    float2 v = make_float2(v0, v1);
                    *reinterpret_cast<float2*>(C + (size_t)m * N + n) = v;
                } else {
                    int type = n >> 10;
                    int rr = n & 1023;
                    int h = rr >> 6;
                    int d = rr & 63;
                    int b = m >> 11;
                    int s = m & 2047;
                    if (type == 0) { v0 *= 0.125f; v1 *= 0.125f; }
                    __half2 hh = __floats2half2_rn(v0, v1);
                    size_t hb = (size_t)(b * H_ + h) * S_ + s;
                    if (type == 0) {            // Q: hi only, pre-scaled
                        *reinterpret_cast<__half2*>(g_Q + hb * 64 + d) = hh;
                    } else if (type == 1) {     // K: hi only
                        *reinterpret_cast<__half2*>(g_K + hb * 64 + d) = hh;
                    } else {                    // V: hi only
                        *reinterpret_cast<__half2*>(g_Vhi + hb * 64 + d) = hh;
                    }
                }
            }
        }
    }
}

// ---------------------------------------------------------------------------
// Flash attention (HMMA): q-tile 128 (Q hi, 64 cols), key blocks of 64
// (K hi). PV: fp16(P) @ Vhi — single pass. 3-stage KV ring, one sync/iter,
// MUFU exp2.  Smem: Q 16K + 3 x 16K = 64K -> 3 CTAs/SM.
// ---------------------------------------------------------------------------
#define FA_STAGE  16384
#define FA_SMEM   (16384 + 3 * FA_STAGE)

__global__ __launch_bounds__(256) void flash_kernel(__half* __restrict__ a2out)
{
    extern __shared__ char smem[];
    const uint32_t sQ = smem_u32(smem);
    const uint32_t sKV0 = sQ + 16384;
    const int t = threadIdx.x;
    const int lane = t & 31;
    const int wid = t >> 5;
    const int qb = blockIdx.x;
    const int h = blockIdx.y;
    const int b = blockIdx.z;

    const size_t headbase = (size_t)(b * H_ + h) * S_;
    const __half* Qg = g_Q + (headbase + qb * 128) * 64;
    const __half* Kg = g_K + headbase * 64;
    const __half* Vh = g_Vhi + headbase * 64;

    // Load Q tile (128 x 64 fp16, 128B rows, swizzled)
#pragma unroll
    for (int i = 0; i < 4; i++) {
        int id = t + 256 * i;          // 0..1023
        int r = id >> 3;               // 0..127
        int u = id & 7;
        int swu = u ^ (r & 7);
        CP_ASYNC16(sQ + r * 128 + swu * 16, Qg + (size_t)r * 64 + u * 8);
    }

    auto loadKV = [&](int kb, int st) {
        uint32_t sk = sKV0 + st * FA_STAGE;
        uint32_t sv = sk + 8192;
        const __half* kg = Kg + (size_t)kb * 64 * 64;
        const __half* vh = Vh + (size_t)kb * 64 * 64;
#pragma unroll
        for (int i = 0; i < 2; i++) {
            int id = t + 256 * i;
            int r = id >> 3;
            int u = id & 7;
            int swu = u ^ (r & 7);
            CP_ASYNC16(sk + r * 128 + swu * 16, kg + (size_t)r * 64 + u * 8);
            CP_ASYNC16(sv + r * 128 + swu * 16, vh + (size_t)r * 64 + u * 8);
        }
    };

    loadKV(0, 0);
    CP_COMMIT();
    loadKV(1, 1);
    CP_COMMIT();

    float o[8][4];
#pragma unroll
    for (int i = 0; i < 8; i++)
#pragma unroll
        for (int j = 0; j < 4; j++) o[i][j] = 0.0f;
    float m0 = -1e30f, m1 = -1e30f, l0 = 0.0f, l1 = 0.0f;

    const int mat = lane >> 3;
    const int wi = lane & 7;

    for (int kb = 0; kb < 32; kb++) {
        if (kb + 1 < 32) { CP_WAIT(1); } else { CP_WAIT(0); }
        __syncthreads();
        if (kb + 2 < 32) {
            loadKV(kb + 2, (kb + 2) % 3);
            CP_COMMIT();
        }

        int st = kb % 3;
        uint32_t skb = sKV0 + st * FA_STAGE;
        uint32_t sv = skb + 8192;

        // ---- scores: S = Qhi @ Khi^T ----
        float s[8][4];
#pragma unroll
        for (int i = 0; i < 8; i++)
#pragma unroll
            for (int j = 0; j < 4; j++) s[i][j] = 0.0f;

#pragma unroll
        for (int ks = 0; ks < 4; ks++) {
            uint32_t a0[4];
            {
                int row = wid * 16 + (mat & 1) * 8 + wi;
                int u = 2 * ks + (mat >> 1);
                ldsm_x4(a0[0], a0[1], a0[2], a0[3],
                        sQ + row * 128 + (((u ^ row) & 7) << 4));
            }
#pragma unroll
            for (int j = 0; j < 4; j++) {
                uint32_t bb[4];
                int row = j * 16 + (mat & 1) * 8 + wi;
                int u = 2 * ks + (mat >> 1);
                ldsm_x4(bb[0], bb[1], bb[2], bb[3],
                        skb + row * 128 + (((u ^ row) & 7) << 4));
                mma16816(s[j * 2 + 0], a0, bb[0], bb[2]);
                mma16816(s[j * 2 + 1], a0, bb[1], bb[3]);
            }
        }

        // ---- online softmax ----
        float nm0 = -1e30f, nm1 = -1e30f;
#pragma unroll
        for (int nn = 0; nn < 8; nn++) {
            nm0 = fmaxf(nm0, fmaxf(s[nn][0], s[nn][1]));
            nm1 = fmaxf(nm1, fmaxf(s[nn][2], s[nn][3]));
        }
        nm0 = fmaxf(nm0, __shfl_xor_sync(0xffffffffu, nm0, 1));
        nm0 = fmaxf(nm0, __shfl_xor_sync(0xffffffffu, nm0, 2));
        nm1 = fmaxf(nm1, __shfl_xor_sync(0xffffffffu, nm1, 1));
        nm1 = fmaxf(nm1, __shfl_xor_sync(0xffffffffu, nm1, 2));
        nm0 = fmaxf(nm0, m0);
        nm1 = fmaxf(nm1, m1);
        float al0 = fexp2((m0 - nm0) * LOG2E);
        float al1 = fexp2((m1 - nm1) * LOG2E);
        m0 = nm0;
        m1 = nm1;

        float sum0 = 0.0f, sum1 = 0.0f;
        uint32_t ph0[8], ph1[8];
#pragma unroll
        for (int nn = 0; nn < 8; nn++) {
            float p00 = fexp2((s[nn][0] - m0) * LOG2E);
            float p01 = fexp2((s[nn][1] - m0) * LOG2E);
            float p10 = fexp2((s[nn][2] - m1) * LOG2E);
            float p11 = fexp2((s[nn][3] - m1) * LOG2E);
            sum0 += p00 + p01;
            sum1 += p10 + p11;
            ph0[nn] = packh2(p00, p01);
            ph1[nn] = packh2(p10, p11);
        }
        sum0 += __shfl_xor_sync(0xffffffffu, sum0, 1);
        sum0 += __shfl_xor_sync(0xffffffffu, sum0, 2);
        sum1 += __shfl_xor_sync(0xffffffffu, sum1, 1);
        sum1 += __shfl_xor_sync(0xffffffffu, sum1, 2);
        l0 = l0 * al0 + sum0;
        l1 = l1 * al1 + sum1;
#pragma unroll
        for (int nn = 0; nn < 8; nn++) {
            o[nn][0] *= al0;
            o[nn][1] *= al0;
            o[nn][2] *= al1;
            o[nn][3] *= al1;
        }

        // ---- O += fp16(P) @ Vhi  (single pass) ----
#pragma unroll
        for (int ks = 0; ks < 4; ks++) {
            uint32_t ah[4] = { ph0[2 * ks], ph1[2 * ks],
                               ph0[2 * ks + 1], ph1[2 * ks + 1] };
#pragma unroll
            for (int j = 0; j < 4; j++) {
                int krow = ks * 16 + (mat & 1) * 8 + wi;
                int u = j * 2 + (mat >> 1);
                int swu = u ^ (krow & 7);
                uint32_t vhi[4];
                ldsm_x4_t(vhi[0], vhi[1], vhi[2], vhi[3],
                          sv + krow * 128 + swu * 16);
                mma16816(o[j * 2 + 0], ah, vhi[0], vhi[1]);
                mma16816(o[j * 2 + 1], ah, vhi[2], vhi[3]);
            }
        }
    }

    // ---- epilogue: normalize, write hi-only proj input ----
    float inv0 = 1.0f / l0;
    float inv1 = 1.0f / l1;
    int s0 = qb * 128 + wid * 16 + (lane >> 2);
    int s1 = s0 + 8;
#pragma unroll
    for (int nn = 0; nn < 8; nn++) {
        int d = h * 64 + nn * 8 + (lane & 3) * 2;
#pragma unroll
        for (int rp = 0; rp < 2; rp++) {
            int srow = rp ? s1 : s0;
            float inv = rp ? inv1 : inv0;
            float v0 = o[nn][rp * 2 + 0] * inv;
            float v1 = o[nn][rp * 2 + 1] * inv;
            __half* p = a2out + (size_t)(b * S_ + srow) * D_ + d;
            *reinterpret_cast<__half2*>(p) = __floats2half2_rn(v0, v1);
        }
    }
}

// ---------------------------------------------------------------------------
extern "C" void kernel_launch(void* const* d_in, const int* in_sizes, int n_in,
                              void* d_out, int out_size)
{
    const float* x      = (const float*)d_in[0];
    const float* w_qkv  = (const float*)d_in[1];
    const float* b_qkv  = (const float*)d_in[2];
    const float* w_proj = (const float*)d_in[3];
    const float* b_proj = (const float*)d_in[4];
    float* out = (float*)d_out;

    __half *a1_p, *a2_p, *wq_p, *wp_p;
    cudaGetSymbolAddress((void**)&a1_p, g_a1);
    cudaGetSymbolAddress((void**)&a2_p, g_a2);
    cudaGetSymbolAddress((void**)&wq_p, g_wqkvT);
    cudaGetSymbolAddress((void**)&wp_p, g_wprojT);

    cudaFuncSetAttribute(gemm_hmma_kernel<0>,
                         cudaFuncAttributeMaxDynamicSharedMemorySize, GEMM_SMEM);
    cudaFuncSetAttribute(gemm_hmma_kernel<1>,
                         cudaFuncAttributeMaxDynamicSharedMemorySize, GEMM_SMEM);
    cudaFuncSetAttribute(flash_kernel,
                         cudaFuncAttributeMaxDynamicSharedMemorySize, FA_SMEM);

    // 1) converts (one kernel for x, one for both weight transposes)
    convert_hi_kernel<<<(M_TOT * D_) / 1024, 256>>>(
        reinterpret_cast<const float4*>(x),
        reinterpret_cast<__half2*>(a1_p));
    transpose_both_kernel<<<dim3(128, D_ / 32), dim3(32, 8)>>>(
        w_qkv, w_proj, wq_p, wp_p);

    // 2) QKV GEMM (epilogue writes scaled Q/K/V hi directly)
    gemm_hmma_kernel<1><<<dim3((3 * D_) / 128, M_TOT / 128), 128, GEMM_SMEM>>>(
        a1_p, wq_p, b_qkv, nullptr, 3 * D_);

    // 3) flash attention (epilogue writes hi-only proj input)
    flash_kernel<<<dim3(S_ / 128, H_, B_), 256, FA_SMEM>>>(a2_p);

    // 4) projection GEMM
    gemm_hmma_kernel<0><<<dim3(D_ / 128, M_TOT / 128), 128, GEMM_SMEM>>>(
        a2_p, wp_p, b_proj, out, D_);
}